// round 9
// baseline (speedup 1.0000x reference)
#include <cuda_runtime.h>
#include <cuda_bf16.h>
#include <cstdint>
#include <cstddef>

// Problem dims (fixed)
#define BB 4
#define SS 2048
#define DD 1024
#define HH 16
#define HD 64
#define RR 512
#define MTOT (BB*SS)          // 8192 rows

// ---------------- scratch (device globals: allocation-guard safe) -------------
__device__ float g_att [(size_t)MTOT * DD];   // 32 MB
__device__ float g_tmpk[(size_t)MTOT * RR];   // 16 MB
__device__ float g_tmpv[(size_t)MTOT * RR];   // 16 MB
__device__ float g_cpt [(size_t)DD * DD];     // 4 MB  (c_proj transposed -> [N,K])
// split bf16 Q/K/V (written by projection GEMM epilogues)
__device__ __nv_bfloat16 g_qhi[(size_t)MTOT * DD];
__device__ __nv_bfloat16 g_qlo[(size_t)MTOT * DD];
__device__ __nv_bfloat16 g_khi[(size_t)MTOT * DD];
__device__ __nv_bfloat16 g_klo[(size_t)MTOT * DD];
__device__ __nv_bfloat16 g_vhi[(size_t)MTOT * DD];
__device__ __nv_bfloat16 g_vlo[(size_t)MTOT * DD];

// ---------------- mma.sync helpers (family-stable, OK on compute_103) ----------
__device__ __forceinline__ uint32_t smem_u32(const void* p) {
    uint32_t a;
    asm("{ .reg .u64 t; cvta.to.shared.u64 t, %1; cvt.u32.u64 %0, t; }"
        : "=r"(a) : "l"(p));
    return a;
}

__device__ __forceinline__ void ldsm_x4(uint32_t addr, uint32_t* r) {
    asm volatile("ldmatrix.sync.aligned.m8n8.x4.shared.b16 {%0,%1,%2,%3}, [%4];"
                 : "=r"(r[0]), "=r"(r[1]), "=r"(r[2]), "=r"(r[3]) : "r"(addr));
}
__device__ __forceinline__ void ldsm_x4_t(uint32_t addr, uint32_t* r) {
    asm volatile("ldmatrix.sync.aligned.m8n8.x4.trans.shared.b16 {%0,%1,%2,%3}, [%4];"
                 : "=r"(r[0]), "=r"(r[1]), "=r"(r[2]), "=r"(r[3]) : "r"(addr));
}
__device__ __forceinline__ void mma16816(float* d, const uint32_t* a, const uint32_t* b) {
    asm volatile(
        "mma.sync.aligned.m16n8k16.row.col.f32.bf16.bf16.f32 "
        "{%0,%1,%2,%3}, {%4,%5,%6,%7}, {%8,%9}, {%0,%1,%2,%3};"
        : "+f"(d[0]), "+f"(d[1]), "+f"(d[2]), "+f"(d[3])
        : "r"(a[0]), "r"(a[1]), "r"(a[2]), "r"(a[3]), "r"(b[0]), "r"(b[1]));
}

__device__ __forceinline__ void cp16(uint32_t dst, const void* src) {
    asm volatile("cp.async.cg.shared.global [%0], [%1], 16;"
                 :: "r"(dst), "l"(src) : "memory");
}
#define CP_COMMIT()  asm volatile("cp.async.commit_group;" ::: "memory")
#define CP_WAIT1()   asm volatile("cp.async.wait_group 1;" ::: "memory")
#define CP_WAIT0()   asm volatile("cp.async.wait_group 0;" ::: "memory")

// split a float4 into packed-bf16 hi(8B) and lo(8B)
__device__ __forceinline__ void split_f4(float4 v, uint2& hi, uint2& lo) {
    __nv_bfloat16 h0 = __float2bfloat16(v.x), h1 = __float2bfloat16(v.y);
    __nv_bfloat16 h2 = __float2bfloat16(v.z), h3 = __float2bfloat16(v.w);
    __nv_bfloat16 l0 = __float2bfloat16(v.x - __bfloat162float(h0));
    __nv_bfloat16 l1 = __float2bfloat16(v.y - __bfloat162float(h1));
    __nv_bfloat16 l2 = __float2bfloat16(v.z - __bfloat162float(h2));
    __nv_bfloat16 l3 = __float2bfloat16(v.w - __bfloat162float(h3));
    __nv_bfloat162 hp0(h0, h1), hp1(h2, h3), lp0(l0, l1), lp1(l2, l3);
    hi.x = *reinterpret_cast<uint32_t*>(&hp0);
    hi.y = *reinterpret_cast<uint32_t*>(&hp1);
    lo.x = *reinterpret_cast<uint32_t*>(&lp0);
    lo.y = *reinterpret_cast<uint32_t*>(&lp1);
}

// split a pair of floats into packed bf16 hi / lo
__device__ __forceinline__ void split2(float x, float y, uint32_t& hi, uint32_t& lo) {
    __nv_bfloat16 hx = __float2bfloat16(x), hy = __float2bfloat16(y);
    __nv_bfloat16 lx = __float2bfloat16(x - __bfloat162float(hx));
    __nv_bfloat16 ly = __float2bfloat16(y - __bfloat162float(hy));
    __nv_bfloat162 hp(hx, hy), lp(lx, ly);
    hi = *reinterpret_cast<uint32_t*>(&hp);
    lo = *reinterpret_cast<uint32_t*>(&lp);
}

// ---------------- HMMA bf16x3 GEMM core (unchanged, verified) -------------------
#define PITCH 80
#define TILE_B (128 * PITCH)
#define STAGE_B (4 * TILE_B)
#define HMMA_SMEM (2 * STAGE_B)

template <bool BIAS, bool SPLITOUT>
__device__ __forceinline__ void
hmma_core(const float* __restrict__ A, const float* __restrict__ B,
          const float* __restrict__ bias, float* __restrict__ C,
          __nv_bfloat16* __restrict__ Chi, __nv_bfloat16* __restrict__ Clo,
          int M, int N, int K)
{
    extern __shared__ char smem[];
    const uint32_t sb = smem_u32(smem);

    const int tid  = threadIdx.x;
    const int lane = tid & 31;
    const int wid  = tid >> 5;
    const int m0 = blockIdx.y * 128, n0 = blockIdx.x * 128;
    const int wm = (wid & 3) * 32;
    const int wn = (wid >> 2) * 64;

    const int lr = tid >> 3;
    const int lq = tid & 7;

    const int a_row = wm + (lane & 7) + ((lane >> 3) & 1) * 8;
    const int a_kb  = ((lane >> 4) & 1) * 16;
    const int b_row = wn + (lane & 7) + ((lane >> 4) & 1) * 8;
    const int b_kb  = ((lane >> 3) & 1) * 16;

    float acc[2][8][4];
#pragma unroll
    for (int i = 0; i < 2; i++)
#pragma unroll
        for (int j = 0; j < 8; j++)
#pragma unroll
            for (int k = 0; k < 4; k++) acc[i][j][k] = 0.f;

    const int NC = K >> 5;

    float4 ra[4], rb[4];
#pragma unroll
    for (int p = 0; p < 4; p++) {
        int row = lr + p * 32;
        ra[p] = *reinterpret_cast<const float4*>(&A[(size_t)(m0 + row) * K + lq * 4]);
        rb[p] = *reinterpret_cast<const float4*>(&B[(size_t)(n0 + row) * K + lq * 4]);
    }
#pragma unroll
    for (int p = 0; p < 4; p++) {
        int row = lr + p * 32;
        uint32_t off = (uint32_t)(row * PITCH + lq * 8);
        uint2 hi, lo;
        split_f4(ra[p], hi, lo);
        *reinterpret_cast<uint2*>(smem + (off))              = hi;
        *reinterpret_cast<uint2*>(smem + (off + TILE_B))     = lo;
        split_f4(rb[p], hi, lo);
        *reinterpret_cast<uint2*>(smem + (off + 2 * TILE_B)) = hi;
        *reinterpret_cast<uint2*>(smem + (off + 3 * TILE_B)) = lo;
    }
    __syncthreads();

    for (int c = 0; c < NC; c++) {
        if (c + 1 < NC) {
            const int kc = (c + 1) << 5;
#pragma unroll
            for (int p = 0; p < 4; p++) {
                int row = lr + p * 32;
                ra[p] = *reinterpret_cast<const float4*>(
                    &A[(size_t)(m0 + row) * K + kc + lq * 4]);
                rb[p] = *reinterpret_cast<const float4*>(
                    &B[(size_t)(n0 + row) * K + kc + lq * 4]);
            }
        }

        const uint32_t st = sb + (uint32_t)(c & 1) * STAGE_B;
#pragma unroll
        for (int ks = 0; ks < 2; ks++) {
            uint32_t ah[2][4], al[2][4];
#pragma unroll
            for (int mt = 0; mt < 2; mt++) {
                uint32_t aaddr = st + (uint32_t)((a_row + mt * 16) * PITCH + a_kb + ks * 32);
                ldsm_x4(aaddr, ah[mt]);
                ldsm_x4(aaddr + TILE_B, al[mt]);
            }
#pragma unroll
            for (int nt2 = 0; nt2 < 4; nt2++) {
                uint32_t bh[4], bl[4];
                uint32_t baddr = st + 2 * TILE_B +
                    (uint32_t)((b_row + nt2 * 16) * PITCH + b_kb + ks * 32);
                ldsm_x4(baddr, bh);
                ldsm_x4(baddr + TILE_B, bl);
#pragma unroll
                for (int mt = 0; mt < 2; mt++) {
#pragma unroll
                    for (int half = 0; half < 2; half++) {
                        float* d = acc[mt][nt2 * 2 + half];
                        mma16816(d, ah[mt], &bh[half * 2]);
                        mma16816(d, ah[mt], &bl[half * 2]);
                        mma16816(d, al[mt], &bh[half * 2]);
                    }
                }
            }
        }

        if (c + 1 < NC) {
            char* so = smem + (size_t)((c + 1) & 1) * STAGE_B;
#pragma unroll
            for (int p = 0; p < 4; p++) {
                int row = lr + p * 32;
                uint32_t off = (uint32_t)(row * PITCH + lq * 8);
                uint2 hi, lo;
                split_f4(ra[p], hi, lo);
                *reinterpret_cast<uint2*>(so + off)              = hi;
                *reinterpret_cast<uint2*>(so + off + TILE_B)     = lo;
                split_f4(rb[p], hi, lo);
                *reinterpret_cast<uint2*>(so + off + 2 * TILE_B) = hi;
                *reinterpret_cast<uint2*>(so + off + 3 * TILE_B) = lo;
            }
        }
        __syncthreads();
    }

    const int g = lane >> 2;
    const int cpair = (lane & 3) * 2;
#pragma unroll
    for (int mt = 0; mt < 2; mt++) {
#pragma unroll
        for (int nt = 0; nt < 8; nt++) {
            int col = n0 + wn + nt * 8 + cpair;
            float bx = 0.f, by = 0.f;
            if (BIAS) { bx = bias[col]; by = bias[col + 1]; }
            int row0 = m0 + wm + mt * 16 + g;
            float x0 = acc[mt][nt][0] + bx, y0 = acc[mt][nt][1] + by;
            float x1 = acc[mt][nt][2] + bx, y1 = acc[mt][nt][3] + by;
            if (SPLITOUT) {
                uint32_t hi, lo;
                size_t o0 = (size_t)row0 * N + col;
                size_t o1 = (size_t)(row0 + 8) * N + col;
                split2(x0, y0, hi, lo);
                *reinterpret_cast<uint32_t*>(Chi + o0) = hi;
                *reinterpret_cast<uint32_t*>(Clo + o0) = lo;
                split2(x1, y1, hi, lo);
                *reinterpret_cast<uint32_t*>(Chi + o1) = hi;
                *reinterpret_cast<uint32_t*>(Clo + o1) = lo;
            } else {
                *reinterpret_cast<float2*>(&C[(size_t)row0 * N + col]) =
                    make_float2(x0, y0);
                *reinterpret_cast<float2*>(&C[(size_t)(row0 + 8) * N + col]) =
                    make_float2(x1, y1);
            }
        }
    }
}

template <bool BIAS, bool SPLITOUT>
__global__ void __launch_bounds__(256)
hmma_gemm(const float* __restrict__ A, const float* __restrict__ B,
          const float* __restrict__ bias, float* __restrict__ C,
          __nv_bfloat16* __restrict__ Chi, __nv_bfloat16* __restrict__ Clo,
          int M, int N, int K)
{
    hmma_core<BIAS, SPLITOUT>(A, B, bias, C, Chi, Clo, M, N, K);
}

// dual fp32-out GEMM (stage-1 K/V low-rank): z selects operand set
__global__ void __launch_bounds__(256)
hmma_gemm_dual_f32(const float* __restrict__ A,
                   const float* __restrict__ B0, const float* __restrict__ B1,
                   float* __restrict__ C0, float* __restrict__ C1,
                   int M, int N, int K)
{
    if (blockIdx.z == 0)
        hmma_core<false, false>(A, B0, nullptr, C0, nullptr, nullptr, M, N, K);
    else
        hmma_core<false, false>(A, B1, nullptr, C1, nullptr, nullptr, M, N, K);
}

// dual split-out GEMM (stage-2 K/V): z selects operand set
__global__ void __launch_bounds__(256)
hmma_gemm_dual_split(const float* __restrict__ A0, const float* __restrict__ A1,
                     const float* __restrict__ B0, const float* __restrict__ B1,
                     const float* __restrict__ bias0, const float* __restrict__ bias1,
                     __nv_bfloat16* __restrict__ C0hi, __nv_bfloat16* __restrict__ C0lo,
                     __nv_bfloat16* __restrict__ C1hi, __nv_bfloat16* __restrict__ C1lo,
                     int M, int N, int K)
{
    if (blockIdx.z == 0)
        hmma_core<true, true>(A0, B0, bias0, nullptr, C0hi, C0lo, M, N, K);
    else
        hmma_core<true, true>(A1, B1, bias1, nullptr, C1hi, C1lo, M, N, K);
}

// ---------------- fp32 transpose (for c_proj: [K,N] -> [N,K]) ------------------
__global__ void __launch_bounds__(256)
transpose_kernel(const float* __restrict__ W, float* __restrict__ out, int K, int N)
{
    __shared__ float t[32][33];
    int k0 = blockIdx.y * 32, n0 = blockIdx.x * 32;
    int tx = threadIdx.x & 31, ty = threadIdx.x >> 5;
#pragma unroll
    for (int i = 0; i < 32; i += 8)
        t[ty + i][tx] = W[(size_t)(k0 + ty + i) * N + n0 + tx];
    __syncthreads();
#pragma unroll
    for (int i = 0; i < 32; i += 8)
        out[(size_t)(n0 + ty + i) * K + k0 + tx] = t[tx][ty + i];
}

// ---------------- HMMA flash attention (software-pipelined softmax) ------------
// grid (S/128, H, B), 256 threads (8 warps x 16 q-rows), k-tiles of 64.
// 3-stage cp.async K/V ring; QK^T(kt+1) issued BEFORE softmax(kt) so the exp/
// shuffle chain executes under MMA shadow. One __syncthreads per iteration.
#define APITCH 144                 // bytes per 64-bf16 row (128B + 16B pad)
#define QTILE (128 * APITCH)       // 18432
#define KTILE (64 * APITCH)        // 9216
#define STAGEA (4 * KTILE)         // Khi,Klo,Vhi,Vlo = 36864
#define ATT_SMEM (2 * QTILE + 3 * STAGEA)   // 147456

// QK^T for one 64-wide k-tile (bf16x3): s += Q(warp rows) @ K^T
__device__ __forceinline__ void qk_tile(float (&s)[8][4], uint32_t sb,
                                        uint32_t stage, uint32_t a_off,
                                        uint32_t b_off)
{
#pragma unroll
    for (int i = 0; i < 8; i++)
#pragma unroll
        for (int j = 0; j < 4; j++) s[i][j] = 0.f;

#pragma unroll
    for (int ks = 0; ks < 4; ks++) {
        uint32_t qh[4], ql[4];
        uint32_t qa = sb + a_off + ks * 32;
        ldsm_x4(qa, qh);
        ldsm_x4(qa + QTILE, ql);
#pragma unroll
        for (int np = 0; np < 4; np++) {
            uint32_t kh[4], kl[4];
            uint32_t ka = stage + b_off + np * 16 * APITCH + ks * 32;
            ldsm_x4(ka, kh);
            ldsm_x4(ka + KTILE, kl);
#pragma unroll
            for (int hh = 0; hh < 2; hh++) {
                float* d = s[np * 2 + hh];
                mma16816(d, qh, &kh[hh * 2]);
                mma16816(d, qh, &kl[hh * 2]);
                mma16816(d, ql, &kh[hh * 2]);
            }
        }
    }
}

__global__ void __launch_bounds__(256)
attn_mma_kernel(const __nv_bfloat16* __restrict__ Qhi,
                const __nv_bfloat16* __restrict__ Qlo,
                const __nv_bfloat16* __restrict__ Khi,
                const __nv_bfloat16* __restrict__ Klo,
                const __nv_bfloat16* __restrict__ Vhi,
                const __nv_bfloat16* __restrict__ Vlo,
                float* __restrict__ O)
{
    extern __shared__ char smem[];
    const uint32_t sb = smem_u32(smem);
    const int tid = threadIdx.x, lane = tid & 31, wid = tid >> 5;
    const int qt = blockIdx.x, h = blockIdx.y, b = blockIdx.z;
    const int q0 = qt * 128;
    const int wm = wid * 16;

    const __nv_bfloat16* qhb = Qhi + ((size_t)b * SS + q0) * DD + h * HD;
    const __nv_bfloat16* qlb = Qlo + ((size_t)b * SS + q0) * DD + h * HD;
    const __nv_bfloat16* khb = Khi + (size_t)b * SS * DD + h * HD;
    const __nv_bfloat16* klb = Klo + (size_t)b * SS * DD + h * HD;
    const __nv_bfloat16* vhb = Vhi + (size_t)b * SS * DD + h * HD;
    const __nv_bfloat16* vlb = Vlo + (size_t)b * SS * DD + h * HD;

    const int lr = tid >> 3;        // 0..31
    const int lc = tid & 7;         // 16B chunk
    const uint32_t kv0 = sb + 2 * QTILE;

    const int nkt = 2 * qt + 2;

    // --- prologue: Q tile + k-tile 0 (group), then k-tile 1 (group) ---
#pragma unroll
    for (int it = 0; it < 4; it++) {
        int r = lr + it * 32;
        size_t goff = (size_t)r * DD + lc * 8;
        uint32_t soff = sb + (uint32_t)(r * APITCH + lc * 16);
        cp16(soff,         qhb + goff);
        cp16(soff + QTILE, qlb + goff);
    }
#pragma unroll
    for (int it = 0; it < 2; it++) {
        int r = lr + it * 32;
        size_t goff = (size_t)r * DD + lc * 8;
        uint32_t soff = kv0 + (uint32_t)(r * APITCH + lc * 16);
        cp16(soff,             khb + goff);
        cp16(soff + KTILE,     klb + goff);
        cp16(soff + 2 * KTILE, vhb + goff);
        cp16(soff + 3 * KTILE, vlb + goff);
    }
    CP_COMMIT();
    // tile 1 (nkt >= 2 always)
#pragma unroll
    for (int it = 0; it < 2; it++) {
        int r = lr + it * 32;
        size_t goff = (size_t)(64 + r) * DD + lc * 8;
        uint32_t soff = kv0 + STAGEA + (uint32_t)(r * APITCH + lc * 16);
        cp16(soff,             khb + goff);
        cp16(soff + KTILE,     klb + goff);
        cp16(soff + 2 * KTILE, vhb + goff);
        cp16(soff + 3 * KTILE, vlb + goff);
    }
    CP_COMMIT();
    CP_WAIT1();          // Q + tile0 arrived
    __syncthreads();

    // fragment address components
    const int g  = lane >> 2;
    const int qd = lane & 3;
    const uint32_t a_off = (uint32_t)((wm + (lane & 7) + ((lane >> 3) & 1) * 8) * APITCH
                                      + ((lane >> 4) & 1) * 16);
    const uint32_t b_off = (uint32_t)(((lane & 7) + ((lane >> 4) & 1) * 8) * APITCH
                                      + ((lane >> 3) & 1) * 16);
    const uint32_t v_off = (uint32_t)(((lane & 7) + ((lane >> 3) & 1) * 8) * APITCH
                                      + ((lane >> 4) & 1) * 16);

    float m0 = -1e30f, m1 = -1e30f, l0 = 0.f, l1 = 0.f;
    float o[8][4];
#pragma unroll
    for (int i = 0; i < 8; i++)
#pragma unroll
        for (int j = 0; j < 4; j++) o[i][j] = 0.f;

    const int row0 = q0 + wm + g;
    const int wlimit = q0 + wm + 15;   // last row this warp owns

    float s_cur[8][4], s_next[8][4];
    qk_tile(s_cur, sb, kv0, a_off, b_off);   // tile 0 (needed by every warp)

    for (int kt = 0; kt < nkt; kt++) {
        const uint32_t stage_cur = kv0 + (uint32_t)(kt % 3) * STAGEA;
        const bool have_next = (kt + 1 < nkt);

        if (have_next) {
            CP_WAIT0();          // tile kt+1 fully arrived
            __syncthreads();     // visible to all warps; stage (kt+2)%3 now dead

            // prefetch tile kt+2 into the dead stage (full iteration of slack)
            if (kt + 2 < nkt) {
                uint32_t pst = kv0 + (uint32_t)((kt + 2) % 3) * STAGEA;
#pragma unroll
                for (int it = 0; it < 2; it++) {
                    int r = lr + it * 32;
                    size_t goff = (size_t)((kt + 2) * 64 + r) * DD + lc * 8;
                    uint32_t soff = pst + (uint32_t)(r * APITCH + lc * 16);
                    cp16(soff,             khb + goff);
                    cp16(soff + KTILE,     klb + goff);
                    cp16(soff + 2 * KTILE, vhb + goff);
                    cp16(soff + 3 * KTILE, vlb + goff);
                }
                CP_COMMIT();
            }

            // QK^T(kt+1) issued BEFORE softmax(kt): MMAs fill the tensor pipe
            // while the exp/shuffle chain below executes on independent regs.
            if ((kt + 1) * 64 <= wlimit)
                qk_tile(s_next, sb, kv0 + (uint32_t)((kt + 1) % 3) * STAGEA,
                        a_off, b_off);
        }

        if (kt * 64 <= wlimit) {
            // --- scale + causal mask ---
            const int kbase0 = kt * 64;
            if (kbase0 + 63 > row0) {
#pragma unroll
                for (int nt = 0; nt < 8; nt++) {
                    int col = kbase0 + nt * 8 + qd * 2;
                    s_cur[nt][0] = (col     <= row0)     ? s_cur[nt][0] * 0.125f : -1e30f;
                    s_cur[nt][1] = (col + 1 <= row0)     ? s_cur[nt][1] * 0.125f : -1e30f;
                    s_cur[nt][2] = (col     <= row0 + 8) ? s_cur[nt][2] * 0.125f : -1e30f;
                    s_cur[nt][3] = (col + 1 <= row0 + 8) ? s_cur[nt][3] * 0.125f : -1e30f;
                }
            } else {
#pragma unroll
                for (int nt = 0; nt < 8; nt++) {
                    s_cur[nt][0] *= 0.125f; s_cur[nt][1] *= 0.125f;
                    s_cur[nt][2] *= 0.125f; s_cur[nt][3] *= 0.125f;
                }
            }

            // --- online softmax (rows g and g+8) ---
            float mx0 = -1e30f, mx1 = -1e30f;
#pragma unroll
            for (int nt = 0; nt < 8; nt++) {
                mx0 = fmaxf(mx0, fmaxf(s_cur[nt][0], s_cur[nt][1]));
                mx1 = fmaxf(mx1, fmaxf(s_cur[nt][2], s_cur[nt][3]));
            }
            mx0 = fmaxf(mx0, __shfl_xor_sync(0xffffffffu, mx0, 1));
            mx0 = fmaxf(mx0, __shfl_xor_sync(0xffffffffu, mx0, 2));
            mx1 = fmaxf(mx1, __shfl_xor_sync(0xffffffffu, mx1, 1));
            mx1 = fmaxf(mx1, __shfl_xor_sync(0xffffffffu, mx1, 2));

            float mn0 = fmaxf(m0, mx0), mn1 = fmaxf(m1, mx1);
            float c0 = __expf(m0 - mn0), c1 = __expf(m1 - mn1);
            m0 = mn0; m1 = mn1;

            float sum0 = 0.f, sum1 = 0.f;
#pragma unroll
            for (int nt = 0; nt < 8; nt++) {
                s_cur[nt][0] = __expf(s_cur[nt][0] - mn0); sum0 += s_cur[nt][0];
                s_cur[nt][1] = __expf(s_cur[nt][1] - mn0); sum0 += s_cur[nt][1];
                s_cur[nt][2] = __expf(s_cur[nt][2] - mn1); sum1 += s_cur[nt][2];
                s_cur[nt][3] = __expf(s_cur[nt][3] - mn1); sum1 += s_cur[nt][3];
            }
            sum0 += __shfl_xor_sync(0xffffffffu, sum0, 1);
            sum0 += __shfl_xor_sync(0xffffffffu, sum0, 2);
            sum1 += __shfl_xor_sync(0xffffffffu, sum1, 1);
            sum1 += __shfl_xor_sync(0xffffffffu, sum1, 2);
            l0 = l0 * c0 + sum0;
            l1 = l1 * c1 + sum1;

#pragma unroll
            for (int nt = 0; nt < 8; nt++) {
                o[nt][0] *= c0; o[nt][1] *= c0;
                o[nt][2] *= c1; o[nt][3] *= c1;
            }

            // --- O += P V (bf16x3; P fragment = S accumulator layout) ---
#pragma unroll
            for (int kc = 0; kc < 4; kc++) {
                uint32_t ph[4], pl[4];
                split2(s_cur[2 * kc][0],     s_cur[2 * kc][1],     ph[0], pl[0]);
                split2(s_cur[2 * kc][2],     s_cur[2 * kc][3],     ph[1], pl[1]);
                split2(s_cur[2 * kc + 1][0], s_cur[2 * kc + 1][1], ph[2], pl[2]);
                split2(s_cur[2 * kc + 1][2], s_cur[2 * kc + 1][3], ph[3], pl[3]);
#pragma unroll
                for (int np = 0; np < 4; np++) {
                    uint32_t vh[4], vl[4];
                    uint32_t va = stage_cur + 2 * KTILE + v_off
                                  + kc * 16 * APITCH + np * 32;
                    ldsm_x4_t(va, vh);
                    ldsm_x4_t(va + KTILE, vl);
#pragma unroll
                    for (int hh = 0; hh < 2; hh++) {
                        float* d = o[np * 2 + hh];
                        mma16816(d, ph, &vh[hh * 2]);
                        mma16816(d, ph, &vl[hh * 2]);
                        mma16816(d, pl, &vh[hh * 2]);
                    }
                }
            }
        }

        // rotate pipeline registers
#pragma unroll
        for (int i = 0; i < 8; i++)
#pragma unroll
            for (int j = 0; j < 4; j++) s_cur[i][j] = s_next[i][j];
    }

    // --- epilogue: normalize and store ---
    const float inv0 = 1.0f / l0, inv1 = 1.0f / l1;
    float* ob0 = O + ((size_t)b * SS + row0) * DD + h * HD;
    float* ob1 = O + ((size_t)b * SS + row0 + 8) * DD + h * HD;
#pragma unroll
    for (int nt = 0; nt < 8; nt++) {
        int col = nt * 8 + qd * 2;
        *reinterpret_cast<float2*>(&ob0[col]) =
            make_float2(o[nt][0] * inv0, o[nt][1] * inv0);
        *reinterpret_cast<float2*>(&ob1[col]) =
            make_float2(o[nt][2] * inv1, o[nt][3] * inv1);
    }
}

// ---------------- launch ------------------------------------------------------
extern "C" void kernel_launch(void* const* d_in, const int* in_sizes, int n_in,
                              void* d_out, int out_size)
{
    const float* hs     = (const float*)d_in[0];
    const float* WQ_w   = (const float*)d_in[1];
    const float* WQ_b   = (const float*)d_in[2];
    const float* WK_A_w = (const float*)d_in[3];
    const float* WK_B_w = (const float*)d_in[4];
    const float* WK_B_b = (const float*)d_in[5];
    const float* WV_A_w = (const float*)d_in[6];
    const float* WV_B_w = (const float*)d_in[7];
    const float* WV_B_b = (const float*)d_in[8];
    const float* c_w    = (const float*)d_in[9];
    const float* c_b    = (const float*)d_in[10];
    float* out = (float*)d_out;

    float *gatt, *gtmpk, *gtmpv, *gcpt;
    __nv_bfloat16 *qhi, *qlo, *khi, *klo, *vhi, *vlo;
    cudaGetSymbolAddress((void**)&gatt,  g_att);
    cudaGetSymbolAddress((void**)&gtmpk, g_tmpk);
    cudaGetSymbolAddress((void**)&gtmpv, g_tmpv);
    cudaGetSymbolAddress((void**)&gcpt,  g_cpt);
    cudaGetSymbolAddress((void**)&qhi,   g_qhi);
    cudaGetSymbolAddress((void**)&qlo,   g_qlo);
    cudaGetSymbolAddress((void**)&khi,   g_khi);
    cudaGetSymbolAddress((void**)&klo,   g_klo);
    cudaGetSymbolAddress((void**)&vhi,   g_vhi);
    cudaGetSymbolAddress((void**)&vlo,   g_vlo);

    cudaFuncSetAttribute(hmma_gemm<true, false>,
                         cudaFuncAttributeMaxDynamicSharedMemorySize, HMMA_SMEM);
    cudaFuncSetAttribute(hmma_gemm<true, true>,
                         cudaFuncAttributeMaxDynamicSharedMemorySize, HMMA_SMEM);
    cudaFuncSetAttribute(hmma_gemm_dual_f32,
                         cudaFuncAttributeMaxDynamicSharedMemorySize, HMMA_SMEM);
    cudaFuncSetAttribute(hmma_gemm_dual_split,
                         cudaFuncAttributeMaxDynamicSharedMemorySize, HMMA_SMEM);
    cudaFuncSetAttribute(attn_mma_kernel,
                         cudaFuncAttributeMaxDynamicSharedMemorySize, ATT_SMEM);

    dim3 blk(256);

    // c_proj: [K,N] -> [N,K] once
    transpose_kernel<<<dim3(DD / 32, DD / 32), blk>>>(c_w, gcpt, DD, DD);

    // Q = hs @ WQ^T + b  -> split bf16
    hmma_gemm<true, true><<<dim3(DD / 128, MTOT / 128), blk, HMMA_SMEM>>>(
        hs, WQ_w, WQ_b, nullptr, qhi, qlo, MTOT, DD, DD);

    // stage-1 low-rank: tmp_k = hs @ WK_A^T, tmp_v = hs @ WV_A^T  (one launch)
    hmma_gemm_dual_f32<<<dim3(RR / 128, MTOT / 128, 2), blk, HMMA_SMEM>>>(
        hs, WK_A_w, WV_A_w, gtmpk, gtmpv, MTOT, RR, DD);

    // stage-2: K = tmp_k @ WK_B^T + b, V = tmp_v @ WV_B^T + b  (one launch, split out)
    hmma_gemm_dual_split<<<dim3(DD / 128, MTOT / 128, 2), blk, HMMA_SMEM>>>(
        gtmpk, gtmpv, WK_B_w, WV_B_w, WK_B_b, WV_B_b,
        khi, klo, vhi, vlo, MTOT, DD, RR);

    // causal attention (HMMA flash, software-pipelined)
    attn_mma_kernel<<<dim3(SS / 128, HH, BB), blk, ATT_SMEM>>>(
        qhi, qlo, khi, klo, vhi, vlo, gatt);

    // out = att @ c_proj + b   (via transposed weights)
    hmma_gemm<true, false><<<dim3(DD / 128, MTOT / 128), blk, HMMA_SMEM>>>(
        gatt, gcpt, c_b, out, nullptr, nullptr, MTOT, DD, DD);

    (void)in_sizes; (void)n_in; (void)out_size;
}

// round 10
// speedup vs baseline: 1.1333x; 1.1333x over previous
#include <cuda_runtime.h>
#include <cuda_bf16.h>
#include <cuda_fp16.h>
#include <cstdint>
#include <cstddef>

// Problem dims (fixed)
#define BB 4
#define SS 2048
#define DD 1024
#define HH 16
#define HD 64
#define RR 512
#define MTOT (BB*SS)          // 8192 rows

// ---------------- scratch (device globals: allocation-guard safe) -------------
__device__ float g_att [(size_t)MTOT * DD];   // 32 MB
__device__ float g_tmpk[(size_t)MTOT * RR];   // 16 MB
__device__ float g_tmpv[(size_t)MTOT * RR];   // 16 MB
__device__ float g_cpt [(size_t)DD * DD];     // 4 MB  (c_proj transposed -> [N,K])
// fp16 Q (single) and K/V (hi/lo) written by projection GEMM epilogues
__device__ __half g_qh [(size_t)MTOT * DD];
__device__ __half g_khi[(size_t)MTOT * DD];
__device__ __half g_klo[(size_t)MTOT * DD];
__device__ __half g_vhi[(size_t)MTOT * DD];
__device__ __half g_vlo[(size_t)MTOT * DD];

// ---------------- mma.sync helpers (family-stable, OK on compute_103) ----------
__device__ __forceinline__ uint32_t smem_u32(const void* p) {
    uint32_t a;
    asm("{ .reg .u64 t; cvta.to.shared.u64 t, %1; cvt.u32.u64 %0, t; }"
        : "=r"(a) : "l"(p));
    return a;
}

__device__ __forceinline__ void ldsm_x4(uint32_t addr, uint32_t* r) {
    asm volatile("ldmatrix.sync.aligned.m8n8.x4.shared.b16 {%0,%1,%2,%3}, [%4];"
                 : "=r"(r[0]), "=r"(r[1]), "=r"(r[2]), "=r"(r[3]) : "r"(addr));
}
__device__ __forceinline__ void ldsm_x4_t(uint32_t addr, uint32_t* r) {
    asm volatile("ldmatrix.sync.aligned.m8n8.x4.trans.shared.b16 {%0,%1,%2,%3}, [%4];"
                 : "=r"(r[0]), "=r"(r[1]), "=r"(r[2]), "=r"(r[3]) : "r"(addr));
}
// bf16 MMA (projection GEMMs)
__device__ __forceinline__ void mma16816(float* d, const uint32_t* a, const uint32_t* b) {
    asm volatile(
        "mma.sync.aligned.m16n8k16.row.col.f32.bf16.bf16.f32 "
        "{%0,%1,%2,%3}, {%4,%5,%6,%7}, {%8,%9}, {%0,%1,%2,%3};"
        : "+f"(d[0]), "+f"(d[1]), "+f"(d[2]), "+f"(d[3])
        : "r"(a[0]), "r"(a[1]), "r"(a[2]), "r"(a[3]), "r"(b[0]), "r"(b[1]));
}
// fp16 MMA (attention)
__device__ __forceinline__ void mma16816h(float* d, const uint32_t* a, const uint32_t* b) {
    asm volatile(
        "mma.sync.aligned.m16n8k16.row.col.f32.f16.f16.f32 "
        "{%0,%1,%2,%3}, {%4,%5,%6,%7}, {%8,%9}, {%0,%1,%2,%3};"
        : "+f"(d[0]), "+f"(d[1]), "+f"(d[2]), "+f"(d[3])
        : "r"(a[0]), "r"(a[1]), "r"(a[2]), "r"(a[3]), "r"(b[0]), "r"(b[1]));
}

__device__ __forceinline__ void cp16(uint32_t dst, const void* src) {
    asm volatile("cp.async.cg.shared.global [%0], [%1], 16;"
                 :: "r"(dst), "l"(src) : "memory");
}
#define CP_COMMIT()  asm volatile("cp.async.commit_group;" ::: "memory")
#define CP_WAIT1()   asm volatile("cp.async.wait_group 1;" ::: "memory")
#define CP_WAIT0()   asm volatile("cp.async.wait_group 0;" ::: "memory")

// split a float4 into packed-bf16 hi(8B) and lo(8B)  (GEMM internals)
__device__ __forceinline__ void split_f4(float4 v, uint2& hi, uint2& lo) {
    __nv_bfloat16 h0 = __float2bfloat16(v.x), h1 = __float2bfloat16(v.y);
    __nv_bfloat16 h2 = __float2bfloat16(v.z), h3 = __float2bfloat16(v.w);
    __nv_bfloat16 l0 = __float2bfloat16(v.x - __bfloat162float(h0));
    __nv_bfloat16 l1 = __float2bfloat16(v.y - __bfloat162float(h1));
    __nv_bfloat16 l2 = __float2bfloat16(v.z - __bfloat162float(h2));
    __nv_bfloat16 l3 = __float2bfloat16(v.w - __bfloat162float(h3));
    __nv_bfloat162 hp0(h0, h1), hp1(h2, h3), lp0(l0, l1), lp1(l2, l3);
    hi.x = *reinterpret_cast<uint32_t*>(&hp0);
    hi.y = *reinterpret_cast<uint32_t*>(&hp1);
    lo.x = *reinterpret_cast<uint32_t*>(&lp0);
    lo.y = *reinterpret_cast<uint32_t*>(&lp1);
}

__device__ __forceinline__ uint32_t pack_h2(float x, float y) {
    __half2 h = __floats2half2_rn(x, y);
    return *reinterpret_cast<uint32_t*>(&h);
}
// split a pair of floats into packed fp16 hi / lo
__device__ __forceinline__ void split2h(float x, float y, uint32_t& hi, uint32_t& lo) {
    __half hx = __float2half_rn(x), hy = __float2half_rn(y);
    __half lx = __float2half_rn(x - __half2float(hx));
    __half ly = __float2half_rn(y - __half2float(hy));
    __half2 hp(hx, hy), lp(lx, ly);
    hi = *reinterpret_cast<uint32_t*>(&hp);
    lo = *reinterpret_cast<uint32_t*>(&lp);
}

// ---------------- HMMA bf16x3 GEMM core -----------------------------------------
// C[M,N] = A[M,K] @ B[N,K]^T (+ bias). fp32 in.
// OMODE: 0 = fp32 out (C), 1 = single fp16 out (Chi), 2 = fp16 hi/lo out (Chi,Clo)
#define PITCH 80
#define TILE_B (128 * PITCH)
#define STAGE_B (4 * TILE_B)
#define HMMA_SMEM (2 * STAGE_B)

template <bool BIAS, int OMODE>
__device__ __forceinline__ void
hmma_core(const float* __restrict__ A, const float* __restrict__ B,
          const float* __restrict__ bias, float* __restrict__ C,
          __half* __restrict__ Chi, __half* __restrict__ Clo,
          int M, int N, int K)
{
    extern __shared__ char smem[];
    const uint32_t sb = smem_u32(smem);

    const int tid  = threadIdx.x;
    const int lane = tid & 31;
    const int wid  = tid >> 5;
    const int m0 = blockIdx.y * 128, n0 = blockIdx.x * 128;
    const int wm = (wid & 3) * 32;
    const int wn = (wid >> 2) * 64;

    const int lr = tid >> 3;
    const int lq = tid & 7;

    const int a_row = wm + (lane & 7) + ((lane >> 3) & 1) * 8;
    const int a_kb  = ((lane >> 4) & 1) * 16;
    const int b_row = wn + (lane & 7) + ((lane >> 4) & 1) * 8;
    const int b_kb  = ((lane >> 3) & 1) * 16;

    float acc[2][8][4];
#pragma unroll
    for (int i = 0; i < 2; i++)
#pragma unroll
        for (int j = 0; j < 8; j++)
#pragma unroll
            for (int k = 0; k < 4; k++) acc[i][j][k] = 0.f;

    const int NC = K >> 5;

    float4 ra[4], rb[4];
#pragma unroll
    for (int p = 0; p < 4; p++) {
        int row = lr + p * 32;
        ra[p] = *reinterpret_cast<const float4*>(&A[(size_t)(m0 + row) * K + lq * 4]);
        rb[p] = *reinterpret_cast<const float4*>(&B[(size_t)(n0 + row) * K + lq * 4]);
    }
#pragma unroll
    for (int p = 0; p < 4; p++) {
        int row = lr + p * 32;
        uint32_t off = (uint32_t)(row * PITCH + lq * 8);
        uint2 hi, lo;
        split_f4(ra[p], hi, lo);
        *reinterpret_cast<uint2*>(smem + (off))              = hi;
        *reinterpret_cast<uint2*>(smem + (off + TILE_B))     = lo;
        split_f4(rb[p], hi, lo);
        *reinterpret_cast<uint2*>(smem + (off + 2 * TILE_B)) = hi;
        *reinterpret_cast<uint2*>(smem + (off + 3 * TILE_B)) = lo;
    }
    __syncthreads();

    for (int c = 0; c < NC; c++) {
        if (c + 1 < NC) {
            const int kc = (c + 1) << 5;
#pragma unroll
            for (int p = 0; p < 4; p++) {
                int row = lr + p * 32;
                ra[p] = *reinterpret_cast<const float4*>(
                    &A[(size_t)(m0 + row) * K + kc + lq * 4]);
                rb[p] = *reinterpret_cast<const float4*>(
                    &B[(size_t)(n0 + row) * K + kc + lq * 4]);
            }
        }

        const uint32_t st = sb + (uint32_t)(c & 1) * STAGE_B;
#pragma unroll
        for (int ks = 0; ks < 2; ks++) {
            uint32_t ah[2][4], al[2][4];
#pragma unroll
            for (int mt = 0; mt < 2; mt++) {
                uint32_t aaddr = st + (uint32_t)((a_row + mt * 16) * PITCH + a_kb + ks * 32);
                ldsm_x4(aaddr, ah[mt]);
                ldsm_x4(aaddr + TILE_B, al[mt]);
            }
#pragma unroll
            for (int nt2 = 0; nt2 < 4; nt2++) {
                uint32_t bh[4], bl[4];
                uint32_t baddr = st + 2 * TILE_B +
                    (uint32_t)((b_row + nt2 * 16) * PITCH + b_kb + ks * 32);
                ldsm_x4(baddr, bh);
                ldsm_x4(baddr + TILE_B, bl);
#pragma unroll
                for (int mt = 0; mt < 2; mt++) {
#pragma unroll
                    for (int half = 0; half < 2; half++) {
                        float* d = acc[mt][nt2 * 2 + half];
                        mma16816(d, ah[mt], &bh[half * 2]);
                        mma16816(d, ah[mt], &bl[half * 2]);
                        mma16816(d, al[mt], &bh[half * 2]);
                    }
                }
            }
        }

        if (c + 1 < NC) {
            char* so = smem + (size_t)((c + 1) & 1) * STAGE_B;
#pragma unroll
            for (int p = 0; p < 4; p++) {
                int row = lr + p * 32;
                uint32_t off = (uint32_t)(row * PITCH + lq * 8);
                uint2 hi, lo;
                split_f4(ra[p], hi, lo);
                *reinterpret_cast<uint2*>(so + off)              = hi;
                *reinterpret_cast<uint2*>(so + off + TILE_B)     = lo;
                split_f4(rb[p], hi, lo);
                *reinterpret_cast<uint2*>(so + off + 2 * TILE_B) = hi;
                *reinterpret_cast<uint2*>(so + off + 3 * TILE_B) = lo;
            }
        }
        __syncthreads();
    }

    const int g = lane >> 2;
    const int cpair = (lane & 3) * 2;
#pragma unroll
    for (int mt = 0; mt < 2; mt++) {
#pragma unroll
        for (int nt = 0; nt < 8; nt++) {
            int col = n0 + wn + nt * 8 + cpair;
            float bx = 0.f, by = 0.f;
            if (BIAS) { bx = bias[col]; by = bias[col + 1]; }
            int row0 = m0 + wm + mt * 16 + g;
            float x0 = acc[mt][nt][0] + bx, y0 = acc[mt][nt][1] + by;
            float x1 = acc[mt][nt][2] + bx, y1 = acc[mt][nt][3] + by;
            size_t o0 = (size_t)row0 * N + col;
            size_t o1 = (size_t)(row0 + 8) * N + col;
            if (OMODE == 0) {
                *reinterpret_cast<float2*>(&C[o0]) = make_float2(x0, y0);
                *reinterpret_cast<float2*>(&C[o1]) = make_float2(x1, y1);
            } else if (OMODE == 1) {
                *reinterpret_cast<uint32_t*>(Chi + o0) = pack_h2(x0, y0);
                *reinterpret_cast<uint32_t*>(Chi + o1) = pack_h2(x1, y1);
            } else {
                uint32_t hi, lo;
                split2h(x0, y0, hi, lo);
                *reinterpret_cast<uint32_t*>(Chi + o0) = hi;
                *reinterpret_cast<uint32_t*>(Clo + o0) = lo;
                split2h(x1, y1, hi, lo);
                *reinterpret_cast<uint32_t*>(Chi + o1) = hi;
                *reinterpret_cast<uint32_t*>(Clo + o1) = lo;
            }
        }
    }
}

template <bool BIAS, int OMODE>
__global__ void __launch_bounds__(256)
hmma_gemm(const float* __restrict__ A, const float* __restrict__ B,
          const float* __restrict__ bias, float* __restrict__ C,
          __half* __restrict__ Chi, __half* __restrict__ Clo,
          int M, int N, int K)
{
    hmma_core<BIAS, OMODE>(A, B, bias, C, Chi, Clo, M, N, K);
}

// dual fp32-out GEMM (stage-1 K/V low-rank): z selects operand set
__global__ void __launch_bounds__(256)
hmma_gemm_dual_f32(const float* __restrict__ A,
                   const float* __restrict__ B0, const float* __restrict__ B1,
                   float* __restrict__ C0, float* __restrict__ C1,
                   int M, int N, int K)
{
    if (blockIdx.z == 0)
        hmma_core<false, 0>(A, B0, nullptr, C0, nullptr, nullptr, M, N, K);
    else
        hmma_core<false, 0>(A, B1, nullptr, C1, nullptr, nullptr, M, N, K);
}

// dual fp16-split-out GEMM (stage-2 K/V): z selects operand set
__global__ void __launch_bounds__(256)
hmma_gemm_dual_split(const float* __restrict__ A0, const float* __restrict__ A1,
                     const float* __restrict__ B0, const float* __restrict__ B1,
                     const float* __restrict__ bias0, const float* __restrict__ bias1,
                     __half* __restrict__ C0hi, __half* __restrict__ C0lo,
                     __half* __restrict__ C1hi, __half* __restrict__ C1lo,
                     int M, int N, int K)
{
    if (blockIdx.z == 0)
        hmma_core<true, 2>(A0, B0, bias0, nullptr, C0hi, C0lo, M, N, K);
    else
        hmma_core<true, 2>(A1, B1, bias1, nullptr, C1hi, C1lo, M, N, K);
}

// ---------------- fp32 transpose (for c_proj: [K,N] -> [N,K]) ------------------
__global__ void __launch_bounds__(256)
transpose_kernel(const float* __restrict__ W, float* __restrict__ out, int K, int N)
{
    __shared__ float t[32][33];
    int k0 = blockIdx.y * 32, n0 = blockIdx.x * 32;
    int tx = threadIdx.x & 31, ty = threadIdx.x >> 5;
#pragma unroll
    for (int i = 0; i < 32; i += 8)
        t[ty + i][tx] = W[(size_t)(k0 + ty + i) * N + n0 + tx];
    __syncthreads();
#pragma unroll
    for (int i = 0; i < 32; i += 8)
        out[(size_t)(n0 + ty + i) * K + k0 + tx] = t[tx][ty + i];
}

// ---------------- HMMA flash attention (fp16 2-term, cp.async pipelined) -------
// grid (S/128, H, B), 256 threads (8 warps x 16 q-rows), k-tiles of 64, 2 stages.
// QK = Qh*(Khi+Klo), PV = Ph*(Vhi+Vlo): 128 MMAs/tile (was 192), no split ALU.
#define APITCH 144                 // bytes per 64-fp16 row (128B + 16B pad)
#define QTILE (128 * APITCH)       // 18432 (Q single fp16)
#define KTILE (64 * APITCH)        // 9216
#define STAGEA (4 * KTILE)         // Khi,Klo,Vhi,Vlo = 36864
#define ATT_SMEM (QTILE + 2 * STAGEA)   // 92160

__global__ void __launch_bounds__(256)
attn_mma_kernel(const __half* __restrict__ Qh,
                const __half* __restrict__ Khi,
                const __half* __restrict__ Klo,
                const __half* __restrict__ Vhi,
                const __half* __restrict__ Vlo,
                float* __restrict__ O)
{
    extern __shared__ char smem[];
    const uint32_t sb = smem_u32(smem);
    const int tid = threadIdx.x, lane = tid & 31, wid = tid >> 5;
    const int qt = blockIdx.x, h = blockIdx.y, b = blockIdx.z;
    const int q0 = qt * 128;
    const int wm = wid * 16;

    const __half* qhb = Qh  + ((size_t)b * SS + q0) * DD + h * HD;
    const __half* khb = Khi + (size_t)b * SS * DD + h * HD;
    const __half* klb = Klo + (size_t)b * SS * DD + h * HD;
    const __half* vhb = Vhi + (size_t)b * SS * DD + h * HD;
    const __half* vlb = Vlo + (size_t)b * SS * DD + h * HD;

    const int lr = tid >> 3;        // 0..31
    const int lc = tid & 7;         // 16B chunk
    const uint32_t kv0 = sb + QTILE;

    // --- prologue: Q tile (128 rows) + k-tile 0, one cp.async group ---
#pragma unroll
    for (int it = 0; it < 4; it++) {
        int r = lr + it * 32;       // 0..127
        cp16(sb + (uint32_t)(r * APITCH + lc * 16), qhb + (size_t)r * DD + lc * 8);
    }
#pragma unroll
    for (int it = 0; it < 2; it++) {
        int r = lr + it * 32;       // 0..63
        size_t goff = (size_t)r * DD + lc * 8;
        uint32_t soff = kv0 + (uint32_t)(r * APITCH + lc * 16);
        cp16(soff,             khb + goff);
        cp16(soff + KTILE,     klb + goff);
        cp16(soff + 2 * KTILE, vhb + goff);
        cp16(soff + 3 * KTILE, vlb + goff);
    }
    CP_COMMIT();

    // fragment address components
    const int g  = lane >> 2;
    const int qd = lane & 3;
    const uint32_t a_off = (uint32_t)((wm + (lane & 7) + ((lane >> 3) & 1) * 8) * APITCH
                                      + ((lane >> 4) & 1) * 16);
    const uint32_t b_off = (uint32_t)(((lane & 7) + ((lane >> 4) & 1) * 8) * APITCH
                                      + ((lane >> 3) & 1) * 16);
    const uint32_t v_off = (uint32_t)(((lane & 7) + ((lane >> 3) & 1) * 8) * APITCH
                                      + ((lane >> 4) & 1) * 16);

    float m0 = -1e30f, m1 = -1e30f, l0 = 0.f, l1 = 0.f;
    float o[8][4];
#pragma unroll
    for (int i = 0; i < 8; i++)
#pragma unroll
        for (int j = 0; j < 4; j++) o[i][j] = 0.f;

    const int row0 = q0 + wm + g;
    const int nkt = 2 * qt + 2;

    for (int kt = 0; kt < nkt; kt++) {
        const uint32_t stage = kv0 + (uint32_t)(kt & 1) * STAGEA;

        // issue next tile into the other stage, then drain current tile's group
        if (kt + 1 < nkt) {
            const uint32_t nst = kv0 + (uint32_t)((kt + 1) & 1) * STAGEA;
#pragma unroll
            for (int it = 0; it < 2; it++) {
                int r = lr + it * 32;
                size_t goff = (size_t)((kt + 1) * 64 + r) * DD + lc * 8;
                uint32_t soff = nst + (uint32_t)(r * APITCH + lc * 16);
                cp16(soff,             khb + goff);
                cp16(soff + KTILE,     klb + goff);
                cp16(soff + 2 * KTILE, vhb + goff);
                cp16(soff + 3 * KTILE, vlb + goff);
            }
            CP_COMMIT();
            CP_WAIT1();
        } else {
            CP_WAIT0();
        }
        __syncthreads();

        if (kt * 64 <= q0 + wm + 15) {
            // --- S = Qh (Khi + Klo) ---
            float s[8][4];
#pragma unroll
            for (int i = 0; i < 8; i++)
#pragma unroll
                for (int j = 0; j < 4; j++) s[i][j] = 0.f;

#pragma unroll
            for (int ks = 0; ks < 4; ks++) {
                uint32_t qh[4];
                ldsm_x4(sb + a_off + ks * 32, qh);
#pragma unroll
                for (int np = 0; np < 4; np++) {
                    uint32_t kh[4], kl[4];
                    uint32_t ka = stage + b_off + np * 16 * APITCH + ks * 32;
                    ldsm_x4(ka, kh);
                    ldsm_x4(ka + KTILE, kl);
#pragma unroll
                    for (int hh = 0; hh < 2; hh++) {
                        float* d = s[np * 2 + hh];
                        mma16816h(d, qh, &kh[hh * 2]);
                        mma16816h(d, qh, &kl[hh * 2]);
                    }
                }
            }

            // --- scale + causal mask ---
            const int kbase0 = kt * 64;
            if (kbase0 + 63 > row0) {
#pragma unroll
                for (int nt = 0; nt < 8; nt++) {
                    int col = kbase0 + nt * 8 + qd * 2;
                    s[nt][0] = (col     <= row0)     ? s[nt][0] * 0.125f : -1e30f;
                    s[nt][1] = (col + 1 <= row0)     ? s[nt][1] * 0.125f : -1e30f;
                    s[nt][2] = (col     <= row0 + 8) ? s[nt][2] * 0.125f : -1e30f;
                    s[nt][3] = (col + 1 <= row0 + 8) ? s[nt][3] * 0.125f : -1e30f;
                }
            } else {
#pragma unroll
                for (int nt = 0; nt < 8; nt++) {
                    s[nt][0] *= 0.125f; s[nt][1] *= 0.125f;
                    s[nt][2] *= 0.125f; s[nt][3] *= 0.125f;
                }
            }

            // --- online softmax (rows g and g+8) ---
            float mx0 = -1e30f, mx1 = -1e30f;
#pragma unroll
            for (int nt = 0; nt < 8; nt++) {
                mx0 = fmaxf(mx0, fmaxf(s[nt][0], s[nt][1]));
                mx1 = fmaxf(mx1, fmaxf(s[nt][2], s[nt][3]));
            }
            mx0 = fmaxf(mx0, __shfl_xor_sync(0xffffffffu, mx0, 1));
            mx0 = fmaxf(mx0, __shfl_xor_sync(0xffffffffu, mx0, 2));
            mx1 = fmaxf(mx1, __shfl_xor_sync(0xffffffffu, mx1, 1));
            mx1 = fmaxf(mx1, __shfl_xor_sync(0xffffffffu, mx1, 2));

            float mn0 = fmaxf(m0, mx0), mn1 = fmaxf(m1, mx1);
            float c0 = __expf(m0 - mn0), c1 = __expf(m1 - mn1);
            m0 = mn0; m1 = mn1;

            float sum0 = 0.f, sum1 = 0.f;
#pragma unroll
            for (int nt = 0; nt < 8; nt++) {
                s[nt][0] = __expf(s[nt][0] - mn0); sum0 += s[nt][0];
                s[nt][1] = __expf(s[nt][1] - mn0); sum0 += s[nt][1];
                s[nt][2] = __expf(s[nt][2] - mn1); sum1 += s[nt][2];
                s[nt][3] = __expf(s[nt][3] - mn1); sum1 += s[nt][3];
            }
            sum0 += __shfl_xor_sync(0xffffffffu, sum0, 1);
            sum0 += __shfl_xor_sync(0xffffffffu, sum0, 2);
            sum1 += __shfl_xor_sync(0xffffffffu, sum1, 1);
            sum1 += __shfl_xor_sync(0xffffffffu, sum1, 2);
            l0 = l0 * c0 + sum0;
            l1 = l1 * c1 + sum1;

#pragma unroll
            for (int nt = 0; nt < 8; nt++) {
                o[nt][0] *= c0; o[nt][1] *= c0;
                o[nt][2] *= c1; o[nt][3] *= c1;
            }

            // --- O += Ph (Vhi + Vlo)  (P packed straight to fp16) ---
#pragma unroll
            for (int kc = 0; kc < 4; kc++) {
                uint32_t ph[4];
                ph[0] = pack_h2(s[2 * kc][0],     s[2 * kc][1]);
                ph[1] = pack_h2(s[2 * kc][2],     s[2 * kc][3]);
                ph[2] = pack_h2(s[2 * kc + 1][0], s[2 * kc + 1][1]);
                ph[3] = pack_h2(s[2 * kc + 1][2], s[2 * kc + 1][3]);
#pragma unroll
                for (int np = 0; np < 4; np++) {
                    uint32_t vh[4], vl[4];
                    uint32_t va = stage + 2 * KTILE + v_off
                                  + kc * 16 * APITCH + np * 32;
                    ldsm_x4_t(va, vh);
                    ldsm_x4_t(va + KTILE, vl);
#pragma unroll
                    for (int hh = 0; hh < 2; hh++) {
                        float* d = o[np * 2 + hh];
                        mma16816h(d, ph, &vh[hh * 2]);
                        mma16816h(d, ph, &vl[hh * 2]);
                    }
                }
            }
        }
        __syncthreads();
    }

    // --- epilogue: normalize and store ---
    const float inv0 = 1.0f / l0, inv1 = 1.0f / l1;
    float* ob0 = O + ((size_t)b * SS + row0) * DD + h * HD;
    float* ob1 = O + ((size_t)b * SS + row0 + 8) * DD + h * HD;
#pragma unroll
    for (int nt = 0; nt < 8; nt++) {
        int col = nt * 8 + qd * 2;
        *reinterpret_cast<float2*>(&ob0[col]) =
            make_float2(o[nt][0] * inv0, o[nt][1] * inv0);
        *reinterpret_cast<float2*>(&ob1[col]) =
            make_float2(o[nt][2] * inv1, o[nt][3] * inv1);
    }
}

// ---------------- launch ------------------------------------------------------
extern "C" void kernel_launch(void* const* d_in, const int* in_sizes, int n_in,
                              void* d_out, int out_size)
{
    const float* hs     = (const float*)d_in[0];
    const float* WQ_w   = (const float*)d_in[1];
    const float* WQ_b   = (const float*)d_in[2];
    const float* WK_A_w = (const float*)d_in[3];
    const float* WK_B_w = (const float*)d_in[4];
    const float* WK_B_b = (const float*)d_in[5];
    const float* WV_A_w = (const float*)d_in[6];
    const float* WV_B_w = (const float*)d_in[7];
    const float* WV_B_b = (const float*)d_in[8];
    const float* c_w    = (const float*)d_in[9];
    const float* c_b    = (const float*)d_in[10];
    float* out = (float*)d_out;

    float *gatt, *gtmpk, *gtmpv, *gcpt;
    __half *qh, *khi, *klo, *vhi, *vlo;
    cudaGetSymbolAddress((void**)&gatt,  g_att);
    cudaGetSymbolAddress((void**)&gtmpk, g_tmpk);
    cudaGetSymbolAddress((void**)&gtmpv, g_tmpv);
    cudaGetSymbolAddress((void**)&gcpt,  g_cpt);
    cudaGetSymbolAddress((void**)&qh,    g_qh);
    cudaGetSymbolAddress((void**)&khi,   g_khi);
    cudaGetSymbolAddress((void**)&klo,   g_klo);
    cudaGetSymbolAddress((void**)&vhi,   g_vhi);
    cudaGetSymbolAddress((void**)&vlo,   g_vlo);

    cudaFuncSetAttribute(hmma_gemm<true, 0>,
                         cudaFuncAttributeMaxDynamicSharedMemorySize, HMMA_SMEM);
    cudaFuncSetAttribute(hmma_gemm<true, 1>,
                         cudaFuncAttributeMaxDynamicSharedMemorySize, HMMA_SMEM);
    cudaFuncSetAttribute(hmma_gemm_dual_f32,
                         cudaFuncAttributeMaxDynamicSharedMemorySize, HMMA_SMEM);
    cudaFuncSetAttribute(hmma_gemm_dual_split,
                         cudaFuncAttributeMaxDynamicSharedMemorySize, HMMA_SMEM);
    cudaFuncSetAttribute(attn_mma_kernel,
                         cudaFuncAttributeMaxDynamicSharedMemorySize, ATT_SMEM);

    dim3 blk(256);

    // c_proj: [K,N] -> [N,K] once
    transpose_kernel<<<dim3(DD / 32, DD / 32), blk>>>(c_w, gcpt, DD, DD);

    // Q = hs @ WQ^T + b  -> single fp16
    hmma_gemm<true, 1><<<dim3(DD / 128, MTOT / 128), blk, HMMA_SMEM>>>(
        hs, WQ_w, WQ_b, nullptr, qh, nullptr, MTOT, DD, DD);

    // stage-1 low-rank: tmp_k = hs @ WK_A^T, tmp_v = hs @ WV_A^T  (one launch)
    hmma_gemm_dual_f32<<<dim3(RR / 128, MTOT / 128, 2), blk, HMMA_SMEM>>>(
        hs, WK_A_w, WV_A_w, gtmpk, gtmpv, MTOT, RR, DD);

    // stage-2: K = tmp_k @ WK_B^T + b, V = tmp_v @ WV_B^T + b  (fp16 hi/lo out)
    hmma_gemm_dual_split<<<dim3(DD / 128, MTOT / 128, 2), blk, HMMA_SMEM>>>(
        gtmpk, gtmpv, WK_B_w, WV_B_w, WK_B_b, WV_B_b,
        khi, klo, vhi, vlo, MTOT, DD, RR);

    // causal attention (fp16 2-term HMMA flash)
    attn_mma_kernel<<<dim3(SS / 128, HH, BB), blk, ATT_SMEM>>>(
        qh, khi, klo, vhi, vlo, gatt);

    // out = att @ c_proj + b   (via transposed weights)
    hmma_gemm<true, 0><<<dim3(DD / 128, MTOT / 128), blk, HMMA_SMEM>>>(
        gatt, gcpt, c_b, out, nullptr, nullptr, MTOT, DD, DD);

    (void)in_sizes; (void)n_in; (void)out_size;
}

// round 11
// speedup vs baseline: 1.2837x; 1.1327x over previous
#include <cuda_runtime.h>
#include <cuda_bf16.h>
#include <cuda_fp16.h>
#include <cstdint>
#include <cstddef>

// Problem dims (fixed)
#define BB 4
#define SS 2048
#define DD 1024
#define HH 16
#define HD 64
#define RR 512
#define MTOT (BB*SS)          // 8192 rows

// ---------------- scratch (device globals: allocation-guard safe) -------------
__device__ float g_att [(size_t)MTOT * DD];   // 32 MB
__device__ float g_tmpk[(size_t)MTOT * RR];   // 16 MB
__device__ float g_tmpv[(size_t)MTOT * RR];   // 16 MB
__device__ float g_cpt [(size_t)DD * DD];     // 4 MB  (c_proj transposed -> [N,K])
// fp16 Q/K/V (single-rounded) written by projection GEMM epilogues
__device__ __half g_qh[(size_t)MTOT * DD];
__device__ __half g_kh[(size_t)MTOT * DD];
__device__ __half g_vh[(size_t)MTOT * DD];

// ---------------- mma.sync helpers (family-stable, OK on compute_103) ----------
__device__ __forceinline__ uint32_t smem_u32(const void* p) {
    uint32_t a;
    asm("{ .reg .u64 t; cvta.to.shared.u64 t, %1; cvt.u32.u64 %0, t; }"
        : "=r"(a) : "l"(p));
    return a;
}

__device__ __forceinline__ void ldsm_x4(uint32_t addr, uint32_t* r) {
    asm volatile("ldmatrix.sync.aligned.m8n8.x4.shared.b16 {%0,%1,%2,%3}, [%4];"
                 : "=r"(r[0]), "=r"(r[1]), "=r"(r[2]), "=r"(r[3]) : "r"(addr));
}
__device__ __forceinline__ void ldsm_x4_t(uint32_t addr, uint32_t* r) {
    asm volatile("ldmatrix.sync.aligned.m8n8.x4.trans.shared.b16 {%0,%1,%2,%3}, [%4];"
                 : "=r"(r[0]), "=r"(r[1]), "=r"(r[2]), "=r"(r[3]) : "r"(addr));
}
// bf16 MMA (projection GEMMs)
__device__ __forceinline__ void mma16816(float* d, const uint32_t* a, const uint32_t* b) {
    asm volatile(
        "mma.sync.aligned.m16n8k16.row.col.f32.bf16.bf16.f32 "
        "{%0,%1,%2,%3}, {%4,%5,%6,%7}, {%8,%9}, {%0,%1,%2,%3};"
        : "+f"(d[0]), "+f"(d[1]), "+f"(d[2]), "+f"(d[3])
        : "r"(a[0]), "r"(a[1]), "r"(a[2]), "r"(a[3]), "r"(b[0]), "r"(b[1]));
}
// fp16 MMA (attention)
__device__ __forceinline__ void mma16816h(float* d, const uint32_t* a, const uint32_t* b) {
    asm volatile(
        "mma.sync.aligned.m16n8k16.row.col.f32.f16.f16.f32 "
        "{%0,%1,%2,%3}, {%4,%5,%6,%7}, {%8,%9}, {%0,%1,%2,%3};"
        : "+f"(d[0]), "+f"(d[1]), "+f"(d[2]), "+f"(d[3])
        : "r"(a[0]), "r"(a[1]), "r"(a[2]), "r"(a[3]), "r"(b[0]), "r"(b[1]));
}

__device__ __forceinline__ void cp16(uint32_t dst, const void* src) {
    asm volatile("cp.async.cg.shared.global [%0], [%1], 16;"
                 :: "r"(dst), "l"(src) : "memory");
}
#define CP_COMMIT()  asm volatile("cp.async.commit_group;" ::: "memory")
#define CP_WAIT1()   asm volatile("cp.async.wait_group 1;" ::: "memory")
#define CP_WAIT0()   asm volatile("cp.async.wait_group 0;" ::: "memory")

// split a float4 into packed-bf16 hi(8B) and lo(8B)  (GEMM internals)
__device__ __forceinline__ void split_f4(float4 v, uint2& hi, uint2& lo) {
    __nv_bfloat16 h0 = __float2bfloat16(v.x), h1 = __float2bfloat16(v.y);
    __nv_bfloat16 h2 = __float2bfloat16(v.z), h3 = __float2bfloat16(v.w);
    __nv_bfloat16 l0 = __float2bfloat16(v.x - __bfloat162float(h0));
    __nv_bfloat16 l1 = __float2bfloat16(v.y - __bfloat162float(h1));
    __nv_bfloat16 l2 = __float2bfloat16(v.z - __bfloat162float(h2));
    __nv_bfloat16 l3 = __float2bfloat16(v.w - __bfloat162float(h3));
    __nv_bfloat162 hp0(h0, h1), hp1(h2, h3), lp0(l0, l1), lp1(l2, l3);
    hi.x = *reinterpret_cast<uint32_t*>(&hp0);
    hi.y = *reinterpret_cast<uint32_t*>(&hp1);
    lo.x = *reinterpret_cast<uint32_t*>(&lp0);
    lo.y = *reinterpret_cast<uint32_t*>(&lp1);
}

__device__ __forceinline__ uint32_t pack_h2(float x, float y) {
    __half2 h = __floats2half2_rn(x, y);
    return *reinterpret_cast<uint32_t*>(&h);
}

// ---------------- HMMA bf16x3 GEMM core -----------------------------------------
// C[M,N] = A[M,K] @ B[N,K]^T (+ bias). fp32 in.
// OMODE: 0 = fp32 out (C), 1 = single fp16 out (Chi)
#define PITCH 80
#define TILE_B (128 * PITCH)
#define STAGE_B (4 * TILE_B)
#define HMMA_SMEM (2 * STAGE_B)

template <bool BIAS, int OMODE>
__device__ __forceinline__ void
hmma_core(const float* __restrict__ A, const float* __restrict__ B,
          const float* __restrict__ bias, float* __restrict__ C,
          __half* __restrict__ Chi,
          int M, int N, int K)
{
    extern __shared__ char smem[];
    const uint32_t sb = smem_u32(smem);

    const int tid  = threadIdx.x;
    const int lane = tid & 31;
    const int wid  = tid >> 5;
    const int m0 = blockIdx.y * 128, n0 = blockIdx.x * 128;
    const int wm = (wid & 3) * 32;
    const int wn = (wid >> 2) * 64;

    const int lr = tid >> 3;
    const int lq = tid & 7;

    const int a_row = wm + (lane & 7) + ((lane >> 3) & 1) * 8;
    const int a_kb  = ((lane >> 4) & 1) * 16;
    const int b_row = wn + (lane & 7) + ((lane >> 4) & 1) * 8;
    const int b_kb  = ((lane >> 3) & 1) * 16;

    float acc[2][8][4];
#pragma unroll
    for (int i = 0; i < 2; i++)
#pragma unroll
        for (int j = 0; j < 8; j++)
#pragma unroll
            for (int k = 0; k < 4; k++) acc[i][j][k] = 0.f;

    const int NC = K >> 5;

    float4 ra[4], rb[4];
#pragma unroll
    for (int p = 0; p < 4; p++) {
        int row = lr + p * 32;
        ra[p] = *reinterpret_cast<const float4*>(&A[(size_t)(m0 + row) * K + lq * 4]);
        rb[p] = *reinterpret_cast<const float4*>(&B[(size_t)(n0 + row) * K + lq * 4]);
    }
#pragma unroll
    for (int p = 0; p < 4; p++) {
        int row = lr + p * 32;
        uint32_t off = (uint32_t)(row * PITCH + lq * 8);
        uint2 hi, lo;
        split_f4(ra[p], hi, lo);
        *reinterpret_cast<uint2*>(smem + (off))              = hi;
        *reinterpret_cast<uint2*>(smem + (off + TILE_B))     = lo;
        split_f4(rb[p], hi, lo);
        *reinterpret_cast<uint2*>(smem + (off + 2 * TILE_B)) = hi;
        *reinterpret_cast<uint2*>(smem + (off + 3 * TILE_B)) = lo;
    }
    __syncthreads();

    for (int c = 0; c < NC; c++) {
        if (c + 1 < NC) {
            const int kc = (c + 1) << 5;
#pragma unroll
            for (int p = 0; p < 4; p++) {
                int row = lr + p * 32;
                ra[p] = *reinterpret_cast<const float4*>(
                    &A[(size_t)(m0 + row) * K + kc + lq * 4]);
                rb[p] = *reinterpret_cast<const float4*>(
                    &B[(size_t)(n0 + row) * K + kc + lq * 4]);
            }
        }

        const uint32_t st = sb + (uint32_t)(c & 1) * STAGE_B;
#pragma unroll
        for (int ks = 0; ks < 2; ks++) {
            uint32_t ah[2][4], al[2][4];
#pragma unroll
            for (int mt = 0; mt < 2; mt++) {
                uint32_t aaddr = st + (uint32_t)((a_row + mt * 16) * PITCH + a_kb + ks * 32);
                ldsm_x4(aaddr, ah[mt]);
                ldsm_x4(aaddr + TILE_B, al[mt]);
            }
#pragma unroll
            for (int nt2 = 0; nt2 < 4; nt2++) {
                uint32_t bh[4], bl[4];
                uint32_t baddr = st + 2 * TILE_B +
                    (uint32_t)((b_row + nt2 * 16) * PITCH + b_kb + ks * 32);
                ldsm_x4(baddr, bh);
                ldsm_x4(baddr + TILE_B, bl);
#pragma unroll
                for (int mt = 0; mt < 2; mt++) {
#pragma unroll
                    for (int half = 0; half < 2; half++) {
                        float* d = acc[mt][nt2 * 2 + half];
                        mma16816(d, ah[mt], &bh[half * 2]);
                        mma16816(d, ah[mt], &bl[half * 2]);
                        mma16816(d, al[mt], &bh[half * 2]);
                    }
                }
            }
        }

        if (c + 1 < NC) {
            char* so = smem + (size_t)((c + 1) & 1) * STAGE_B;
#pragma unroll
            for (int p = 0; p < 4; p++) {
                int row = lr + p * 32;
                uint32_t off = (uint32_t)(row * PITCH + lq * 8);
                uint2 hi, lo;
                split_f4(ra[p], hi, lo);
                *reinterpret_cast<uint2*>(so + off)              = hi;
                *reinterpret_cast<uint2*>(so + off + TILE_B)     = lo;
                split_f4(rb[p], hi, lo);
                *reinterpret_cast<uint2*>(so + off + 2 * TILE_B) = hi;
                *reinterpret_cast<uint2*>(so + off + 3 * TILE_B) = lo;
            }
        }
        __syncthreads();
    }

    const int g = lane >> 2;
    const int cpair = (lane & 3) * 2;
#pragma unroll
    for (int mt = 0; mt < 2; mt++) {
#pragma unroll
        for (int nt = 0; nt < 8; nt++) {
            int col = n0 + wn + nt * 8 + cpair;
            float bx = 0.f, by = 0.f;
            if (BIAS) { bx = bias[col]; by = bias[col + 1]; }
            int row0 = m0 + wm + mt * 16 + g;
            float x0 = acc[mt][nt][0] + bx, y0 = acc[mt][nt][1] + by;
            float x1 = acc[mt][nt][2] + bx, y1 = acc[mt][nt][3] + by;
            size_t o0 = (size_t)row0 * N + col;
            size_t o1 = (size_t)(row0 + 8) * N + col;
            if (OMODE == 0) {
                *reinterpret_cast<float2*>(&C[o0]) = make_float2(x0, y0);
                *reinterpret_cast<float2*>(&C[o1]) = make_float2(x1, y1);
            } else {
                *reinterpret_cast<uint32_t*>(Chi + o0) = pack_h2(x0, y0);
                *reinterpret_cast<uint32_t*>(Chi + o1) = pack_h2(x1, y1);
            }
        }
    }
}

template <bool BIAS, int OMODE>
__global__ void __launch_bounds__(256)
hmma_gemm(const float* __restrict__ A, const float* __restrict__ B,
          const float* __restrict__ bias, float* __restrict__ C,
          __half* __restrict__ Chi,
          int M, int N, int K)
{
    hmma_core<BIAS, OMODE>(A, B, bias, C, Chi, M, N, K);
}

// dual fp32-out GEMM (stage-1 K/V low-rank): z selects operand set
__global__ void __launch_bounds__(256)
hmma_gemm_dual_f32(const float* __restrict__ A,
                   const float* __restrict__ B0, const float* __restrict__ B1,
                   float* __restrict__ C0, float* __restrict__ C1,
                   int M, int N, int K)
{
    if (blockIdx.z == 0)
        hmma_core<false, 0>(A, B0, nullptr, C0, nullptr, M, N, K);
    else
        hmma_core<false, 0>(A, B1, nullptr, C1, nullptr, M, N, K);
}

// dual fp16-out GEMM (stage-2 K/V): z selects operand set
__global__ void __launch_bounds__(256)
hmma_gemm_dual_h(const float* __restrict__ A0, const float* __restrict__ A1,
                 const float* __restrict__ B0, const float* __restrict__ B1,
                 const float* __restrict__ bias0, const float* __restrict__ bias1,
                 __half* __restrict__ C0h, __half* __restrict__ C1h,
                 int M, int N, int K)
{
    if (blockIdx.z == 0)
        hmma_core<true, 1>(A0, B0, bias0, nullptr, C0h, M, N, K);
    else
        hmma_core<true, 1>(A1, B1, bias1, nullptr, C1h, M, N, K);
}

// ---------------- fp32 transpose (for c_proj: [K,N] -> [N,K]) ------------------
__global__ void __launch_bounds__(256)
transpose_kernel(const float* __restrict__ W, float* __restrict__ out, int K, int N)
{
    __shared__ float t[32][33];
    int k0 = blockIdx.y * 32, n0 = blockIdx.x * 32;
    int tx = threadIdx.x & 31, ty = threadIdx.x >> 5;
#pragma unroll
    for (int i = 0; i < 32; i += 8)
        t[ty + i][tx] = W[(size_t)(k0 + ty + i) * N + n0 + tx];
    __syncthreads();
#pragma unroll
    for (int i = 0; i < 32; i += 8)
        out[(size_t)(n0 + ty + i) * K + k0 + tx] = t[tx][ty + i];
}

// ---------------- HMMA flash attention (single fp16, cp.async pipelined) -------
// grid (S/128, H, B), 256 threads (8 warps x 16 q-rows), k-tiles of 64, 2 stages.
// QK = Qh*Kh, PV = Ph*Vh: 64 MMAs/tile.
#define APITCH 144                 // bytes per 64-fp16 row (128B + 16B pad)
#define QTILE (128 * APITCH)       // 18432
#define KTILE (64 * APITCH)        // 9216
#define STAGEA (2 * KTILE)         // Kh,Vh = 18432
#define ATT_SMEM (QTILE + 2 * STAGEA)   // 55296

__global__ void __launch_bounds__(256)
attn_mma_kernel(const __half* __restrict__ Qh,
                const __half* __restrict__ Kh,
                const __half* __restrict__ Vh,
                float* __restrict__ O)
{
    extern __shared__ char smem[];
    const uint32_t sb = smem_u32(smem);
    const int tid = threadIdx.x, lane = tid & 31, wid = tid >> 5;
    const int qt = blockIdx.x, h = blockIdx.y, b = blockIdx.z;
    const int q0 = qt * 128;
    const int wm = wid * 16;

    const __half* qhb = Qh + ((size_t)b * SS + q0) * DD + h * HD;
    const __half* khb = Kh + (size_t)b * SS * DD + h * HD;
    const __half* vhb = Vh + (size_t)b * SS * DD + h * HD;

    const int lr = tid >> 3;        // 0..31
    const int lc = tid & 7;         // 16B chunk
    const uint32_t kv0 = sb + QTILE;

    // --- prologue: Q tile (128 rows) + k-tile 0, one cp.async group ---
#pragma unroll
    for (int it = 0; it < 4; it++) {
        int r = lr + it * 32;       // 0..127
        cp16(sb + (uint32_t)(r * APITCH + lc * 16), qhb + (size_t)r * DD + lc * 8);
    }
#pragma unroll
    for (int it = 0; it < 2; it++) {
        int r = lr + it * 32;       // 0..63
        size_t goff = (size_t)r * DD + lc * 8;
        uint32_t soff = kv0 + (uint32_t)(r * APITCH + lc * 16);
        cp16(soff,         khb + goff);
        cp16(soff + KTILE, vhb + goff);
    }
    CP_COMMIT();

    // fragment address components
    const int g  = lane >> 2;
    const int qd = lane & 3;
    const uint32_t a_off = (uint32_t)((wm + (lane & 7) + ((lane >> 3) & 1) * 8) * APITCH
                                      + ((lane >> 4) & 1) * 16);
    const uint32_t b_off = (uint32_t)(((lane & 7) + ((lane >> 4) & 1) * 8) * APITCH
                                      + ((lane >> 3) & 1) * 16);
    const uint32_t v_off = (uint32_t)(((lane & 7) + ((lane >> 3) & 1) * 8) * APITCH
                                      + ((lane >> 4) & 1) * 16);

    float m0 = -1e30f, m1 = -1e30f, l0 = 0.f, l1 = 0.f;
    float o[8][4];
#pragma unroll
    for (int i = 0; i < 8; i++)
#pragma unroll
        for (int j = 0; j < 4; j++) o[i][j] = 0.f;

    const int row0 = q0 + wm + g;
    const int nkt = 2 * qt + 2;

    for (int kt = 0; kt < nkt; kt++) {
        const uint32_t stage = kv0 + (uint32_t)(kt & 1) * STAGEA;

        // issue next tile into the other stage, then drain current tile's group
        if (kt + 1 < nkt) {
            const uint32_t nst = kv0 + (uint32_t)((kt + 1) & 1) * STAGEA;
#pragma unroll
            for (int it = 0; it < 2; it++) {
                int r = lr + it * 32;
                size_t goff = (size_t)((kt + 1) * 64 + r) * DD + lc * 8;
                uint32_t soff = nst + (uint32_t)(r * APITCH + lc * 16);
                cp16(soff,         khb + goff);
                cp16(soff + KTILE, vhb + goff);
            }
            CP_COMMIT();
            CP_WAIT1();
        } else {
            CP_WAIT0();
        }
        __syncthreads();

        if (kt * 64 <= q0 + wm + 15) {
            // --- S = Qh Kh^T ---
            float s[8][4];
#pragma unroll
            for (int i = 0; i < 8; i++)
#pragma unroll
                for (int j = 0; j < 4; j++) s[i][j] = 0.f;

#pragma unroll
            for (int ks = 0; ks < 4; ks++) {
                uint32_t qh[4];
                ldsm_x4(sb + a_off + ks * 32, qh);
#pragma unroll
                for (int np = 0; np < 4; np++) {
                    uint32_t kh[4];
                    ldsm_x4(stage + b_off + np * 16 * APITCH + ks * 32, kh);
#pragma unroll
                    for (int hh = 0; hh < 2; hh++)
                        mma16816h(s[np * 2 + hh], qh, &kh[hh * 2]);
                }
            }

            // --- scale + causal mask ---
            const int kbase0 = kt * 64;
            if (kbase0 + 63 > row0) {
#pragma unroll
                for (int nt = 0; nt < 8; nt++) {
                    int col = kbase0 + nt * 8 + qd * 2;
                    s[nt][0] = (col     <= row0)     ? s[nt][0] * 0.125f : -1e30f;
                    s[nt][1] = (col + 1 <= row0)     ? s[nt][1] * 0.125f : -1e30f;
                    s[nt][2] = (col     <= row0 + 8) ? s[nt][2] * 0.125f : -1e30f;
                    s[nt][3] = (col + 1 <= row0 + 8) ? s[nt][3] * 0.125f : -1e30f;
                }
            } else {
#pragma unroll
                for (int nt = 0; nt < 8; nt++) {
                    s[nt][0] *= 0.125f; s[nt][1] *= 0.125f;
                    s[nt][2] *= 0.125f; s[nt][3] *= 0.125f;
                }
            }

            // --- online softmax (rows g and g+8) ---
            float mx0 = -1e30f, mx1 = -1e30f;
#pragma unroll
            for (int nt = 0; nt < 8; nt++) {
                mx0 = fmaxf(mx0, fmaxf(s[nt][0], s[nt][1]));
                mx1 = fmaxf(mx1, fmaxf(s[nt][2], s[nt][3]));
            }
            mx0 = fmaxf(mx0, __shfl_xor_sync(0xffffffffu, mx0, 1));
            mx0 = fmaxf(mx0, __shfl_xor_sync(0xffffffffu, mx0, 2));
            mx1 = fmaxf(mx1, __shfl_xor_sync(0xffffffffu, mx1, 1));
            mx1 = fmaxf(mx1, __shfl_xor_sync(0xffffffffu, mx1, 2));

            float mn0 = fmaxf(m0, mx0), mn1 = fmaxf(m1, mx1);
            float c0 = __expf(m0 - mn0), c1 = __expf(m1 - mn1);
            m0 = mn0; m1 = mn1;

            float sum0 = 0.f, sum1 = 0.f;
#pragma unroll
            for (int nt = 0; nt < 8; nt++) {
                s[nt][0] = __expf(s[nt][0] - mn0); sum0 += s[nt][0];
                s[nt][1] = __expf(s[nt][1] - mn0); sum0 += s[nt][1];
                s[nt][2] = __expf(s[nt][2] - mn1); sum1 += s[nt][2];
                s[nt][3] = __expf(s[nt][3] - mn1); sum1 += s[nt][3];
            }
            sum0 += __shfl_xor_sync(0xffffffffu, sum0, 1);
            sum0 += __shfl_xor_sync(0xffffffffu, sum0, 2);
            sum1 += __shfl_xor_sync(0xffffffffu, sum1, 1);
            sum1 += __shfl_xor_sync(0xffffffffu, sum1, 2);
            l0 = l0 * c0 + sum0;
            l1 = l1 * c1 + sum1;

#pragma unroll
            for (int nt = 0; nt < 8; nt++) {
                o[nt][0] *= c0; o[nt][1] *= c0;
                o[nt][2] *= c1; o[nt][3] *= c1;
            }

            // --- O += Ph Vh  (P packed straight to fp16) ---
#pragma unroll
            for (int kc = 0; kc < 4; kc++) {
                uint32_t ph[4];
                ph[0] = pack_h2(s[2 * kc][0],     s[2 * kc][1]);
                ph[1] = pack_h2(s[2 * kc][2],     s[2 * kc][3]);
                ph[2] = pack_h2(s[2 * kc + 1][0], s[2 * kc + 1][1]);
                ph[3] = pack_h2(s[2 * kc + 1][2], s[2 * kc + 1][3]);
#pragma unroll
                for (int np = 0; np < 4; np++) {
                    uint32_t vh[4];
                    ldsm_x4_t(stage + KTILE + v_off + kc * 16 * APITCH + np * 32, vh);
#pragma unroll
                    for (int hh = 0; hh < 2; hh++)
                        mma16816h(o[np * 2 + hh], ph, &vh[hh * 2]);
                }
            }
        }
        __syncthreads();
    }

    // --- epilogue: normalize and store ---
    const float inv0 = 1.0f / l0, inv1 = 1.0f / l1;
    float* ob0 = O + ((size_t)b * SS + row0) * DD + h * HD;
    float* ob1 = O + ((size_t)b * SS + row0 + 8) * DD + h * HD;
#pragma unroll
    for (int nt = 0; nt < 8; nt++) {
        int col = nt * 8 + qd * 2;
        *reinterpret_cast<float2*>(&ob0[col]) =
            make_float2(o[nt][0] * inv0, o[nt][1] * inv0);
        *reinterpret_cast<float2*>(&ob1[col]) =
            make_float2(o[nt][2] * inv1, o[nt][3] * inv1);
    }
}

// ---------------- launch ------------------------------------------------------
extern "C" void kernel_launch(void* const* d_in, const int* in_sizes, int n_in,
                              void* d_out, int out_size)
{
    const float* hs     = (const float*)d_in[0];
    const float* WQ_w   = (const float*)d_in[1];
    const float* WQ_b   = (const float*)d_in[2];
    const float* WK_A_w = (const float*)d_in[3];
    const float* WK_B_w = (const float*)d_in[4];
    const float* WK_B_b = (const float*)d_in[5];
    const float* WV_A_w = (const float*)d_in[6];
    const float* WV_B_w = (const float*)d_in[7];
    const float* WV_B_b = (const float*)d_in[8];
    const float* c_w    = (const float*)d_in[9];
    const float* c_b    = (const float*)d_in[10];
    float* out = (float*)d_out;

    float *gatt, *gtmpk, *gtmpv, *gcpt;
    __half *qh, *kh, *vh;
    cudaGetSymbolAddress((void**)&gatt,  g_att);
    cudaGetSymbolAddress((void**)&gtmpk, g_tmpk);
    cudaGetSymbolAddress((void**)&gtmpv, g_tmpv);
    cudaGetSymbolAddress((void**)&gcpt,  g_cpt);
    cudaGetSymbolAddress((void**)&qh,    g_qh);
    cudaGetSymbolAddress((void**)&kh,    g_kh);
    cudaGetSymbolAddress((void**)&vh,    g_vh);

    cudaFuncSetAttribute(hmma_gemm<true, 0>,
                         cudaFuncAttributeMaxDynamicSharedMemorySize, HMMA_SMEM);
    cudaFuncSetAttribute(hmma_gemm<true, 1>,
                         cudaFuncAttributeMaxDynamicSharedMemorySize, HMMA_SMEM);
    cudaFuncSetAttribute(hmma_gemm_dual_f32,
                         cudaFuncAttributeMaxDynamicSharedMemorySize, HMMA_SMEM);
    cudaFuncSetAttribute(hmma_gemm_dual_h,
                         cudaFuncAttributeMaxDynamicSharedMemorySize, HMMA_SMEM);
    cudaFuncSetAttribute(attn_mma_kernel,
                         cudaFuncAttributeMaxDynamicSharedMemorySize, ATT_SMEM);

    dim3 blk(256);

    // c_proj: [K,N] -> [N,K] once
    transpose_kernel<<<dim3(DD / 32, DD / 32), blk>>>(c_w, gcpt, DD, DD);

    // Q = hs @ WQ^T + b  -> single fp16
    hmma_gemm<true, 1><<<dim3(DD / 128, MTOT / 128), blk, HMMA_SMEM>>>(
        hs, WQ_w, WQ_b, nullptr, qh, MTOT, DD, DD);

    // stage-1 low-rank: tmp_k = hs @ WK_A^T, tmp_v = hs @ WV_A^T  (one launch)
    hmma_gemm_dual_f32<<<dim3(RR / 128, MTOT / 128, 2), blk, HMMA_SMEM>>>(
        hs, WK_A_w, WV_A_w, gtmpk, gtmpv, MTOT, RR, DD);

    // stage-2: K = tmp_k @ WK_B^T + b, V = tmp_v @ WV_B^T + b  (single fp16 out)
    hmma_gemm_dual_h<<<dim3(DD / 128, MTOT / 128, 2), blk, HMMA_SMEM>>>(
        gtmpk, gtmpv, WK_B_w, WV_B_w, WK_B_b, WV_B_b,
        kh, vh, MTOT, DD, RR);

    // causal attention (single-fp16 HMMA flash)
    attn_mma_kernel<<<dim3(SS / 128, HH, BB), blk, ATT_SMEM>>>(
        qh, kh, vh, gatt);

    // out = att @ c_proj + b   (via transposed weights)
    hmma_gemm<true, 0><<<dim3(DD / 128, MTOT / 128), blk, HMMA_SMEM>>>(
        gatt, gcpt, c_b, out, nullptr, MTOT, DD, DD);

    (void)in_sizes; (void)n_in; (void)out_size;
}

// round 12
// speedup vs baseline: 1.6217x; 1.2633x over previous
#include <cuda_runtime.h>
#include <cuda_fp16.h>
#include <cstdint>
#include <cstddef>

// Problem dims (fixed)
#define BB 4
#define SS 2048
#define DD 1024
#define HH 16
#define HD 64
#define RR 512
#define MTOT (BB*SS)          // 8192 rows

// ---------------- scratch (device globals: allocation-guard safe) -------------
__device__ float g_att [(size_t)MTOT * DD];   // 32 MB
__device__ float g_tmpk[(size_t)MTOT * RR];   // 16 MB
__device__ float g_tmpv[(size_t)MTOT * RR];   // 16 MB
__device__ float g_cpt [(size_t)DD * DD];     // 4 MB  (c_proj transposed -> [N,K])
// fp16 Q/K/V (single-rounded) written by projection GEMM epilogues
__device__ __half g_qh[(size_t)MTOT * DD];
__device__ __half g_kh[(size_t)MTOT * DD];
__device__ __half g_vh[(size_t)MTOT * DD];

// ---------------- mma.sync helpers (family-stable, OK on compute_103) ----------
__device__ __forceinline__ uint32_t smem_u32(const void* p) {
    uint32_t a;
    asm("{ .reg .u64 t; cvta.to.shared.u64 t, %1; cvt.u32.u64 %0, t; }"
        : "=r"(a) : "l"(p));
    return a;
}

__device__ __forceinline__ void ldsm_x4(uint32_t addr, uint32_t* r) {
    asm volatile("ldmatrix.sync.aligned.m8n8.x4.shared.b16 {%0,%1,%2,%3}, [%4];"
                 : "=r"(r[0]), "=r"(r[1]), "=r"(r[2]), "=r"(r[3]) : "r"(addr));
}
__device__ __forceinline__ void ldsm_x4_t(uint32_t addr, uint32_t* r) {
    asm volatile("ldmatrix.sync.aligned.m8n8.x4.trans.shared.b16 {%0,%1,%2,%3}, [%4];"
                 : "=r"(r[0]), "=r"(r[1]), "=r"(r[2]), "=r"(r[3]) : "r"(addr));
}
// fp16 MMA (used everywhere now)
__device__ __forceinline__ void mma16816h(float* d, const uint32_t* a, const uint32_t* b) {
    asm volatile(
        "mma.sync.aligned.m16n8k16.row.col.f32.f16.f16.f32 "
        "{%0,%1,%2,%3}, {%4,%5,%6,%7}, {%8,%9}, {%0,%1,%2,%3};"
        : "+f"(d[0]), "+f"(d[1]), "+f"(d[2]), "+f"(d[3])
        : "r"(a[0]), "r"(a[1]), "r"(a[2]), "r"(a[3]), "r"(b[0]), "r"(b[1]));
}

__device__ __forceinline__ void cp16(uint32_t dst, const void* src) {
    asm volatile("cp.async.cg.shared.global [%0], [%1], 16;"
                 :: "r"(dst), "l"(src) : "memory");
}
#define CP_COMMIT()  asm volatile("cp.async.commit_group;" ::: "memory")
#define CP_WAIT1()   asm volatile("cp.async.wait_group 1;" ::: "memory")
#define CP_WAIT0()   asm volatile("cp.async.wait_group 0;" ::: "memory")

__device__ __forceinline__ uint32_t pack_h2(float x, float y) {
    __half2 h = __floats2half2_rn(x, y);
    return *reinterpret_cast<uint32_t*>(&h);
}
// pack float4 -> 4 fp16 (single-rounded)
__device__ __forceinline__ void pack_f4h(float4 v, uint2& h) {
    h.x = pack_h2(v.x, v.y);
    h.y = pack_h2(v.z, v.w);
}
// split float4 -> fp16 hi(8B) + fp16 lo(8B)
__device__ __forceinline__ void split_f4h(float4 v, uint2& hi, uint2& lo) {
    __half h0 = __float2half_rn(v.x), h1 = __float2half_rn(v.y);
    __half h2 = __float2half_rn(v.z), h3 = __float2half_rn(v.w);
    __half l0 = __float2half_rn(v.x - __half2float(h0));
    __half l1 = __float2half_rn(v.y - __half2float(h1));
    __half l2 = __float2half_rn(v.z - __half2float(h2));
    __half l3 = __float2half_rn(v.w - __half2float(h3));
    __half2 hp0(h0, h1), hp1(h2, h3), lp0(l0, l1), lp1(l2, l3);
    hi.x = *reinterpret_cast<uint32_t*>(&hp0);
    hi.y = *reinterpret_cast<uint32_t*>(&hp1);
    lo.x = *reinterpret_cast<uint32_t*>(&lp0);
    lo.y = *reinterpret_cast<uint32_t*>(&lp1);
}

// ---------------- HMMA fp16x2 GEMM core ------------------------------------------
// C[M,N] = A[M,K] @ B[N,K]^T (+ bias). fp32 in.
// A single-rounded fp16; B split fp16 hi/lo. 2 MMAs per fragment product.
// OMODE: 0 = fp32 out (C), 1 = single fp16 out (Chi)
#define PITCH 80
#define TILE_B (128 * PITCH)
#define STAGE_B (3 * TILE_B)      // A, Bhi, Blo
#define HMMA_SMEM (2 * STAGE_B)   // 61440

template <bool BIAS, int OMODE>
__device__ __forceinline__ void
hmma_core(const float* __restrict__ A, const float* __restrict__ B,
          const float* __restrict__ bias, float* __restrict__ C,
          __half* __restrict__ Chi,
          int M, int N, int K)
{
    extern __shared__ char smem[];
    const uint32_t sb = smem_u32(smem);

    const int tid  = threadIdx.x;
    const int lane = tid & 31;
    const int wid  = tid >> 5;
    const int m0 = blockIdx.y * 128, n0 = blockIdx.x * 128;
    const int wm = (wid & 3) * 32;
    const int wn = (wid >> 2) * 64;

    const int lr = tid >> 3;
    const int lq = tid & 7;

    const int a_row = wm + (lane & 7) + ((lane >> 3) & 1) * 8;
    const int a_kb  = ((lane >> 4) & 1) * 16;
    const int b_row = wn + (lane & 7) + ((lane >> 4) & 1) * 8;
    const int b_kb  = ((lane >> 3) & 1) * 16;

    float acc[2][8][4];
#pragma unroll
    for (int i = 0; i < 2; i++)
#pragma unroll
        for (int j = 0; j < 8; j++)
#pragma unroll
            for (int k = 0; k < 4; k++) acc[i][j][k] = 0.f;

    const int NC = K >> 5;

    float4 ra[4], rb[4];
#pragma unroll
    for (int p = 0; p < 4; p++) {
        int row = lr + p * 32;
        ra[p] = *reinterpret_cast<const float4*>(&A[(size_t)(m0 + row) * K + lq * 4]);
        rb[p] = *reinterpret_cast<const float4*>(&B[(size_t)(n0 + row) * K + lq * 4]);
    }
#pragma unroll
    for (int p = 0; p < 4; p++) {
        int row = lr + p * 32;
        uint32_t off = (uint32_t)(row * PITCH + lq * 8);
        uint2 ah, hi, lo;
        pack_f4h(ra[p], ah);
        *reinterpret_cast<uint2*>(smem + off) = ah;
        split_f4h(rb[p], hi, lo);
        *reinterpret_cast<uint2*>(smem + (off + TILE_B))     = hi;
        *reinterpret_cast<uint2*>(smem + (off + 2 * TILE_B)) = lo;
    }
    __syncthreads();

    for (int c = 0; c < NC; c++) {
        if (c + 1 < NC) {
            const int kc = (c + 1) << 5;
#pragma unroll
            for (int p = 0; p < 4; p++) {
                int row = lr + p * 32;
                ra[p] = *reinterpret_cast<const float4*>(
                    &A[(size_t)(m0 + row) * K + kc + lq * 4]);
                rb[p] = *reinterpret_cast<const float4*>(
                    &B[(size_t)(n0 + row) * K + kc + lq * 4]);
            }
        }

        const uint32_t st = sb + (uint32_t)(c & 1) * STAGE_B;
#pragma unroll
        for (int ks = 0; ks < 2; ks++) {
            uint32_t ah[2][4];
#pragma unroll
            for (int mt = 0; mt < 2; mt++) {
                uint32_t aaddr = st + (uint32_t)((a_row + mt * 16) * PITCH + a_kb + ks * 32);
                ldsm_x4(aaddr, ah[mt]);
            }
#pragma unroll
            for (int nt2 = 0; nt2 < 4; nt2++) {
                uint32_t bh[4], bl[4];
                uint32_t baddr = st + TILE_B +
                    (uint32_t)((b_row + nt2 * 16) * PITCH + b_kb + ks * 32);
                ldsm_x4(baddr, bh);
                ldsm_x4(baddr + TILE_B, bl);
#pragma unroll
                for (int mt = 0; mt < 2; mt++) {
#pragma unroll
                    for (int half = 0; half < 2; half++) {
                        float* d = acc[mt][nt2 * 2 + half];
                        mma16816h(d, ah[mt], &bh[half * 2]);
                        mma16816h(d, ah[mt], &bl[half * 2]);
                    }
                }
            }
        }

        if (c + 1 < NC) {
            char* so = smem + (size_t)((c + 1) & 1) * STAGE_B;
#pragma unroll
            for (int p = 0; p < 4; p++) {
                int row = lr + p * 32;
                uint32_t off = (uint32_t)(row * PITCH + lq * 8);
                uint2 ah, hi, lo;
                pack_f4h(ra[p], ah);
                *reinterpret_cast<uint2*>(so + off) = ah;
                split_f4h(rb[p], hi, lo);
                *reinterpret_cast<uint2*>(so + off + TILE_B)     = hi;
                *reinterpret_cast<uint2*>(so + off + 2 * TILE_B) = lo;
            }
        }
        __syncthreads();
    }

    const int g = lane >> 2;
    const int cpair = (lane & 3) * 2;
#pragma unroll
    for (int mt = 0; mt < 2; mt++) {
#pragma unroll
        for (int nt = 0; nt < 8; nt++) {
            int col = n0 + wn + nt * 8 + cpair;
            float bx = 0.f, by = 0.f;
            if (BIAS) { bx = bias[col]; by = bias[col + 1]; }
            int row0 = m0 + wm + mt * 16 + g;
            float x0 = acc[mt][nt][0] + bx, y0 = acc[mt][nt][1] + by;
            float x1 = acc[mt][nt][2] + bx, y1 = acc[mt][nt][3] + by;
            size_t o0 = (size_t)row0 * N + col;
            size_t o1 = (size_t)(row0 + 8) * N + col;
            if (OMODE == 0) {
                *reinterpret_cast<float2*>(&C[o0]) = make_float2(x0, y0);
                *reinterpret_cast<float2*>(&C[o1]) = make_float2(x1, y1);
            } else {
                *reinterpret_cast<uint32_t*>(Chi + o0) = pack_h2(x0, y0);
                *reinterpret_cast<uint32_t*>(Chi + o1) = pack_h2(x1, y1);
            }
        }
    }
}

template <bool BIAS, int OMODE>
__global__ void __launch_bounds__(256)
hmma_gemm(const float* __restrict__ A, const float* __restrict__ B,
          const float* __restrict__ bias, float* __restrict__ C,
          __half* __restrict__ Chi,
          int M, int N, int K)
{
    hmma_core<BIAS, OMODE>(A, B, bias, C, Chi, M, N, K);
}

// dual fp32-out GEMM (stage-1 K/V low-rank): z selects operand set
__global__ void __launch_bounds__(256)
hmma_gemm_dual_f32(const float* __restrict__ A,
                   const float* __restrict__ B0, const float* __restrict__ B1,
                   float* __restrict__ C0, float* __restrict__ C1,
                   int M, int N, int K)
{
    if (blockIdx.z == 0)
        hmma_core<false, 0>(A, B0, nullptr, C0, nullptr, M, N, K);
    else
        hmma_core<false, 0>(A, B1, nullptr, C1, nullptr, M, N, K);
}

// dual fp16-out GEMM (stage-2 K/V): z selects operand set
__global__ void __launch_bounds__(256)
hmma_gemm_dual_h(const float* __restrict__ A0, const float* __restrict__ A1,
                 const float* __restrict__ B0, const float* __restrict__ B1,
                 const float* __restrict__ bias0, const float* __restrict__ bias1,
                 __half* __restrict__ C0h, __half* __restrict__ C1h,
                 int M, int N, int K)
{
    if (blockIdx.z == 0)
        hmma_core<true, 1>(A0, B0, bias0, nullptr, C0h, M, N, K);
    else
        hmma_core<true, 1>(A1, B1, bias1, nullptr, C1h, M, N, K);
}

// ---------------- fp32 transpose (for c_proj: [K,N] -> [N,K]) ------------------
__global__ void __launch_bounds__(256)
transpose_kernel(const float* __restrict__ W, float* __restrict__ out, int K, int N)
{
    __shared__ float t[32][33];
    int k0 = blockIdx.y * 32, n0 = blockIdx.x * 32;
    int tx = threadIdx.x & 31, ty = threadIdx.x >> 5;
#pragma unroll
    for (int i = 0; i < 32; i += 8)
        t[ty + i][tx] = W[(size_t)(k0 + ty + i) * N + n0 + tx];
    __syncthreads();
#pragma unroll
    for (int i = 0; i < 32; i += 8)
        out[(size_t)(n0 + ty + i) * K + k0 + tx] = t[tx][ty + i];
}

// ---------------- HMMA flash attention (single fp16, cp.async pipelined) -------
// grid (S/128, H, B), 256 threads (8 warps x 16 q-rows), k-tiles of 64, 2 stages.
// QK = Qh*Kh, PV = Ph*Vh: 64 MMAs/tile.
#define APITCH 144                 // bytes per 64-fp16 row (128B + 16B pad)
#define QTILE (128 * APITCH)       // 18432
#define KTILE (64 * APITCH)        // 9216
#define STAGEA (2 * KTILE)         // Kh,Vh = 18432
#define ATT_SMEM (QTILE + 2 * STAGEA)   // 55296

__global__ void __launch_bounds__(256)
attn_mma_kernel(const __half* __restrict__ Qh,
                const __half* __restrict__ Kh,
                const __half* __restrict__ Vh,
                float* __restrict__ O)
{
    extern __shared__ char smem[];
    const uint32_t sb = smem_u32(smem);
    const int tid = threadIdx.x, lane = tid & 31, wid = tid >> 5;
    const int qt = blockIdx.x, h = blockIdx.y, b = blockIdx.z;
    const int q0 = qt * 128;
    const int wm = wid * 16;

    const __half* qhb = Qh + ((size_t)b * SS + q0) * DD + h * HD;
    const __half* khb = Kh + (size_t)b * SS * DD + h * HD;
    const __half* vhb = Vh + (size_t)b * SS * DD + h * HD;

    const int lr = tid >> 3;        // 0..31
    const int lc = tid & 7;         // 16B chunk
    const uint32_t kv0 = sb + QTILE;

    // --- prologue: Q tile (128 rows) + k-tile 0, one cp.async group ---
#pragma unroll
    for (int it = 0; it < 4; it++) {
        int r = lr + it * 32;       // 0..127
        cp16(sb + (uint32_t)(r * APITCH + lc * 16), qhb + (size_t)r * DD + lc * 8);
    }
#pragma unroll
    for (int it = 0; it < 2; it++) {
        int r = lr + it * 32;       // 0..63
        size_t goff = (size_t)r * DD + lc * 8;
        uint32_t soff = kv0 + (uint32_t)(r * APITCH + lc * 16);
        cp16(soff,         khb + goff);
        cp16(soff + KTILE, vhb + goff);
    }
    CP_COMMIT();

    // fragment address components
    const int g  = lane >> 2;
    const int qd = lane & 3;
    const uint32_t a_off = (uint32_t)((wm + (lane & 7) + ((lane >> 3) & 1) * 8) * APITCH
                                      + ((lane >> 4) & 1) * 16);
    const uint32_t b_off = (uint32_t)(((lane & 7) + ((lane >> 4) & 1) * 8) * APITCH
                                      + ((lane >> 3) & 1) * 16);
    const uint32_t v_off = (uint32_t)(((lane & 7) + ((lane >> 3) & 1) * 8) * APITCH
                                      + ((lane >> 4) & 1) * 16);

    float m0 = -1e30f, m1 = -1e30f, l0 = 0.f, l1 = 0.f;
    float o[8][4];
#pragma unroll
    for (int i = 0; i < 8; i++)
#pragma unroll
        for (int j = 0; j < 4; j++) o[i][j] = 0.f;

    const int row0 = q0 + wm + g;
    const int nkt = 2 * qt + 2;

    for (int kt = 0; kt < nkt; kt++) {
        const uint32_t stage = kv0 + (uint32_t)(kt & 1) * STAGEA;

        // issue next tile into the other stage, then drain current tile's group
        if (kt + 1 < nkt) {
            const uint32_t nst = kv0 + (uint32_t)((kt + 1) & 1) * STAGEA;
#pragma unroll
            for (int it = 0; it < 2; it++) {
                int r = lr + it * 32;
                size_t goff = (size_t)((kt + 1) * 64 + r) * DD + lc * 8;
                uint32_t soff = nst + (uint32_t)(r * APITCH + lc * 16);
                cp16(soff,         khb + goff);
                cp16(soff + KTILE, vhb + goff);
            }
            CP_COMMIT();
            CP_WAIT1();
        } else {
            CP_WAIT0();
        }
        __syncthreads();

        if (kt * 64 <= q0 + wm + 15) {
            // --- S = Qh Kh^T ---
            float s[8][4];
#pragma unroll
            for (int i = 0; i < 8; i++)
#pragma unroll
                for (int j = 0; j < 4; j++) s[i][j] = 0.f;

#pragma unroll
            for (int ks = 0; ks < 4; ks++) {
                uint32_t qh[4];
                ldsm_x4(sb + a_off + ks * 32, qh);
#pragma unroll
                for (int np = 0; np < 4; np++) {
                    uint32_t kh[4];
                    ldsm_x4(stage + b_off + np * 16 * APITCH + ks * 32, kh);
#pragma unroll
                    for (int hh = 0; hh < 2; hh++)
                        mma16816h(s[np * 2 + hh], qh, &kh[hh * 2]);
                }
            }

            // --- scale + causal mask ---
            const int kbase0 = kt * 64;
            if (kbase0 + 63 > row0) {
#pragma unroll
                for (int nt = 0; nt < 8; nt++) {
                    int col = kbase0 + nt * 8 + qd * 2;
                    s[nt][0] = (col     <= row0)     ? s[nt][0] * 0.125f : -1e30f;
                    s[nt][1] = (col + 1 <= row0)     ? s[nt][1] * 0.125f : -1e30f;
                    s[nt][2] = (col     <= row0 + 8) ? s[nt][2] * 0.125f : -1e30f;
                    s[nt][3] = (col + 1 <= row0 + 8) ? s[nt][3] * 0.125f : -1e30f;
                }
            } else {
#pragma unroll
                for (int nt = 0; nt < 8; nt++) {
                    s[nt][0] *= 0.125f; s[nt][1] *= 0.125f;
                    s[nt][2] *= 0.125f; s[nt][3] *= 0.125f;
                }
            }

            // --- online softmax (rows g and g+8) ---
            float mx0 = -1e30f, mx1 = -1e30f;
#pragma unroll
            for (int nt = 0; nt < 8; nt++) {
                mx0 = fmaxf(mx0, fmaxf(s[nt][0], s[nt][1]));
                mx1 = fmaxf(mx1, fmaxf(s[nt][2], s[nt][3]));
            }
            mx0 = fmaxf(mx0, __shfl_xor_sync(0xffffffffu, mx0, 1));
            mx0 = fmaxf(mx0, __shfl_xor_sync(0xffffffffu, mx0, 2));
            mx1 = fmaxf(mx1, __shfl_xor_sync(0xffffffffu, mx1, 1));
            mx1 = fmaxf(mx1, __shfl_xor_sync(0xffffffffu, mx1, 2));

            float mn0 = fmaxf(m0, mx0), mn1 = fmaxf(m1, mx1);
            float c0 = __expf(m0 - mn0), c1 = __expf(m1 - mn1);
            m0 = mn0; m1 = mn1;

            float sum0 = 0.f, sum1 = 0.f;
#pragma unroll
            for (int nt = 0; nt < 8; nt++) {
                s[nt][0] = __expf(s[nt][0] - mn0); sum0 += s[nt][0];
                s[nt][1] = __expf(s[nt][1] - mn0); sum0 += s[nt][1];
                s[nt][2] = __expf(s[nt][2] - mn1); sum1 += s[nt][2];
                s[nt][3] = __expf(s[nt][3] - mn1); sum1 += s[nt][3];
            }
            sum0 += __shfl_xor_sync(0xffffffffu, sum0, 1);
            sum0 += __shfl_xor_sync(0xffffffffu, sum0, 2);
            sum1 += __shfl_xor_sync(0xffffffffu, sum1, 1);
            sum1 += __shfl_xor_sync(0xffffffffu, sum1, 2);
            l0 = l0 * c0 + sum0;
            l1 = l1 * c1 + sum1;

#pragma unroll
            for (int nt = 0; nt < 8; nt++) {
                o[nt][0] *= c0; o[nt][1] *= c0;
                o[nt][2] *= c1; o[nt][3] *= c1;
            }

            // --- O += Ph Vh  (P packed straight to fp16) ---
#pragma unroll
            for (int kc = 0; kc < 4; kc++) {
                uint32_t ph[4];
                ph[0] = pack_h2(s[2 * kc][0],     s[2 * kc][1]);
                ph[1] = pack_h2(s[2 * kc][2],     s[2 * kc][3]);
                ph[2] = pack_h2(s[2 * kc + 1][0], s[2 * kc + 1][1]);
                ph[3] = pack_h2(s[2 * kc + 1][2], s[2 * kc + 1][3]);
#pragma unroll
                for (int np = 0; np < 4; np++) {
                    uint32_t vh[4];
                    ldsm_x4_t(stage + KTILE + v_off + kc * 16 * APITCH + np * 32, vh);
#pragma unroll
                    for (int hh = 0; hh < 2; hh++)
                        mma16816h(o[np * 2 + hh], ph, &vh[hh * 2]);
                }
            }
        }
        __syncthreads();
    }

    // --- epilogue: normalize and store ---
    const float inv0 = 1.0f / l0, inv1 = 1.0f / l1;
    float* ob0 = O + ((size_t)b * SS + row0) * DD + h * HD;
    float* ob1 = O + ((size_t)b * SS + row0 + 8) * DD + h * HD;
#pragma unroll
    for (int nt = 0; nt < 8; nt++) {
        int col = nt * 8 + qd * 2;
        *reinterpret_cast<float2*>(&ob0[col]) =
            make_float2(o[nt][0] * inv0, o[nt][1] * inv0);
        *reinterpret_cast<float2*>(&ob1[col]) =
            make_float2(o[nt][2] * inv1, o[nt][3] * inv1);
    }
}

// ---------------- launch ------------------------------------------------------
extern "C" void kernel_launch(void* const* d_in, const int* in_sizes, int n_in,
                              void* d_out, int out_size)
{
    const float* hs     = (const float*)d_in[0];
    const float* WQ_w   = (const float*)d_in[1];
    const float* WQ_b   = (const float*)d_in[2];
    const float* WK_A_w = (const float*)d_in[3];
    const float* WK_B_w = (const float*)d_in[4];
    const float* WK_B_b = (const float*)d_in[5];
    const float* WV_A_w = (const float*)d_in[6];
    const float* WV_B_w = (const float*)d_in[7];
    const float* WV_B_b = (const float*)d_in[8];
    const float* c_w    = (const float*)d_in[9];
    const float* c_b    = (const float*)d_in[10];
    float* out = (float*)d_out;

    float *gatt, *gtmpk, *gtmpv, *gcpt;
    __half *qh, *kh, *vh;
    cudaGetSymbolAddress((void**)&gatt,  g_att);
    cudaGetSymbolAddress((void**)&gtmpk, g_tmpk);
    cudaGetSymbolAddress((void**)&gtmpv, g_tmpv);
    cudaGetSymbolAddress((void**)&gcpt,  g_cpt);
    cudaGetSymbolAddress((void**)&qh,    g_qh);
    cudaGetSymbolAddress((void**)&kh,    g_kh);
    cudaGetSymbolAddress((void**)&vh,    g_vh);

    cudaFuncSetAttribute(hmma_gemm<true, 0>,
                         cudaFuncAttributeMaxDynamicSharedMemorySize, HMMA_SMEM);
    cudaFuncSetAttribute(hmma_gemm<true, 1>,
                         cudaFuncAttributeMaxDynamicSharedMemorySize, HMMA_SMEM);
    cudaFuncSetAttribute(hmma_gemm_dual_f32,
                         cudaFuncAttributeMaxDynamicSharedMemorySize, HMMA_SMEM);
    cudaFuncSetAttribute(hmma_gemm_dual_h,
                         cudaFuncAttributeMaxDynamicSharedMemorySize, HMMA_SMEM);
    cudaFuncSetAttribute(attn_mma_kernel,
                         cudaFuncAttributeMaxDynamicSharedMemorySize, ATT_SMEM);

    dim3 blk(256);

    // c_proj: [K,N] -> [N,K] once
    transpose_kernel<<<dim3(DD / 32, DD / 32), blk>>>(c_w, gcpt, DD, DD);

    // Q = hs @ WQ^T + b  -> single fp16
    hmma_gemm<true, 1><<<dim3(DD / 128, MTOT / 128), blk, HMMA_SMEM>>>(
        hs, WQ_w, WQ_b, nullptr, qh, MTOT, DD, DD);

    // stage-1 low-rank: tmp_k = hs @ WK_A^T, tmp_v = hs @ WV_A^T  (one launch)
    hmma_gemm_dual_f32<<<dim3(RR / 128, MTOT / 128, 2), blk, HMMA_SMEM>>>(
        hs, WK_A_w, WV_A_w, gtmpk, gtmpv, MTOT, RR, DD);

    // stage-2: K = tmp_k @ WK_B^T + b, V = tmp_v @ WV_B^T + b  (single fp16 out)
    hmma_gemm_dual_h<<<dim3(DD / 128, MTOT / 128, 2), blk, HMMA_SMEM>>>(
        gtmpk, gtmpv, WK_B_w, WV_B_w, WK_B_b, WV_B_b,
        kh, vh, MTOT, DD, RR);

    // causal attention (single-fp16 HMMA flash)
    attn_mma_kernel<<<dim3(SS / 128, HH, BB), blk, ATT_SMEM>>>(
        qh, kh, vh, gatt);

    // out = att @ c_proj + b   (via transposed weights)
    hmma_gemm<true, 0><<<dim3(DD / 128, MTOT / 128), blk, HMMA_SMEM>>>(
        gatt, gcpt, c_b, out, nullptr, MTOT, DD, DD);

    (void)in_sizes; (void)n_in; (void)out_size;
}

// round 13
// speedup vs baseline: 1.9155x; 1.1812x over previous
#include <cuda_runtime.h>
#include <cuda_fp16.h>
#include <cstdint>
#include <cstddef>

// Problem dims (fixed)
#define BB 4
#define SS 2048
#define DD 1024
#define HH 16
#define HD 64
#define RR 512
#define MTOT (BB*SS)          // 8192 rows

// ---------------- scratch (device globals: allocation-guard safe) -------------
__device__ float g_tmpk[(size_t)MTOT * RR];   // 16 MB
__device__ float g_tmpv[(size_t)MTOT * RR];   // 16 MB
__device__ float g_cpt [(size_t)DD * DD];     // 4 MB  (c_proj transposed -> [N,K])
// fp16 Q/K/V (single-rounded) written by projection GEMM epilogues
__device__ __half g_qh  [(size_t)MTOT * DD];
__device__ __half g_kh  [(size_t)MTOT * DD];
__device__ __half g_vh  [(size_t)MTOT * DD];
__device__ __half g_atth[(size_t)MTOT * DD];  // attention output, fp16

// ---------------- mma.sync helpers (family-stable, OK on compute_103) ----------
__device__ __forceinline__ uint32_t smem_u32(const void* p) {
    uint32_t a;
    asm("{ .reg .u64 t; cvta.to.shared.u64 t, %1; cvt.u32.u64 %0, t; }"
        : "=r"(a) : "l"(p));
    return a;
}

__device__ __forceinline__ void ldsm_x4(uint32_t addr, uint32_t* r) {
    asm volatile("ldmatrix.sync.aligned.m8n8.x4.shared.b16 {%0,%1,%2,%3}, [%4];"
                 : "=r"(r[0]), "=r"(r[1]), "=r"(r[2]), "=r"(r[3]) : "r"(addr));
}
__device__ __forceinline__ void ldsm_x4_t(uint32_t addr, uint32_t* r) {
    asm volatile("ldmatrix.sync.aligned.m8n8.x4.trans.shared.b16 {%0,%1,%2,%3}, [%4];"
                 : "=r"(r[0]), "=r"(r[1]), "=r"(r[2]), "=r"(r[3]) : "r"(addr));
}
__device__ __forceinline__ void mma16816h(float* d, const uint32_t* a, const uint32_t* b) {
    asm volatile(
        "mma.sync.aligned.m16n8k16.row.col.f32.f16.f16.f32 "
        "{%0,%1,%2,%3}, {%4,%5,%6,%7}, {%8,%9}, {%0,%1,%2,%3};"
        : "+f"(d[0]), "+f"(d[1]), "+f"(d[2]), "+f"(d[3])
        : "r"(a[0]), "r"(a[1]), "r"(a[2]), "r"(a[3]), "r"(b[0]), "r"(b[1]));
}

__device__ __forceinline__ void cp16(uint32_t dst, const void* src) {
    asm volatile("cp.async.cg.shared.global [%0], [%1], 16;"
                 :: "r"(dst), "l"(src) : "memory");
}
#define CP_COMMIT()  asm volatile("cp.async.commit_group;" ::: "memory")
#define CP_WAIT1()   asm volatile("cp.async.wait_group 1;" ::: "memory")
#define CP_WAIT0()   asm volatile("cp.async.wait_group 0;" ::: "memory")

__device__ __forceinline__ uint32_t pack_h2(float x, float y) {
    __half2 h = __floats2half2_rn(x, y);
    return *reinterpret_cast<uint32_t*>(&h);
}
// pack float4 -> 4 fp16 (single-rounded)
__device__ __forceinline__ void pack_f4h(float4 v, uint2& h) {
    h.x = pack_h2(v.x, v.y);
    h.y = pack_h2(v.z, v.w);
}

// ---------------- HMMA fp16x1 GEMM core ------------------------------------------
// C[M,N] = A[M,K] @ B[N,K]^T (+ bias).
// A: fp32 in (rounded to fp16) or fp16 in (AHALF). B: fp32 in, rounded to fp16.
// 1 MMA per fragment product.  OMODE: 0 = fp32 out, 1 = fp16 out.
#define PITCH 80
#define TILE_B (128 * PITCH)
#define STAGE_B (2 * TILE_B)      // A, B
#define HMMA_SMEM (2 * STAGE_B)   // 40960

template <bool BIAS, int OMODE, bool AHALF>
__device__ __forceinline__ void
hmma_core(const void* __restrict__ Av, const float* __restrict__ B,
          const float* __restrict__ bias, float* __restrict__ C,
          __half* __restrict__ Chi,
          int M, int N, int K)
{
    extern __shared__ char smem[];
    const uint32_t sb = smem_u32(smem);
    const float* Af = (const float*)Av;
    const __half* Ah = (const __half*)Av;

    const int tid  = threadIdx.x;
    const int lane = tid & 31;
    const int wid  = tid >> 5;
    const int m0 = blockIdx.y * 128, n0 = blockIdx.x * 128;
    const int wm = (wid & 3) * 32;
    const int wn = (wid >> 2) * 64;

    const int lr = tid >> 3;
    const int lq = tid & 7;

    const int a_row = wm + (lane & 7) + ((lane >> 3) & 1) * 8;
    const int a_kb  = ((lane >> 4) & 1) * 16;
    const int b_row = wn + (lane & 7) + ((lane >> 4) & 1) * 8;
    const int b_kb  = ((lane >> 3) & 1) * 16;

    float acc[2][8][4];
#pragma unroll
    for (int i = 0; i < 2; i++)
#pragma unroll
        for (int j = 0; j < 8; j++)
#pragma unroll
            for (int k = 0; k < 4; k++) acc[i][j][k] = 0.f;

    const int NC = K >> 5;

    float4 ra[4];
    uint2  rah[4];
    float4 rb[4];
#pragma unroll
    for (int p = 0; p < 4; p++) {
        int row = lr + p * 32;
        if (AHALF)
            rah[p] = *reinterpret_cast<const uint2*>(&Ah[(size_t)(m0 + row) * K + lq * 4]);
        else
            ra[p] = *reinterpret_cast<const float4*>(&Af[(size_t)(m0 + row) * K + lq * 4]);
        rb[p] = *reinterpret_cast<const float4*>(&B[(size_t)(n0 + row) * K + lq * 4]);
    }
#pragma unroll
    for (int p = 0; p < 4; p++) {
        int row = lr + p * 32;
        uint32_t off = (uint32_t)(row * PITCH + lq * 8);
        uint2 ah;
        if (AHALF) ah = rah[p]; else pack_f4h(ra[p], ah);
        *reinterpret_cast<uint2*>(smem + off) = ah;
        uint2 bh;
        pack_f4h(rb[p], bh);
        *reinterpret_cast<uint2*>(smem + (off + TILE_B)) = bh;
    }
    __syncthreads();

    for (int c = 0; c < NC; c++) {
        if (c + 1 < NC) {
            const int kc = (c + 1) << 5;
#pragma unroll
            for (int p = 0; p < 4; p++) {
                int row = lr + p * 32;
                if (AHALF)
                    rah[p] = *reinterpret_cast<const uint2*>(
                        &Ah[(size_t)(m0 + row) * K + kc + lq * 4]);
                else
                    ra[p] = *reinterpret_cast<const float4*>(
                        &Af[(size_t)(m0 + row) * K + kc + lq * 4]);
                rb[p] = *reinterpret_cast<const float4*>(
                    &B[(size_t)(n0 + row) * K + kc + lq * 4]);
            }
        }

        const uint32_t st = sb + (uint32_t)(c & 1) * STAGE_B;
#pragma unroll
        for (int ks = 0; ks < 2; ks++) {
            uint32_t ah[2][4];
#pragma unroll
            for (int mt = 0; mt < 2; mt++) {
                uint32_t aaddr = st + (uint32_t)((a_row + mt * 16) * PITCH + a_kb + ks * 32);
                ldsm_x4(aaddr, ah[mt]);
            }
#pragma unroll
            for (int nt2 = 0; nt2 < 4; nt2++) {
                uint32_t bh[4];
                uint32_t baddr = st + TILE_B +
                    (uint32_t)((b_row + nt2 * 16) * PITCH + b_kb + ks * 32);
                ldsm_x4(baddr, bh);
#pragma unroll
                for (int mt = 0; mt < 2; mt++) {
#pragma unroll
                    for (int half = 0; half < 2; half++)
                        mma16816h(acc[mt][nt2 * 2 + half], ah[mt], &bh[half * 2]);
                }
            }
        }

        if (c + 1 < NC) {
            char* so = smem + (size_t)((c + 1) & 1) * STAGE_B;
#pragma unroll
            for (int p = 0; p < 4; p++) {
                int row = lr + p * 32;
                uint32_t off = (uint32_t)(row * PITCH + lq * 8);
                uint2 ah;
                if (AHALF) ah = rah[p]; else pack_f4h(ra[p], ah);
                *reinterpret_cast<uint2*>(so + off) = ah;
                uint2 bh;
                pack_f4h(rb[p], bh);
                *reinterpret_cast<uint2*>(so + off + TILE_B) = bh;
            }
        }
        __syncthreads();
    }

    const int g = lane >> 2;
    const int cpair = (lane & 3) * 2;
#pragma unroll
    for (int mt = 0; mt < 2; mt++) {
#pragma unroll
        for (int nt = 0; nt < 8; nt++) {
            int col = n0 + wn + nt * 8 + cpair;
            float bx = 0.f, by = 0.f;
            if (BIAS) { bx = bias[col]; by = bias[col + 1]; }
            int row0 = m0 + wm + mt * 16 + g;
            float x0 = acc[mt][nt][0] + bx, y0 = acc[mt][nt][1] + by;
            float x1 = acc[mt][nt][2] + bx, y1 = acc[mt][nt][3] + by;
            size_t o0 = (size_t)row0 * N + col;
            size_t o1 = (size_t)(row0 + 8) * N + col;
            if (OMODE == 0) {
                *reinterpret_cast<float2*>(&C[o0]) = make_float2(x0, y0);
                *reinterpret_cast<float2*>(&C[o1]) = make_float2(x1, y1);
            } else {
                *reinterpret_cast<uint32_t*>(Chi + o0) = pack_h2(x0, y0);
                *reinterpret_cast<uint32_t*>(Chi + o1) = pack_h2(x1, y1);
            }
        }
    }
}

template <bool BIAS, int OMODE, bool AHALF>
__global__ void __launch_bounds__(256)
hmma_gemm(const void* __restrict__ A, const float* __restrict__ B,
          const float* __restrict__ bias, float* __restrict__ C,
          __half* __restrict__ Chi,
          int M, int N, int K)
{
    hmma_core<BIAS, OMODE, AHALF>(A, B, bias, C, Chi, M, N, K);
}

// dual fp32-out GEMM (stage-1 K/V low-rank): z selects operand set
__global__ void __launch_bounds__(256)
hmma_gemm_dual_f32(const float* __restrict__ A,
                   const float* __restrict__ B0, const float* __restrict__ B1,
                   float* __restrict__ C0, float* __restrict__ C1,
                   int M, int N, int K)
{
    if (blockIdx.z == 0)
        hmma_core<false, 0, false>(A, B0, nullptr, C0, nullptr, M, N, K);
    else
        hmma_core<false, 0, false>(A, B1, nullptr, C1, nullptr, M, N, K);
}

// dual fp16-out GEMM (stage-2 K/V): z selects operand set
__global__ void __launch_bounds__(256)
hmma_gemm_dual_h(const float* __restrict__ A0, const float* __restrict__ A1,
                 const float* __restrict__ B0, const float* __restrict__ B1,
                 const float* __restrict__ bias0, const float* __restrict__ bias1,
                 __half* __restrict__ C0h, __half* __restrict__ C1h,
                 int M, int N, int K)
{
    if (blockIdx.z == 0)
        hmma_core<true, 1, false>(A0, B0, bias0, nullptr, C0h, M, N, K);
    else
        hmma_core<true, 1, false>(A1, B1, bias1, nullptr, C1h, M, N, K);
}

// ---------------- fp32 transpose (for c_proj: [K,N] -> [N,K]) ------------------
__global__ void __launch_bounds__(256)
transpose_kernel(const float* __restrict__ W, float* __restrict__ out, int K, int N)
{
    __shared__ float t[32][33];
    int k0 = blockIdx.y * 32, n0 = blockIdx.x * 32;
    int tx = threadIdx.x & 31, ty = threadIdx.x >> 5;
#pragma unroll
    for (int i = 0; i < 32; i += 8)
        t[ty + i][tx] = W[(size_t)(k0 + ty + i) * N + n0 + tx];
    __syncthreads();
#pragma unroll
    for (int i = 0; i < 32; i += 8)
        out[(size_t)(n0 + ty + i) * K + k0 + tx] = t[tx][ty + i];
}

// ---------------- HMMA flash attention (single fp16, cp.async pipelined) -------
// grid (S/128, H, B), 256 threads (8 warps x 16 q-rows), k-tiles of 64, 2 stages.
#define APITCH 144                 // bytes per 64-fp16 row (128B + 16B pad)
#define QTILE (128 * APITCH)       // 18432
#define KTILE (64 * APITCH)        // 9216
#define STAGEA (2 * KTILE)         // Kh,Vh = 18432
#define ATT_SMEM (QTILE + 2 * STAGEA)   // 55296

__global__ void __launch_bounds__(256)
attn_mma_kernel(const __half* __restrict__ Qh,
                const __half* __restrict__ Kh,
                const __half* __restrict__ Vh,
                __half* __restrict__ O)
{
    extern __shared__ char smem[];
    const uint32_t sb = smem_u32(smem);
    const int tid = threadIdx.x, lane = tid & 31, wid = tid >> 5;
    const int qt = blockIdx.x, h = blockIdx.y, b = blockIdx.z;
    const int q0 = qt * 128;
    const int wm = wid * 16;

    const __half* qhb = Qh + ((size_t)b * SS + q0) * DD + h * HD;
    const __half* khb = Kh + (size_t)b * SS * DD + h * HD;
    const __half* vhb = Vh + (size_t)b * SS * DD + h * HD;

    const int lr = tid >> 3;        // 0..31
    const int lc = tid & 7;         // 16B chunk
    const uint32_t kv0 = sb + QTILE;

    // --- prologue: Q tile (128 rows) + k-tile 0, one cp.async group ---
#pragma unroll
    for (int it = 0; it < 4; it++) {
        int r = lr + it * 32;       // 0..127
        cp16(sb + (uint32_t)(r * APITCH + lc * 16), qhb + (size_t)r * DD + lc * 8);
    }
#pragma unroll
    for (int it = 0; it < 2; it++) {
        int r = lr + it * 32;       // 0..63
        size_t goff = (size_t)r * DD + lc * 8;
        uint32_t soff = kv0 + (uint32_t)(r * APITCH + lc * 16);
        cp16(soff,         khb + goff);
        cp16(soff + KTILE, vhb + goff);
    }
    CP_COMMIT();

    // fragment address components
    const int g  = lane >> 2;
    const int qd = lane & 3;
    const uint32_t a_off = (uint32_t)((wm + (lane & 7) + ((lane >> 3) & 1) * 8) * APITCH
                                      + ((lane >> 4) & 1) * 16);
    const uint32_t b_off = (uint32_t)(((lane & 7) + ((lane >> 4) & 1) * 8) * APITCH
                                      + ((lane >> 3) & 1) * 16);
    const uint32_t v_off = (uint32_t)(((lane & 7) + ((lane >> 3) & 1) * 8) * APITCH
                                      + ((lane >> 4) & 1) * 16);

    float m0 = -1e30f, m1 = -1e30f, l0 = 0.f, l1 = 0.f;
    float o[8][4];
#pragma unroll
    for (int i = 0; i < 8; i++)
#pragma unroll
        for (int j = 0; j < 4; j++) o[i][j] = 0.f;

    const int row0 = q0 + wm + g;
    const int nkt = 2 * qt + 2;

    for (int kt = 0; kt < nkt; kt++) {
        const uint32_t stage = kv0 + (uint32_t)(kt & 1) * STAGEA;

        if (kt + 1 < nkt) {
            const uint32_t nst = kv0 + (uint32_t)((kt + 1) & 1) * STAGEA;
#pragma unroll
            for (int it = 0; it < 2; it++) {
                int r = lr + it * 32;
                size_t goff = (size_t)((kt + 1) * 64 + r) * DD + lc * 8;
                uint32_t soff = nst + (uint32_t)(r * APITCH + lc * 16);
                cp16(soff,         khb + goff);
                cp16(soff + KTILE, vhb + goff);
            }
            CP_COMMIT();
            CP_WAIT1();
        } else {
            CP_WAIT0();
        }
        __syncthreads();

        if (kt * 64 <= q0 + wm + 15) {
            // --- S = Qh Kh^T ---
            float s[8][4];
#pragma unroll
            for (int i = 0; i < 8; i++)
#pragma unroll
                for (int j = 0; j < 4; j++) s[i][j] = 0.f;

#pragma unroll
            for (int ks = 0; ks < 4; ks++) {
                uint32_t qh[4];
                ldsm_x4(sb + a_off + ks * 32, qh);
#pragma unroll
                for (int np = 0; np < 4; np++) {
                    uint32_t kh[4];
                    ldsm_x4(stage + b_off + np * 16 * APITCH + ks * 32, kh);
#pragma unroll
                    for (int hh = 0; hh < 2; hh++)
                        mma16816h(s[np * 2 + hh], qh, &kh[hh * 2]);
                }
            }

            // --- scale + causal mask ---
            const int kbase0 = kt * 64;
            if (kbase0 + 63 > row0) {
#pragma unroll
                for (int nt = 0; nt < 8; nt++) {
                    int col = kbase0 + nt * 8 + qd * 2;
                    s[nt][0] = (col     <= row0)     ? s[nt][0] * 0.125f : -1e30f;
                    s[nt][1] = (col + 1 <= row0)     ? s[nt][1] * 0.125f : -1e30f;
                    s[nt][2] = (col     <= row0 + 8) ? s[nt][2] * 0.125f : -1e30f;
                    s[nt][3] = (col + 1 <= row0 + 8) ? s[nt][3] * 0.125f : -1e30f;
                }
            } else {
#pragma unroll
                for (int nt = 0; nt < 8; nt++) {
                    s[nt][0] *= 0.125f; s[nt][1] *= 0.125f;
                    s[nt][2] *= 0.125f; s[nt][3] *= 0.125f;
                }
            }

            // --- online softmax (rows g and g+8) ---
            float mx0 = -1e30f, mx1 = -1e30f;
#pragma unroll
            for (int nt = 0; nt < 8; nt++) {
                mx0 = fmaxf(mx0, fmaxf(s[nt][0], s[nt][1]));
                mx1 = fmaxf(mx1, fmaxf(s[nt][2], s[nt][3]));
            }
            mx0 = fmaxf(mx0, __shfl_xor_sync(0xffffffffu, mx0, 1));
            mx0 = fmaxf(mx0, __shfl_xor_sync(0xffffffffu, mx0, 2));
            mx1 = fmaxf(mx1, __shfl_xor_sync(0xffffffffu, mx1, 1));
            mx1 = fmaxf(mx1, __shfl_xor_sync(0xffffffffu, mx1, 2));

            float mn0 = fmaxf(m0, mx0), mn1 = fmaxf(m1, mx1);
            float c0 = __expf(m0 - mn0), c1 = __expf(m1 - mn1);
            m0 = mn0; m1 = mn1;

            float sum0 = 0.f, sum1 = 0.f;
#pragma unroll
            for (int nt = 0; nt < 8; nt++) {
                s[nt][0] = __expf(s[nt][0] - mn0); sum0 += s[nt][0];
                s[nt][1] = __expf(s[nt][1] - mn0); sum0 += s[nt][1];
                s[nt][2] = __expf(s[nt][2] - mn1); sum1 += s[nt][2];
                s[nt][3] = __expf(s[nt][3] - mn1); sum1 += s[nt][3];
            }
            sum0 += __shfl_xor_sync(0xffffffffu, sum0, 1);
            sum0 += __shfl_xor_sync(0xffffffffu, sum0, 2);
            sum1 += __shfl_xor_sync(0xffffffffu, sum1, 1);
            sum1 += __shfl_xor_sync(0xffffffffu, sum1, 2);
            l0 = l0 * c0 + sum0;
            l1 = l1 * c1 + sum1;

#pragma unroll
            for (int nt = 0; nt < 8; nt++) {
                o[nt][0] *= c0; o[nt][1] *= c0;
                o[nt][2] *= c1; o[nt][3] *= c1;
            }

            // --- O += Ph Vh  (P packed straight to fp16) ---
#pragma unroll
            for (int kc = 0; kc < 4; kc++) {
                uint32_t ph[4];
                ph[0] = pack_h2(s[2 * kc][0],     s[2 * kc][1]);
                ph[1] = pack_h2(s[2 * kc][2],     s[2 * kc][3]);
                ph[2] = pack_h2(s[2 * kc + 1][0], s[2 * kc + 1][1]);
                ph[3] = pack_h2(s[2 * kc + 1][2], s[2 * kc + 1][3]);
#pragma unroll
                for (int np = 0; np < 4; np++) {
                    uint32_t vh[4];
                    ldsm_x4_t(stage + KTILE + v_off + kc * 16 * APITCH + np * 32, vh);
#pragma unroll
                    for (int hh = 0; hh < 2; hh++)
                        mma16816h(o[np * 2 + hh], ph, &vh[hh * 2]);
                }
            }
        }
        __syncthreads();
    }

    // --- epilogue: normalize and store as fp16 (same rounding c_proj would do) ---
    const float inv0 = 1.0f / l0, inv1 = 1.0f / l1;
    __half* ob0 = O + ((size_t)b * SS + row0) * DD + h * HD;
    __half* ob1 = O + ((size_t)b * SS + row0 + 8) * DD + h * HD;
#pragma unroll
    for (int nt = 0; nt < 8; nt++) {
        int col = nt * 8 + qd * 2;
        *reinterpret_cast<uint32_t*>(ob0 + col) =
            pack_h2(o[nt][0] * inv0, o[nt][1] * inv0);
        *reinterpret_cast<uint32_t*>(ob1 + col) =
            pack_h2(o[nt][2] * inv1, o[nt][3] * inv1);
    }
}

// ---------------- launch ------------------------------------------------------
extern "C" void kernel_launch(void* const* d_in, const int* in_sizes, int n_in,
                              void* d_out, int out_size)
{
    const float* hs     = (const float*)d_in[0];
    const float* WQ_w   = (const float*)d_in[1];
    const float* WQ_b   = (const float*)d_in[2];
    const float* WK_A_w = (const float*)d_in[3];
    const float* WK_B_w = (const float*)d_in[4];
    const float* WK_B_b = (const float*)d_in[5];
    const float* WV_A_w = (const float*)d_in[6];
    const float* WV_B_w = (const float*)d_in[7];
    const float* WV_B_b = (const float*)d_in[8];
    const float* c_w    = (const float*)d_in[9];
    const float* c_b    = (const float*)d_in[10];
    float* out = (float*)d_out;

    float *gtmpk, *gtmpv, *gcpt;
    __half *qh, *kh, *vh, *atth;
    cudaGetSymbolAddress((void**)&gtmpk, g_tmpk);
    cudaGetSymbolAddress((void**)&gtmpv, g_tmpv);
    cudaGetSymbolAddress((void**)&gcpt,  g_cpt);
    cudaGetSymbolAddress((void**)&qh,    g_qh);
    cudaGetSymbolAddress((void**)&kh,    g_kh);
    cudaGetSymbolAddress((void**)&vh,    g_vh);
    cudaGetSymbolAddress((void**)&atth,  g_atth);

    cudaFuncSetAttribute(hmma_gemm<true, 0, true>,
                         cudaFuncAttributeMaxDynamicSharedMemorySize, HMMA_SMEM);
    cudaFuncSetAttribute(hmma_gemm<true, 1, false>,
                         cudaFuncAttributeMaxDynamicSharedMemorySize, HMMA_SMEM);
    cudaFuncSetAttribute(hmma_gemm_dual_f32,
                         cudaFuncAttributeMaxDynamicSharedMemorySize, HMMA_SMEM);
    cudaFuncSetAttribute(hmma_gemm_dual_h,
                         cudaFuncAttributeMaxDynamicSharedMemorySize, HMMA_SMEM);
    cudaFuncSetAttribute(attn_mma_kernel,
                         cudaFuncAttributeMaxDynamicSharedMemorySize, ATT_SMEM);

    dim3 blk(256);

    // c_proj: [K,N] -> [N,K] once
    transpose_kernel<<<dim3(DD / 32, DD / 32), blk>>>(c_w, gcpt, DD, DD);

    // Q = hs @ WQ^T + b  -> single fp16
    hmma_gemm<true, 1, false><<<dim3(DD / 128, MTOT / 128), blk, HMMA_SMEM>>>(
        hs, WQ_w, WQ_b, nullptr, qh, MTOT, DD, DD);

    // stage-1 low-rank: tmp_k = hs @ WK_A^T, tmp_v = hs @ WV_A^T  (one launch)
    hmma_gemm_dual_f32<<<dim3(RR / 128, MTOT / 128, 2), blk, HMMA_SMEM>>>(
        hs, WK_A_w, WV_A_w, gtmpk, gtmpv, MTOT, RR, DD);

    // stage-2: K = tmp_k @ WK_B^T + b, V = tmp_v @ WV_B^T + b  (single fp16 out)
    hmma_gemm_dual_h<<<dim3(DD / 128, MTOT / 128, 2), blk, HMMA_SMEM>>>(
        gtmpk, gtmpv, WK_B_w, WV_B_w, WK_B_b, WV_B_b,
        kh, vh, MTOT, DD, RR);

    // causal attention (single-fp16 HMMA flash), fp16 output
    attn_mma_kernel<<<dim3(SS / 128, HH, BB), blk, ATT_SMEM>>>(
        qh, kh, vh, atth);

    // out = att @ c_proj + b   (fp16 A path, via transposed weights)
    hmma_gemm<true, 0, true><<<dim3(DD / 128, MTOT / 128), blk, HMMA_SMEM>>>(
        atth, gcpt, c_b, out, nullptr, MTOT, DD, DD);

    (void)in_sizes; (void)n_in; (void)out_size;
}

// round 14
// speedup vs baseline: 2.3193x; 1.2108x over previous
#include <cuda_runtime.h>
#include <cuda_fp16.h>
#include <cstdint>
#include <cstddef>

// Problem dims (fixed)
#define BB 4
#define SS 2048
#define DD 1024
#define HH 16
#define HD 64
#define RR 512
#define MTOT (BB*SS)          // 8192 rows

// ---------------- scratch (device globals: allocation-guard safe) -------------
// fp16 copies of inputs (converted once; identical rounding to previous per-tile packs)
__device__ __half g_hsh [(size_t)MTOT * DD];
__device__ __half g_wqh [(size_t)DD * DD];
__device__ __half g_wkah[(size_t)RR * DD];
__device__ __half g_wkbh[(size_t)DD * RR];
__device__ __half g_wvah[(size_t)RR * DD];
__device__ __half g_wvbh[(size_t)DD * RR];
__device__ __half g_cpth[(size_t)DD * DD];     // c_proj transposed -> [N,K], fp16
// fp16 intermediates
__device__ __half g_tmpkh[(size_t)MTOT * RR];
__device__ __half g_tmpvh[(size_t)MTOT * RR];
__device__ __half g_qh  [(size_t)MTOT * DD];
__device__ __half g_kh  [(size_t)MTOT * DD];
__device__ __half g_vh  [(size_t)MTOT * DD];
__device__ __half g_atth[(size_t)MTOT * DD];

// ---------------- mma.sync helpers (family-stable, OK on compute_103) ----------
__device__ __forceinline__ uint32_t smem_u32(const void* p) {
    uint32_t a;
    asm("{ .reg .u64 t; cvta.to.shared.u64 t, %1; cvt.u32.u64 %0, t; }"
        : "=r"(a) : "l"(p));
    return a;
}

__device__ __forceinline__ void ldsm_x4(uint32_t addr, uint32_t* r) {
    asm volatile("ldmatrix.sync.aligned.m8n8.x4.shared.b16 {%0,%1,%2,%3}, [%4];"
                 : "=r"(r[0]), "=r"(r[1]), "=r"(r[2]), "=r"(r[3]) : "r"(addr));
}
__device__ __forceinline__ void ldsm_x4_t(uint32_t addr, uint32_t* r) {
    asm volatile("ldmatrix.sync.aligned.m8n8.x4.trans.shared.b16 {%0,%1,%2,%3}, [%4];"
                 : "=r"(r[0]), "=r"(r[1]), "=r"(r[2]), "=r"(r[3]) : "r"(addr));
}
__device__ __forceinline__ void mma16816h(float* d, const uint32_t* a, const uint32_t* b) {
    asm volatile(
        "mma.sync.aligned.m16n8k16.row.col.f32.f16.f16.f32 "
        "{%0,%1,%2,%3}, {%4,%5,%6,%7}, {%8,%9}, {%0,%1,%2,%3};"
        : "+f"(d[0]), "+f"(d[1]), "+f"(d[2]), "+f"(d[3])
        : "r"(a[0]), "r"(a[1]), "r"(a[2]), "r"(a[3]), "r"(b[0]), "r"(b[1]));
}

__device__ __forceinline__ void cp16(uint32_t dst, const void* src) {
    asm volatile("cp.async.cg.shared.global [%0], [%1], 16;"
                 :: "r"(dst), "l"(src) : "memory");
}
#define CP_COMMIT()  asm volatile("cp.async.commit_group;" ::: "memory")
#define CP_WAIT1()   asm volatile("cp.async.wait_group 1;" ::: "memory")
#define CP_WAIT0()   asm volatile("cp.async.wait_group 0;" ::: "memory")

__device__ __forceinline__ uint32_t pack_h2(float x, float y) {
    __half2 h = __floats2half2_rn(x, y);
    return *reinterpret_cast<uint32_t*>(&h);
}
__device__ __forceinline__ void pack_f4h(float4 v, uint2& h) {
    h.x = pack_h2(v.x, v.y);
    h.y = pack_h2(v.z, v.w);
}

// ---------------- fp32 -> fp16 converters --------------------------------------
__global__ void __launch_bounds__(256)
convert_h_kernel(const float* __restrict__ x, __half* __restrict__ y, int n4)
{
    int i = blockIdx.x * 256 + threadIdx.x;
    if (i >= n4) return;
    float4 v = reinterpret_cast<const float4*>(x)[i];
    uint2 h;
    pack_f4h(v, h);
    reinterpret_cast<uint2*>(y)[i] = h;
}

// transpose + convert: W[K,N] fp32 -> out[N,K] fp16
__global__ void __launch_bounds__(256)
transpose_convert_kernel(const float* __restrict__ W, __half* __restrict__ out,
                         int K, int N)
{
    __shared__ float t[32][33];
    int k0 = blockIdx.y * 32, n0 = blockIdx.x * 32;
    int tx = threadIdx.x & 31, ty = threadIdx.x >> 5;
#pragma unroll
    for (int i = 0; i < 32; i += 8)
        t[ty + i][tx] = W[(size_t)(k0 + ty + i) * N + n0 + tx];
    __syncthreads();
#pragma unroll
    for (int i = 0; i < 32; i += 8)
        out[(size_t)(n0 + ty + i) * K + k0 + tx] = __float2half_rn(t[tx][ty + i]);
}

// ---------------- HMMA fp16 GEMM core (cp.async, 2 blocks/SM) -------------------
// C[M,N] = A[M,K] @ B[N,K]^T (+ bias). A, B fp16 in global.
// OMODE: 0 = fp32 out, 1 = fp16 out.
#define PITCH 80
#define TILE_B (128 * PITCH)      // 10240
#define STAGE_B (2 * TILE_B)      // A, B = 20480
#define HMMA_SMEM (2 * STAGE_B)   // 40960

__device__ __forceinline__ void
gemm_load_stage(uint32_t st, const __half* __restrict__ A,
                const __half* __restrict__ B,
                int m0, int n0, int kc, int K, int tid)
{
#pragma unroll
    for (int i = 0; i < 2; i++) {
        int idx = tid + i * 256;       // 0..511
        int row = idx >> 2;            // 0..127
        int ch  = idx & 3;             // 16B chunk within 64B row
        uint32_t so = st + (uint32_t)(row * PITCH + ch * 16);
        size_t go = (size_t)row * K + kc + ch * 8;
        cp16(so,          A + (size_t)m0 * K + go);
        cp16(so + TILE_B, B + (size_t)n0 * K + go);
    }
}

template <bool BIAS, int OMODE>
__device__ __forceinline__ void
hmma_core(const __half* __restrict__ A, const __half* __restrict__ B,
          const float* __restrict__ bias, float* __restrict__ C,
          __half* __restrict__ Chi,
          int M, int N, int K)
{
    extern __shared__ char smem[];
    const uint32_t sb = smem_u32(smem);

    const int tid  = threadIdx.x;
    const int lane = tid & 31;
    const int wid  = tid >> 5;
    const int m0 = blockIdx.y * 128, n0 = blockIdx.x * 128;
    const int wm = (wid & 3) * 32;
    const int wn = (wid >> 2) * 64;

    const int a_row = wm + (lane & 7) + ((lane >> 3) & 1) * 8;
    const int a_kb  = ((lane >> 4) & 1) * 16;
    const int b_row = wn + (lane & 7) + ((lane >> 4) & 1) * 8;
    const int b_kb  = ((lane >> 3) & 1) * 16;

    float acc[2][8][4];
#pragma unroll
    for (int i = 0; i < 2; i++)
#pragma unroll
        for (int j = 0; j < 8; j++)
#pragma unroll
            for (int k = 0; k < 4; k++) acc[i][j][k] = 0.f;

    const int NC = K >> 5;

    // prologue: stage 0
    gemm_load_stage(sb, A, B, m0, n0, 0, K, tid);
    CP_COMMIT();

    for (int c = 0; c < NC; c++) {
        if (c + 1 < NC) {
            gemm_load_stage(sb + (uint32_t)((c + 1) & 1) * STAGE_B,
                            A, B, m0, n0, (c + 1) << 5, K, tid);
            CP_COMMIT();
            CP_WAIT1();
        } else {
            CP_WAIT0();
        }
        __syncthreads();

        const uint32_t st = sb + (uint32_t)(c & 1) * STAGE_B;
#pragma unroll
        for (int ks = 0; ks < 2; ks++) {
            uint32_t ah[2][4];
#pragma unroll
            for (int mt = 0; mt < 2; mt++) {
                uint32_t aaddr = st + (uint32_t)((a_row + mt * 16) * PITCH + a_kb + ks * 32);
                ldsm_x4(aaddr, ah[mt]);
            }
#pragma unroll
            for (int nt2 = 0; nt2 < 4; nt2++) {
                uint32_t bh[4];
                uint32_t baddr = st + TILE_B +
                    (uint32_t)((b_row + nt2 * 16) * PITCH + b_kb + ks * 32);
                ldsm_x4(baddr, bh);
#pragma unroll
                for (int mt = 0; mt < 2; mt++) {
#pragma unroll
                    for (int half = 0; half < 2; half++)
                        mma16816h(acc[mt][nt2 * 2 + half], ah[mt], &bh[half * 2]);
                }
            }
        }
        __syncthreads();
    }

    const int g = lane >> 2;
    const int cpair = (lane & 3) * 2;
#pragma unroll
    for (int mt = 0; mt < 2; mt++) {
#pragma unroll
        for (int nt = 0; nt < 8; nt++) {
            int col = n0 + wn + nt * 8 + cpair;
            float bx = 0.f, by = 0.f;
            if (BIAS) { bx = bias[col]; by = bias[col + 1]; }
            int row0 = m0 + wm + mt * 16 + g;
            float x0 = acc[mt][nt][0] + bx, y0 = acc[mt][nt][1] + by;
            float x1 = acc[mt][nt][2] + bx, y1 = acc[mt][nt][3] + by;
            size_t o0 = (size_t)row0 * N + col;
            size_t o1 = (size_t)(row0 + 8) * N + col;
            if (OMODE == 0) {
                *reinterpret_cast<float2*>(&C[o0]) = make_float2(x0, y0);
                *reinterpret_cast<float2*>(&C[o1]) = make_float2(x1, y1);
            } else {
                *reinterpret_cast<uint32_t*>(Chi + o0) = pack_h2(x0, y0);
                *reinterpret_cast<uint32_t*>(Chi + o1) = pack_h2(x1, y1);
            }
        }
    }
}

template <bool BIAS, int OMODE>
__global__ void __launch_bounds__(256, 2)
hmma_gemm(const __half* __restrict__ A, const __half* __restrict__ B,
          const float* __restrict__ bias, float* __restrict__ C,
          __half* __restrict__ Chi,
          int M, int N, int K)
{
    hmma_core<BIAS, OMODE>(A, B, bias, C, Chi, M, N, K);
}

// dual fp16-out GEMM (stage-1 K/V low-rank, no bias): z selects operand set
__global__ void __launch_bounds__(256, 2)
hmma_gemm_dual_s1(const __half* __restrict__ A,
                  const __half* __restrict__ B0, const __half* __restrict__ B1,
                  __half* __restrict__ C0, __half* __restrict__ C1,
                  int M, int N, int K)
{
    if (blockIdx.z == 0)
        hmma_core<false, 1>(A, B0, nullptr, nullptr, C0, M, N, K);
    else
        hmma_core<false, 1>(A, B1, nullptr, nullptr, C1, M, N, K);
}

// dual fp16-out GEMM (stage-2 K/V, bias): z selects operand set
__global__ void __launch_bounds__(256, 2)
hmma_gemm_dual_s2(const __half* __restrict__ A0, const __half* __restrict__ A1,
                  const __half* __restrict__ B0, const __half* __restrict__ B1,
                  const float* __restrict__ bias0, const float* __restrict__ bias1,
                  __half* __restrict__ C0h, __half* __restrict__ C1h,
                  int M, int N, int K)
{
    if (blockIdx.z == 0)
        hmma_core<true, 1>(A0, B0, bias0, nullptr, C0h, M, N, K);
    else
        hmma_core<true, 1>(A1, B1, bias1, nullptr, C1h, M, N, K);
}

// ---------------- HMMA flash attention (single fp16, cp.async pipelined) -------
// grid (S/128, H, B), 256 threads (8 warps x 16 q-rows), k-tiles of 64, 2 stages.
#define APITCH 144                 // bytes per 64-fp16 row (128B + 16B pad)
#define QTILE (128 * APITCH)       // 18432
#define KTILE (64 * APITCH)        // 9216
#define STAGEA (2 * KTILE)         // Kh,Vh = 18432
#define ATT_SMEM (QTILE + 2 * STAGEA)   // 55296

__global__ void __launch_bounds__(256)
attn_mma_kernel(const __half* __restrict__ Qh,
                const __half* __restrict__ Kh,
                const __half* __restrict__ Vh,
                __half* __restrict__ O)
{
    extern __shared__ char smem[];
    const uint32_t sb = smem_u32(smem);
    const int tid = threadIdx.x, lane = tid & 31, wid = tid >> 5;
    const int qt = blockIdx.x, h = blockIdx.y, b = blockIdx.z;
    const int q0 = qt * 128;
    const int wm = wid * 16;

    const __half* qhb = Qh + ((size_t)b * SS + q0) * DD + h * HD;
    const __half* khb = Kh + (size_t)b * SS * DD + h * HD;
    const __half* vhb = Vh + (size_t)b * SS * DD + h * HD;

    const int lr = tid >> 3;        // 0..31
    const int lc = tid & 7;         // 16B chunk
    const uint32_t kv0 = sb + QTILE;

    // --- prologue: Q tile (128 rows) + k-tile 0, one cp.async group ---
#pragma unroll
    for (int it = 0; it < 4; it++) {
        int r = lr + it * 32;       // 0..127
        cp16(sb + (uint32_t)(r * APITCH + lc * 16), qhb + (size_t)r * DD + lc * 8);
    }
#pragma unroll
    for (int it = 0; it < 2; it++) {
        int r = lr + it * 32;       // 0..63
        size_t goff = (size_t)r * DD + lc * 8;
        uint32_t soff = kv0 + (uint32_t)(r * APITCH + lc * 16);
        cp16(soff,         khb + goff);
        cp16(soff + KTILE, vhb + goff);
    }
    CP_COMMIT();

    // fragment address components
    const int g  = lane >> 2;
    const int qd = lane & 3;
    const uint32_t a_off = (uint32_t)((wm + (lane & 7) + ((lane >> 3) & 1) * 8) * APITCH
                                      + ((lane >> 4) & 1) * 16);
    const uint32_t b_off = (uint32_t)(((lane & 7) + ((lane >> 4) & 1) * 8) * APITCH
                                      + ((lane >> 3) & 1) * 16);
    const uint32_t v_off = (uint32_t)(((lane & 7) + ((lane >> 3) & 1) * 8) * APITCH
                                      + ((lane >> 4) & 1) * 16);

    float m0 = -1e30f, m1 = -1e30f, l0 = 0.f, l1 = 0.f;
    float o[8][4];
#pragma unroll
    for (int i = 0; i < 8; i++)
#pragma unroll
        for (int j = 0; j < 4; j++) o[i][j] = 0.f;

    const int row0 = q0 + wm + g;
    const int nkt = 2 * qt + 2;

    for (int kt = 0; kt < nkt; kt++) {
        const uint32_t stage = kv0 + (uint32_t)(kt & 1) * STAGEA;

        if (kt + 1 < nkt) {
            const uint32_t nst = kv0 + (uint32_t)((kt + 1) & 1) * STAGEA;
#pragma unroll
            for (int it = 0; it < 2; it++) {
                int r = lr + it * 32;
                size_t goff = (size_t)((kt + 1) * 64 + r) * DD + lc * 8;
                uint32_t soff = nst + (uint32_t)(r * APITCH + lc * 16);
                cp16(soff,         khb + goff);
                cp16(soff + KTILE, vhb + goff);
            }
            CP_COMMIT();
            CP_WAIT1();
        } else {
            CP_WAIT0();
        }
        __syncthreads();

        if (kt * 64 <= q0 + wm + 15) {
            // --- S = Qh Kh^T ---
            float s[8][4];
#pragma unroll
            for (int i = 0; i < 8; i++)
#pragma unroll
                for (int j = 0; j < 4; j++) s[i][j] = 0.f;

#pragma unroll
            for (int ks = 0; ks < 4; ks++) {
                uint32_t qh[4];
                ldsm_x4(sb + a_off + ks * 32, qh);
#pragma unroll
                for (int np = 0; np < 4; np++) {
                    uint32_t kh[4];
                    ldsm_x4(stage + b_off + np * 16 * APITCH + ks * 32, kh);
#pragma unroll
                    for (int hh = 0; hh < 2; hh++)
                        mma16816h(s[np * 2 + hh], qh, &kh[hh * 2]);
                }
            }

            // --- scale + causal mask ---
            const int kbase0 = kt * 64;
            if (kbase0 + 63 > row0) {
#pragma unroll
                for (int nt = 0; nt < 8; nt++) {
                    int col = kbase0 + nt * 8 + qd * 2;
                    s[nt][0] = (col     <= row0)     ? s[nt][0] * 0.125f : -1e30f;
                    s[nt][1] = (col + 1 <= row0)     ? s[nt][1] * 0.125f : -1e30f;
                    s[nt][2] = (col     <= row0 + 8) ? s[nt][2] * 0.125f : -1e30f;
                    s[nt][3] = (col + 1 <= row0 + 8) ? s[nt][3] * 0.125f : -1e30f;
                }
            } else {
#pragma unroll
                for (int nt = 0; nt < 8; nt++) {
                    s[nt][0] *= 0.125f; s[nt][1] *= 0.125f;
                    s[nt][2] *= 0.125f; s[nt][3] *= 0.125f;
                }
            }

            // --- online softmax (rows g and g+8) ---
            float mx0 = -1e30f, mx1 = -1e30f;
#pragma unroll
            for (int nt = 0; nt < 8; nt++) {
                mx0 = fmaxf(mx0, fmaxf(s[nt][0], s[nt][1]));
                mx1 = fmaxf(mx1, fmaxf(s[nt][2], s[nt][3]));
            }
            mx0 = fmaxf(mx0, __shfl_xor_sync(0xffffffffu, mx0, 1));
            mx0 = fmaxf(mx0, __shfl_xor_sync(0xffffffffu, mx0, 2));
            mx1 = fmaxf(mx1, __shfl_xor_sync(0xffffffffu, mx1, 1));
            mx1 = fmaxf(mx1, __shfl_xor_sync(0xffffffffu, mx1, 2));

            float mn0 = fmaxf(m0, mx0), mn1 = fmaxf(m1, mx1);
            float c0 = __expf(m0 - mn0), c1 = __expf(m1 - mn1);
            m0 = mn0; m1 = mn1;

            float sum0 = 0.f, sum1 = 0.f;
#pragma unroll
            for (int nt = 0; nt < 8; nt++) {
                s[nt][0] = __expf(s[nt][0] - mn0); sum0 += s[nt][0];
                s[nt][1] = __expf(s[nt][1] - mn0); sum0 += s[nt][1];
                s[nt][2] = __expf(s[nt][2] - mn1); sum1 += s[nt][2];
                s[nt][3] = __expf(s[nt][3] - mn1); sum1 += s[nt][3];
            }
            sum0 += __shfl_xor_sync(0xffffffffu, sum0, 1);
            sum0 += __shfl_xor_sync(0xffffffffu, sum0, 2);
            sum1 += __shfl_xor_sync(0xffffffffu, sum1, 1);
            sum1 += __shfl_xor_sync(0xffffffffu, sum1, 2);
            l0 = l0 * c0 + sum0;
            l1 = l1 * c1 + sum1;

#pragma unroll
            for (int nt = 0; nt < 8; nt++) {
                o[nt][0] *= c0; o[nt][1] *= c0;
                o[nt][2] *= c1; o[nt][3] *= c1;
            }

            // --- O += Ph Vh ---
#pragma unroll
            for (int kc = 0; kc < 4; kc++) {
                uint32_t ph[4];
                ph[0] = pack_h2(s[2 * kc][0],     s[2 * kc][1]);
                ph[1] = pack_h2(s[2 * kc][2],     s[2 * kc][3]);
                ph[2] = pack_h2(s[2 * kc + 1][0], s[2 * kc + 1][1]);
                ph[3] = pack_h2(s[2 * kc + 1][2], s[2 * kc + 1][3]);
#pragma unroll
                for (int np = 0; np < 4; np++) {
                    uint32_t vh[4];
                    ldsm_x4_t(stage + KTILE + v_off + kc * 16 * APITCH + np * 32, vh);
#pragma unroll
                    for (int hh = 0; hh < 2; hh++)
                        mma16816h(o[np * 2 + hh], ph, &vh[hh * 2]);
                }
            }
        }
        __syncthreads();
    }

    // --- epilogue: normalize and store as fp16 ---
    const float inv0 = 1.0f / l0, inv1 = 1.0f / l1;
    __half* ob0 = O + ((size_t)b * SS + row0) * DD + h * HD;
    __half* ob1 = O + ((size_t)b * SS + row0 + 8) * DD + h * HD;
#pragma unroll
    for (int nt = 0; nt < 8; nt++) {
        int col = nt * 8 + qd * 2;
        *reinterpret_cast<uint32_t*>(ob0 + col) =
            pack_h2(o[nt][0] * inv0, o[nt][1] * inv0);
        *reinterpret_cast<uint32_t*>(ob1 + col) =
            pack_h2(o[nt][2] * inv1, o[nt][3] * inv1);
    }
}

// ---------------- launch ------------------------------------------------------
extern "C" void kernel_launch(void* const* d_in, const int* in_sizes, int n_in,
                              void* d_out, int out_size)
{
    const float* hs     = (const float*)d_in[0];
    const float* WQ_w   = (const float*)d_in[1];
    const float* WQ_b   = (const float*)d_in[2];
    const float* WK_A_w = (const float*)d_in[3];
    const float* WK_B_w = (const float*)d_in[4];
    const float* WK_B_b = (const float*)d_in[5];
    const float* WV_A_w = (const float*)d_in[6];
    const float* WV_B_w = (const float*)d_in[7];
    const float* WV_B_b = (const float*)d_in[8];
    const float* c_w    = (const float*)d_in[9];
    const float* c_b    = (const float*)d_in[10];
    float* out = (float*)d_out;

    __half *hsh, *wqh, *wkah, *wkbh, *wvah, *wvbh, *cpth;
    __half *tmpkh, *tmpvh, *qh, *kh, *vh, *atth;
    cudaGetSymbolAddress((void**)&hsh,   g_hsh);
    cudaGetSymbolAddress((void**)&wqh,   g_wqh);
    cudaGetSymbolAddress((void**)&wkah,  g_wkah);
    cudaGetSymbolAddress((void**)&wkbh,  g_wkbh);
    cudaGetSymbolAddress((void**)&wvah,  g_wvah);
    cudaGetSymbolAddress((void**)&wvbh,  g_wvbh);
    cudaGetSymbolAddress((void**)&cpth,  g_cpth);
    cudaGetSymbolAddress((void**)&tmpkh, g_tmpkh);
    cudaGetSymbolAddress((void**)&tmpvh, g_tmpvh);
    cudaGetSymbolAddress((void**)&qh,    g_qh);
    cudaGetSymbolAddress((void**)&kh,    g_kh);
    cudaGetSymbolAddress((void**)&vh,    g_vh);
    cudaGetSymbolAddress((void**)&atth,  g_atth);

    cudaFuncSetAttribute(hmma_gemm<true, 0>,
                         cudaFuncAttributeMaxDynamicSharedMemorySize, HMMA_SMEM);
    cudaFuncSetAttribute(hmma_gemm<true, 1>,
                         cudaFuncAttributeMaxDynamicSharedMemorySize, HMMA_SMEM);
    cudaFuncSetAttribute(hmma_gemm_dual_s1,
                         cudaFuncAttributeMaxDynamicSharedMemorySize, HMMA_SMEM);
    cudaFuncSetAttribute(hmma_gemm_dual_s2,
                         cudaFuncAttributeMaxDynamicSharedMemorySize, HMMA_SMEM);
    cudaFuncSetAttribute(attn_mma_kernel,
                         cudaFuncAttributeMaxDynamicSharedMemorySize, ATT_SMEM);

    dim3 blk(256);

    // -------- fp32 -> fp16 conversions (once) --------
    convert_h_kernel<<<MTOT * DD / 4 / 256, blk>>>(hs, hsh, MTOT * DD / 4);
    convert_h_kernel<<<DD * DD / 4 / 256, blk>>>(WQ_w, wqh, DD * DD / 4);
    convert_h_kernel<<<RR * DD / 4 / 256, blk>>>(WK_A_w, wkah, RR * DD / 4);
    convert_h_kernel<<<DD * RR / 4 / 256, blk>>>(WK_B_w, wkbh, DD * RR / 4);
    convert_h_kernel<<<RR * DD / 4 / 256, blk>>>(WV_A_w, wvah, RR * DD / 4);
    convert_h_kernel<<<DD * RR / 4 / 256, blk>>>(WV_B_w, wvbh, DD * RR / 4);
    transpose_convert_kernel<<<dim3(DD / 32, DD / 32), blk>>>(c_w, cpth, DD, DD);

    // -------- projections --------
    // Q = hs @ WQ^T + b  -> fp16
    hmma_gemm<true, 1><<<dim3(DD / 128, MTOT / 128), blk, HMMA_SMEM>>>(
        hsh, wqh, WQ_b, nullptr, qh, MTOT, DD, DD);
    // stage-1 low-rank: tmp_k/tmp_v (fp16 out, one launch)
    hmma_gemm_dual_s1<<<dim3(RR / 128, MTOT / 128, 2), blk, HMMA_SMEM>>>(
        hsh, wkah, wvah, tmpkh, tmpvh, MTOT, RR, DD);
    // stage-2: K/V (fp16 out, one launch)
    hmma_gemm_dual_s2<<<dim3(DD / 128, MTOT / 128, 2), blk, HMMA_SMEM>>>(
        tmpkh, tmpvh, wkbh, wvbh, WK_B_b, WV_B_b, kh, vh, MTOT, DD, RR);

    // -------- attention (single-fp16 HMMA flash), fp16 output --------
    attn_mma_kernel<<<dim3(SS / 128, HH, BB), blk, ATT_SMEM>>>(
        qh, kh, vh, atth);

    // -------- output projection (fp32 out) --------
    hmma_gemm<true, 0><<<dim3(DD / 128, MTOT / 128), blk, HMMA_SMEM>>>(
        atth, cpth, c_b, out, nullptr, MTOT, DD, DD);

    (void)in_sizes; (void)n_in; (void)out_size;
}

// round 15
// speedup vs baseline: 2.3795x; 1.0260x over previous
#include <cuda_runtime.h>
#include <cuda_fp16.h>
#include <cstdint>
#include <cstddef>

// Problem dims (fixed)
#define BB 4
#define SS 2048
#define DD 1024
#define HH 16
#define HD 64
#define RR 512
#define MTOT (BB*SS)          // 8192 rows

// ---------------- scratch (device globals: allocation-guard safe) -------------
__device__ __half g_hsh [(size_t)MTOT * DD];
__device__ __half g_wqh [(size_t)DD * DD];
__device__ __half g_wkah[(size_t)RR * DD];
__device__ __half g_wkbh[(size_t)DD * RR];
__device__ __half g_wvah[(size_t)RR * DD];
__device__ __half g_wvbh[(size_t)DD * RR];
__device__ __half g_cpth[(size_t)DD * DD];     // c_proj transposed -> [N,K], fp16
__device__ __half g_tmpkh[(size_t)MTOT * RR];
__device__ __half g_tmpvh[(size_t)MTOT * RR];
__device__ __half g_qh  [(size_t)MTOT * DD];   // pre-scaled by 1/8 (exact in fp16)
__device__ __half g_kh  [(size_t)MTOT * DD];
__device__ __half g_vh  [(size_t)MTOT * DD];
__device__ __half g_atth[(size_t)MTOT * DD];

// ---------------- mma.sync helpers (family-stable, OK on compute_103) ----------
__device__ __forceinline__ uint32_t smem_u32(const void* p) {
    uint32_t a;
    asm("{ .reg .u64 t; cvta.to.shared.u64 t, %1; cvt.u32.u64 %0, t; }"
        : "=r"(a) : "l"(p));
    return a;
}

__device__ __forceinline__ void ldsm_x4(uint32_t addr, uint32_t* r) {
    asm volatile("ldmatrix.sync.aligned.m8n8.x4.shared.b16 {%0,%1,%2,%3}, [%4];"
                 : "=r"(r[0]), "=r"(r[1]), "=r"(r[2]), "=r"(r[3]) : "r"(addr));
}
__device__ __forceinline__ void ldsm_x4_t(uint32_t addr, uint32_t* r) {
    asm volatile("ldmatrix.sync.aligned.m8n8.x4.trans.shared.b16 {%0,%1,%2,%3}, [%4];"
                 : "=r"(r[0]), "=r"(r[1]), "=r"(r[2]), "=r"(r[3]) : "r"(addr));
}
__device__ __forceinline__ void mma16816h(float* d, const uint32_t* a, const uint32_t* b) {
    asm volatile(
        "mma.sync.aligned.m16n8k16.row.col.f32.f16.f16.f32 "
        "{%0,%1,%2,%3}, {%4,%5,%6,%7}, {%8,%9}, {%0,%1,%2,%3};"
        : "+f"(d[0]), "+f"(d[1]), "+f"(d[2]), "+f"(d[3])
        : "r"(a[0]), "r"(a[1]), "r"(a[2]), "r"(a[3]), "r"(b[0]), "r"(b[1]));
}

__device__ __forceinline__ void cp16(uint32_t dst, const void* src) {
    asm volatile("cp.async.cg.shared.global [%0], [%1], 16;"
                 :: "r"(dst), "l"(src) : "memory");
}
#define CP_COMMIT()  asm volatile("cp.async.commit_group;" ::: "memory")
#define CP_WAIT1()   asm volatile("cp.async.wait_group 1;" ::: "memory")
#define CP_WAIT0()   asm volatile("cp.async.wait_group 0;" ::: "memory")

__device__ __forceinline__ uint32_t pack_h2(float x, float y) {
    __half2 h = __floats2half2_rn(x, y);
    return *reinterpret_cast<uint32_t*>(&h);
}
__device__ __forceinline__ void pack_f4h(float4 v, uint2& h) {
    h.x = pack_h2(v.x, v.y);
    h.y = pack_h2(v.z, v.w);
}

// ---------------- fp32 -> fp16 converters --------------------------------------
__global__ void __launch_bounds__(256)
convert_h_kernel(const float* __restrict__ x, __half* __restrict__ y, int n4)
{
    int i = blockIdx.x * 256 + threadIdx.x;
    if (i >= n4) return;
    float4 v = reinterpret_cast<const float4*>(x)[i];
    uint2 h;
    pack_f4h(v, h);
    reinterpret_cast<uint2*>(y)[i] = h;
}

// transpose + convert: W[K,N] fp32 -> out[N,K] fp16
__global__ void __launch_bounds__(256)
transpose_convert_kernel(const float* __restrict__ W, __half* __restrict__ out,
                         int K, int N)
{
    __shared__ float t[32][33];
    int k0 = blockIdx.y * 32, n0 = blockIdx.x * 32;
    int tx = threadIdx.x & 31, ty = threadIdx.x >> 5;
#pragma unroll
    for (int i = 0; i < 32; i += 8)
        t[ty + i][tx] = W[(size_t)(k0 + ty + i) * N + n0 + tx];
    __syncthreads();
#pragma unroll
    for (int i = 0; i < 32; i += 8)
        out[(size_t)(n0 + ty + i) * K + k0 + tx] = __float2half_rn(t[tx][ty + i]);
}

// ---------------- HMMA fp16 GEMM core (cp.async, 2 blocks/SM) -------------------
// C[M,N] = A[M,K] @ B[N,K]^T (+ bias). A, B fp16 in global.
// OMODE: 0 = fp32 out, 1 = fp16 out, 2 = fp16 out scaled by 1/8 (exact)
#define PITCH 80
#define TILE_B (128 * PITCH)      // 10240
#define STAGE_B (2 * TILE_B)      // A, B = 20480
#define HMMA_SMEM (2 * STAGE_B)   // 40960

__device__ __forceinline__ void
gemm_load_stage(uint32_t st, const __half* __restrict__ A,
                const __half* __restrict__ B,
                int m0, int n0, int kc, int K, int tid)
{
#pragma unroll
    for (int i = 0; i < 2; i++) {
        int idx = tid + i * 256;       // 0..511
        int row = idx >> 2;            // 0..127
        int ch  = idx & 3;             // 16B chunk within 64B row
        uint32_t so = st + (uint32_t)(row * PITCH + ch * 16);
        size_t go = (size_t)row * K + kc + ch * 8;
        cp16(so,          A + (size_t)m0 * K + go);
        cp16(so + TILE_B, B + (size_t)n0 * K + go);
    }
}

template <bool BIAS, int OMODE>
__device__ __forceinline__ void
hmma_core(const __half* __restrict__ A, const __half* __restrict__ B,
          const float* __restrict__ bias, float* __restrict__ C,
          __half* __restrict__ Chi,
          int M, int N, int K)
{
    extern __shared__ char smem[];
    const uint32_t sb = smem_u32(smem);

    const int tid  = threadIdx.x;
    const int lane = tid & 31;
    const int wid  = tid >> 5;
    const int m0 = blockIdx.y * 128, n0 = blockIdx.x * 128;
    const int wm = (wid & 3) * 32;
    const int wn = (wid >> 2) * 64;

    const int a_row = wm + (lane & 7) + ((lane >> 3) & 1) * 8;
    const int a_kb  = ((lane >> 4) & 1) * 16;
    const int b_row = wn + (lane & 7) + ((lane >> 4) & 1) * 8;
    const int b_kb  = ((lane >> 3) & 1) * 16;

    float acc[2][8][4];
#pragma unroll
    for (int i = 0; i < 2; i++)
#pragma unroll
        for (int j = 0; j < 8; j++)
#pragma unroll
            for (int k = 0; k < 4; k++) acc[i][j][k] = 0.f;

    const int NC = K >> 5;

    gemm_load_stage(sb, A, B, m0, n0, 0, K, tid);
    CP_COMMIT();

    for (int c = 0; c < NC; c++) {
        if (c + 1 < NC) {
            gemm_load_stage(sb + (uint32_t)((c + 1) & 1) * STAGE_B,
                            A, B, m0, n0, (c + 1) << 5, K, tid);
            CP_COMMIT();
            CP_WAIT1();
        } else {
            CP_WAIT0();
        }
        __syncthreads();

        const uint32_t st = sb + (uint32_t)(c & 1) * STAGE_B;
#pragma unroll
        for (int ks = 0; ks < 2; ks++) {
            uint32_t ah[2][4];
#pragma unroll
            for (int mt = 0; mt < 2; mt++) {
                uint32_t aaddr = st + (uint32_t)((a_row + mt * 16) * PITCH + a_kb + ks * 32);
                ldsm_x4(aaddr, ah[mt]);
            }
#pragma unroll
            for (int nt2 = 0; nt2 < 4; nt2++) {
                uint32_t bh[4];
                uint32_t baddr = st + TILE_B +
                    (uint32_t)((b_row + nt2 * 16) * PITCH + b_kb + ks * 32);
                ldsm_x4(baddr, bh);
#pragma unroll
                for (int mt = 0; mt < 2; mt++) {
#pragma unroll
                    for (int half = 0; half < 2; half++)
                        mma16816h(acc[mt][nt2 * 2 + half], ah[mt], &bh[half * 2]);
                }
            }
        }
        __syncthreads();
    }

    const int g = lane >> 2;
    const int cpair = (lane & 3) * 2;
#pragma unroll
    for (int mt = 0; mt < 2; mt++) {
#pragma unroll
        for (int nt = 0; nt < 8; nt++) {
            int col = n0 + wn + nt * 8 + cpair;
            float bx = 0.f, by = 0.f;
            if (BIAS) { bx = bias[col]; by = bias[col + 1]; }
            int row0 = m0 + wm + mt * 16 + g;
            float x0 = acc[mt][nt][0] + bx, y0 = acc[mt][nt][1] + by;
            float x1 = acc[mt][nt][2] + bx, y1 = acc[mt][nt][3] + by;
            size_t o0 = (size_t)row0 * N + col;
            size_t o1 = (size_t)(row0 + 8) * N + col;
            if (OMODE == 0) {
                *reinterpret_cast<float2*>(&C[o0]) = make_float2(x0, y0);
                *reinterpret_cast<float2*>(&C[o1]) = make_float2(x1, y1);
            } else if (OMODE == 1) {
                *reinterpret_cast<uint32_t*>(Chi + o0) = pack_h2(x0, y0);
                *reinterpret_cast<uint32_t*>(Chi + o1) = pack_h2(x1, y1);
            } else {
                // scale by 1/8 (power of two: exponent shift, exact in fp16)
                *reinterpret_cast<uint32_t*>(Chi + o0) = pack_h2(x0 * 0.125f, y0 * 0.125f);
                *reinterpret_cast<uint32_t*>(Chi + o1) = pack_h2(x1 * 0.125f, y1 * 0.125f);
            }
        }
    }
}

template <bool BIAS, int OMODE>
__global__ void __launch_bounds__(256, 2)
hmma_gemm(const __half* __restrict__ A, const __half* __restrict__ B,
          const float* __restrict__ bias, float* __restrict__ C,
          __half* __restrict__ Chi,
          int M, int N, int K)
{
    hmma_core<BIAS, OMODE>(A, B, bias, C, Chi, M, N, K);
}

// dual fp16-out GEMM (stage-1 K/V low-rank, no bias): z selects operand set
__global__ void __launch_bounds__(256, 2)
hmma_gemm_dual_s1(const __half* __restrict__ A,
                  const __half* __restrict__ B0, const __half* __restrict__ B1,
                  __half* __restrict__ C0, __half* __restrict__ C1,
                  int M, int N, int K)
{
    if (blockIdx.z == 0)
        hmma_core<false, 1>(A, B0, nullptr, nullptr, C0, M, N, K);
    else
        hmma_core<false, 1>(A, B1, nullptr, nullptr, C1, M, N, K);
}

// dual fp16-out GEMM (stage-2 K/V, bias): z selects operand set
__global__ void __launch_bounds__(256, 2)
hmma_gemm_dual_s2(const __half* __restrict__ A0, const __half* __restrict__ A1,
                  const __half* __restrict__ B0, const __half* __restrict__ B1,
                  const float* __restrict__ bias0, const float* __restrict__ bias1,
                  __half* __restrict__ C0h, __half* __restrict__ C1h,
                  int M, int N, int K)
{
    if (blockIdx.z == 0)
        hmma_core<true, 1>(A0, B0, bias0, nullptr, C0h, M, N, K);
    else
        hmma_core<true, 1>(A1, B1, bias1, nullptr, C1h, M, N, K);
}

// ---------------- HMMA flash attention (fp16, cp.async, 2 blocks/SM) -----------
// grid (S/128, H, B) with qt REVERSED (longest blocks first), 256 threads,
// k-tiles of 64, 2 stages. Q pre-scaled by 1/8 at projection.
#define APITCH 144                 // bytes per 64-fp16 row (128B + 16B pad)
#define QTILE (128 * APITCH)       // 18432
#define KTILE (64 * APITCH)        // 9216
#define STAGEA (2 * KTILE)         // Kh,Vh = 18432
#define ATT_SMEM (QTILE + 2 * STAGEA)   // 55296

__global__ void __launch_bounds__(256, 2)
attn_mma_kernel(const __half* __restrict__ Qh,
                const __half* __restrict__ Kh,
                const __half* __restrict__ Vh,
                __half* __restrict__ O)
{
    extern __shared__ char smem[];
    const uint32_t sb = smem_u32(smem);
    const int tid = threadIdx.x, lane = tid & 31, wid = tid >> 5;
    // longest-first scheduling: high qt launches first
    const int qt = (int)gridDim.x - 1 - (int)blockIdx.x;
    const int h = blockIdx.y, b = blockIdx.z;
    const int q0 = qt * 128;
    const int wm = wid * 16;

    const __half* qhb = Qh + ((size_t)b * SS + q0) * DD + h * HD;
    const __half* khb = Kh + (size_t)b * SS * DD + h * HD;
    const __half* vhb = Vh + (size_t)b * SS * DD + h * HD;

    const int lr = tid >> 3;        // 0..31
    const int lc = tid & 7;         // 16B chunk
    const uint32_t kv0 = sb + QTILE;

    // --- prologue: Q tile (128 rows) + k-tile 0, one cp.async group ---
#pragma unroll
    for (int it = 0; it < 4; it++) {
        int r = lr + it * 32;       // 0..127
        cp16(sb + (uint32_t)(r * APITCH + lc * 16), qhb + (size_t)r * DD + lc * 8);
    }
#pragma unroll
    for (int it = 0; it < 2; it++) {
        int r = lr + it * 32;       // 0..63
        size_t goff = (size_t)r * DD + lc * 8;
        uint32_t soff = kv0 + (uint32_t)(r * APITCH + lc * 16);
        cp16(soff,         khb + goff);
        cp16(soff + KTILE, vhb + goff);
    }
    CP_COMMIT();

    // fragment address components
    const int g  = lane >> 2;
    const int qd = lane & 3;
    const uint32_t a_off = (uint32_t)((wm + (lane & 7) + ((lane >> 3) & 1) * 8) * APITCH
                                      + ((lane >> 4) & 1) * 16);
    const uint32_t b_off = (uint32_t)(((lane & 7) + ((lane >> 4) & 1) * 8) * APITCH
                                      + ((lane >> 3) & 1) * 16);
    const uint32_t v_off = (uint32_t)(((lane & 7) + ((lane >> 3) & 1) * 8) * APITCH
                                      + ((lane >> 4) & 1) * 16);

    float m0 = -1e30f, m1 = -1e30f, l0 = 0.f, l1 = 0.f;
    float o[8][4];
#pragma unroll
    for (int i = 0; i < 8; i++)
#pragma unroll
        for (int j = 0; j < 4; j++) o[i][j] = 0.f;

    const int row0 = q0 + wm + g;
    const int nkt = 2 * qt + 2;

    for (int kt = 0; kt < nkt; kt++) {
        const uint32_t stage = kv0 + (uint32_t)(kt & 1) * STAGEA;

        if (kt + 1 < nkt) {
            const uint32_t nst = kv0 + (uint32_t)((kt + 1) & 1) * STAGEA;
#pragma unroll
            for (int it = 0; it < 2; it++) {
                int r = lr + it * 32;
                size_t goff = (size_t)((kt + 1) * 64 + r) * DD + lc * 8;
                uint32_t soff = nst + (uint32_t)(r * APITCH + lc * 16);
                cp16(soff,         khb + goff);
                cp16(soff + KTILE, vhb + goff);
            }
            CP_COMMIT();
            CP_WAIT1();
        } else {
            CP_WAIT0();
        }
        __syncthreads();

        if (kt * 64 <= q0 + wm + 15) {
            // --- S = (Q/8) K^T  (scale folded into Q; exact) ---
            float s[8][4];
#pragma unroll
            for (int i = 0; i < 8; i++)
#pragma unroll
                for (int j = 0; j < 4; j++) s[i][j] = 0.f;

#pragma unroll
            for (int ks = 0; ks < 4; ks++) {
                uint32_t qh[4];
                ldsm_x4(sb + a_off + ks * 32, qh);
#pragma unroll
                for (int np = 0; np < 4; np++) {
                    uint32_t kh[4];
                    ldsm_x4(stage + b_off + np * 16 * APITCH + ks * 32, kh);
#pragma unroll
                    for (int hh = 0; hh < 2; hh++)
                        mma16816h(s[np * 2 + hh], qh, &kh[hh * 2]);
                }
            }

            // --- causal mask (scale already applied) ---
            const int kbase0 = kt * 64;
            if (kbase0 + 63 > row0) {
#pragma unroll
                for (int nt = 0; nt < 8; nt++) {
                    int col = kbase0 + nt * 8 + qd * 2;
                    if (col     > row0)     s[nt][0] = -1e30f;
                    if (col + 1 > row0)     s[nt][1] = -1e30f;
                    if (col     > row0 + 8) s[nt][2] = -1e30f;
                    if (col + 1 > row0 + 8) s[nt][3] = -1e30f;
                }
            }

            // --- online softmax (rows g and g+8) ---
            float mx0 = -1e30f, mx1 = -1e30f;
#pragma unroll
            for (int nt = 0; nt < 8; nt++) {
                mx0 = fmaxf(mx0, fmaxf(s[nt][0], s[nt][1]));
                mx1 = fmaxf(mx1, fmaxf(s[nt][2], s[nt][3]));
            }
            mx0 = fmaxf(mx0, __shfl_xor_sync(0xffffffffu, mx0, 1));
            mx0 = fmaxf(mx0, __shfl_xor_sync(0xffffffffu, mx0, 2));
            mx1 = fmaxf(mx1, __shfl_xor_sync(0xffffffffu, mx1, 1));
            mx1 = fmaxf(mx1, __shfl_xor_sync(0xffffffffu, mx1, 2));

            float mn0 = fmaxf(m0, mx0), mn1 = fmaxf(m1, mx1);
            float c0 = __expf(m0 - mn0), c1 = __expf(m1 - mn1);
            m0 = mn0; m1 = mn1;

            float sum0 = 0.f, sum1 = 0.f;
#pragma unroll
            for (int nt = 0; nt < 8; nt++) {
                s[nt][0] = __expf(s[nt][0] - mn0); sum0 += s[nt][0];
                s[nt][1] = __expf(s[nt][1] - mn0); sum0 += s[nt][1];
                s[nt][2] = __expf(s[nt][2] - mn1); sum1 += s[nt][2];
                s[nt][3] = __expf(s[nt][3] - mn1); sum1 += s[nt][3];
            }
            sum0 += __shfl_xor_sync(0xffffffffu, sum0, 1);
            sum0 += __shfl_xor_sync(0xffffffffu, sum0, 2);
            sum1 += __shfl_xor_sync(0xffffffffu, sum1, 1);
            sum1 += __shfl_xor_sync(0xffffffffu, sum1, 2);
            l0 = l0 * c0 + sum0;
            l1 = l1 * c1 + sum1;

#pragma unroll
            for (int nt = 0; nt < 8; nt++) {
                o[nt][0] *= c0; o[nt][1] *= c0;
                o[nt][2] *= c1; o[nt][3] *= c1;
            }

            // --- O += Ph Vh ---
#pragma unroll
            for (int kc = 0; kc < 4; kc++) {
                uint32_t ph[4];
                ph[0] = pack_h2(s[2 * kc][0],     s[2 * kc][1]);
                ph[1] = pack_h2(s[2 * kc][2],     s[2 * kc][3]);
                ph[2] = pack_h2(s[2 * kc + 1][0], s[2 * kc + 1][1]);
                ph[3] = pack_h2(s[2 * kc + 1][2], s[2 * kc + 1][3]);
#pragma unroll
                for (int np = 0; np < 4; np++) {
                    uint32_t vh[4];
                    ldsm_x4_t(stage + KTILE + v_off + kc * 16 * APITCH + np * 32, vh);
#pragma unroll
                    for (int hh = 0; hh < 2; hh++)
                        mma16816h(o[np * 2 + hh], ph, &vh[hh * 2]);
                }
            }
        }
        __syncthreads();
    }

    // --- epilogue: normalize and store as fp16 ---
    const float inv0 = 1.0f / l0, inv1 = 1.0f / l1;
    __half* ob0 = O + ((size_t)b * SS + row0) * DD + h * HD;
    __half* ob1 = O + ((size_t)b * SS + row0 + 8) * DD + h * HD;
#pragma unroll
    for (int nt = 0; nt < 8; nt++) {
        int col = nt * 8 + qd * 2;
        *reinterpret_cast<uint32_t*>(ob0 + col) =
            pack_h2(o[nt][0] * inv0, o[nt][1] * inv0);
        *reinterpret_cast<uint32_t*>(ob1 + col) =
            pack_h2(o[nt][2] * inv1, o[nt][3] * inv1);
    }
}

// ---------------- launch ------------------------------------------------------
extern "C" void kernel_launch(void* const* d_in, const int* in_sizes, int n_in,
                              void* d_out, int out_size)
{
    const float* hs     = (const float*)d_in[0];
    const float* WQ_w   = (const float*)d_in[1];
    const float* WQ_b   = (const float*)d_in[2];
    const float* WK_A_w = (const float*)d_in[3];
    const float* WK_B_w = (const float*)d_in[4];
    const float* WK_B_b = (const float*)d_in[5];
    const float* WV_A_w = (const float*)d_in[6];
    const float* WV_B_w = (const float*)d_in[7];
    const float* WV_B_b = (const float*)d_in[8];
    const float* c_w    = (const float*)d_in[9];
    const float* c_b    = (const float*)d_in[10];
    float* out = (float*)d_out;

    __half *hsh, *wqh, *wkah, *wkbh, *wvah, *wvbh, *cpth;
    __half *tmpkh, *tmpvh, *qh, *kh, *vh, *atth;
    cudaGetSymbolAddress((void**)&hsh,   g_hsh);
    cudaGetSymbolAddress((void**)&wqh,   g_wqh);
    cudaGetSymbolAddress((void**)&wkah,  g_wkah);
    cudaGetSymbolAddress((void**)&wkbh,  g_wkbh);
    cudaGetSymbolAddress((void**)&wvah,  g_wvah);
    cudaGetSymbolAddress((void**)&wvbh,  g_wvbh);
    cudaGetSymbolAddress((void**)&cpth,  g_cpth);
    cudaGetSymbolAddress((void**)&tmpkh, g_tmpkh);
    cudaGetSymbolAddress((void**)&tmpvh, g_tmpvh);
    cudaGetSymbolAddress((void**)&qh,    g_qh);
    cudaGetSymbolAddress((void**)&kh,    g_kh);
    cudaGetSymbolAddress((void**)&vh,    g_vh);
    cudaGetSymbolAddress((void**)&atth,  g_atth);

    cudaFuncSetAttribute(hmma_gemm<true, 0>,
                         cudaFuncAttributeMaxDynamicSharedMemorySize, HMMA_SMEM);
    cudaFuncSetAttribute(hmma_gemm<true, 2>,
                         cudaFuncAttributeMaxDynamicSharedMemorySize, HMMA_SMEM);
    cudaFuncSetAttribute(hmma_gemm_dual_s1,
                         cudaFuncAttributeMaxDynamicSharedMemorySize, HMMA_SMEM);
    cudaFuncSetAttribute(hmma_gemm_dual_s2,
                         cudaFuncAttributeMaxDynamicSharedMemorySize, HMMA_SMEM);
    cudaFuncSetAttribute(attn_mma_kernel,
                         cudaFuncAttributeMaxDynamicSharedMemorySize, ATT_SMEM);

    dim3 blk(256);

    // -------- fp32 -> fp16 conversions (once) --------
    convert_h_kernel<<<MTOT * DD / 4 / 256, blk>>>(hs, hsh, MTOT * DD / 4);
    convert_h_kernel<<<DD * DD / 4 / 256, blk>>>(WQ_w, wqh, DD * DD / 4);
    convert_h_kernel<<<RR * DD / 4 / 256, blk>>>(WK_A_w, wkah, RR * DD / 4);
    convert_h_kernel<<<DD * RR / 4 / 256, blk>>>(WK_B_w, wkbh, DD * RR / 4);
    convert_h_kernel<<<RR * DD / 4 / 256, blk>>>(WV_A_w, wvah, RR * DD / 4);
    convert_h_kernel<<<DD * RR / 4 / 256, blk>>>(WV_B_w, wvbh, DD * RR / 4);
    transpose_convert_kernel<<<dim3(DD / 32, DD / 32), blk>>>(c_w, cpth, DD, DD);

    // -------- projections --------
    // Q = (hs @ WQ^T + b) / 8  -> fp16 (scale exact; folded out of attention)
    hmma_gemm<true, 2><<<dim3(DD / 128, MTOT / 128), blk, HMMA_SMEM>>>(
        hsh, wqh, WQ_b, nullptr, qh, MTOT, DD, DD);
    // stage-1 low-rank: tmp_k/tmp_v (fp16 out, one launch)
    hmma_gemm_dual_s1<<<dim3(RR / 128, MTOT / 128, 2), blk, HMMA_SMEM>>>(
        hsh, wkah, wvah, tmpkh, tmpvh, MTOT, RR, DD);
    // stage-2: K/V (fp16 out, one launch)
    hmma_gemm_dual_s2<<<dim3(DD / 128, MTOT / 128, 2), blk, HMMA_SMEM>>>(
        tmpkh, tmpvh, wkbh, wvbh, WK_B_b, WV_B_b, kh, vh, MTOT, DD, RR);

    // -------- attention (fp16 HMMA flash, 2 blocks/SM, longest-first) --------
    attn_mma_kernel<<<dim3(SS / 128, HH, BB), blk, ATT_SMEM>>>(
        qh, kh, vh, atth);

    // -------- output projection (fp32 out) --------
    hmma_gemm<true, 0><<<dim3(DD / 128, MTOT / 128), blk, HMMA_SMEM>>>(
        atth, cpth, c_b, out, nullptr, MTOT, DD, DD);

    (void)in_sizes; (void)n_in; (void)out_size;
}

// round 16
// speedup vs baseline: 2.5785x; 1.0837x over previous
#include <cuda_runtime.h>
#include <cuda_fp16.h>
#include <cstdint>
#include <cstddef>

// Problem dims (fixed)
#define BB 4
#define SS 2048
#define DD 1024
#define HH 16
#define HD 64
#define RR 512
#define MTOT (BB*SS)          // 8192 rows

// 0.125 * log2(e): folds both the 1/sqrt(64) score scale and the exp->exp2
// conversion into the Q projection epilogue.
#define QSCALE 0.18033688011112042f

// ---------------- scratch (device globals: allocation-guard safe) -------------
__device__ __half g_hsh [(size_t)MTOT * DD];
__device__ __half g_wqh [(size_t)DD * DD];
__device__ __half g_wkah[(size_t)RR * DD];
__device__ __half g_wkbh[(size_t)DD * RR];
__device__ __half g_wvah[(size_t)RR * DD];
__device__ __half g_wvbh[(size_t)DD * RR];
__device__ __half g_cpth[(size_t)DD * DD];     // c_proj transposed -> [N,K], fp16
__device__ __half g_tmpkh[(size_t)MTOT * RR];
__device__ __half g_tmpvh[(size_t)MTOT * RR];
__device__ __half g_qh  [(size_t)MTOT * DD];   // pre-scaled by QSCALE
__device__ __half g_kh  [(size_t)MTOT * DD];
__device__ __half g_vh  [(size_t)MTOT * DD];
__device__ __half g_atth[(size_t)MTOT * DD];

// ---------------- mma.sync helpers (family-stable, OK on compute_103) ----------
__device__ __forceinline__ uint32_t smem_u32(const void* p) {
    uint32_t a;
    asm("{ .reg .u64 t; cvta.to.shared.u64 t, %1; cvt.u32.u64 %0, t; }"
        : "=r"(a) : "l"(p));
    return a;
}

__device__ __forceinline__ void ldsm_x4(uint32_t addr, uint32_t* r) {
    asm volatile("ldmatrix.sync.aligned.m8n8.x4.shared.b16 {%0,%1,%2,%3}, [%4];"
                 : "=r"(r[0]), "=r"(r[1]), "=r"(r[2]), "=r"(r[3]) : "r"(addr));
}
__device__ __forceinline__ void ldsm_x4_t(uint32_t addr, uint32_t* r) {
    asm volatile("ldmatrix.sync.aligned.m8n8.x4.trans.shared.b16 {%0,%1,%2,%3}, [%4];"
                 : "=r"(r[0]), "=r"(r[1]), "=r"(r[2]), "=r"(r[3]) : "r"(addr));
}
__device__ __forceinline__ void mma16816h(float* d, const uint32_t* a, const uint32_t* b) {
    asm volatile(
        "mma.sync.aligned.m16n8k16.row.col.f32.f16.f16.f32 "
        "{%0,%1,%2,%3}, {%4,%5,%6,%7}, {%8,%9}, {%0,%1,%2,%3};"
        : "+f"(d[0]), "+f"(d[1]), "+f"(d[2]), "+f"(d[3])
        : "r"(a[0]), "r"(a[1]), "r"(a[2]), "r"(a[3]), "r"(b[0]), "r"(b[1]));
}

__device__ __forceinline__ void cp16(uint32_t dst, const void* src) {
    asm volatile("cp.async.cg.shared.global [%0], [%1], 16;"
                 :: "r"(dst), "l"(src) : "memory");
}
#define CP_COMMIT()  asm volatile("cp.async.commit_group;" ::: "memory")
#define CP_WAIT1()   asm volatile("cp.async.wait_group 1;" ::: "memory")
#define CP_WAIT0()   asm volatile("cp.async.wait_group 0;" ::: "memory")

__device__ __forceinline__ uint32_t pack_h2(float x, float y) {
    __half2 h = __floats2half2_rn(x, y);
    return *reinterpret_cast<uint32_t*>(&h);
}
__device__ __forceinline__ void pack_f4h(float4 v, uint2& h) {
    h.x = pack_h2(v.x, v.y);
    h.y = pack_h2(v.z, v.w);
}

// ---------------- fused fp32 -> fp16 converter (6 arrays, one launch) ----------
// segments in float4 units: hs 2097152 | wq 262144 | wka/wkb/wva/wvb 131072 each
__global__ void __launch_bounds__(256)
convert_all_kernel(const float* __restrict__ hs, const float* __restrict__ wq,
                   const float* __restrict__ wka, const float* __restrict__ wkb,
                   const float* __restrict__ wva, const float* __restrict__ wvb,
                   __half* __restrict__ hsh, __half* __restrict__ wqh,
                   __half* __restrict__ wkah, __half* __restrict__ wkbh,
                   __half* __restrict__ wvah, __half* __restrict__ wvbh)
{
    int i = blockIdx.x * 256 + threadIdx.x;      // global float4 index
    const float* src;
    __half* dst;
    int off;
    if (i < 2097152)        { src = hs;  dst = hsh;  off = 0; }
    else if (i < 2359296)   { src = wq;  dst = wqh;  off = 2097152; }
    else if (i < 2490368)   { src = wka; dst = wkah; off = 2359296; }
    else if (i < 2621440)   { src = wkb; dst = wkbh; off = 2490368; }
    else if (i < 2752512)   { src = wva; dst = wvah; off = 2621440; }
    else                    { src = wvb; dst = wvbh; off = 2752512; }
    int j = i - off;
    float4 v = reinterpret_cast<const float4*>(src)[j];
    uint2 h;
    pack_f4h(v, h);
    reinterpret_cast<uint2*>(dst)[j] = h;
}

// transpose + convert: W[K,N] fp32 -> out[N,K] fp16
__global__ void __launch_bounds__(256)
transpose_convert_kernel(const float* __restrict__ W, __half* __restrict__ out,
                         int K, int N)
{
    __shared__ float t[32][33];
    int k0 = blockIdx.y * 32, n0 = blockIdx.x * 32;
    int tx = threadIdx.x & 31, ty = threadIdx.x >> 5;
#pragma unroll
    for (int i = 0; i < 32; i += 8)
        t[ty + i][tx] = W[(size_t)(k0 + ty + i) * N + n0 + tx];
    __syncthreads();
#pragma unroll
    for (int i = 0; i < 32; i += 8)
        out[(size_t)(n0 + ty + i) * K + k0 + tx] = __float2half_rn(t[tx][ty + i]);
}

// ---------------- HMMA fp16 GEMM core (cp.async, 2 blocks/SM) -------------------
// C[M,N] = A[M,K] @ B[N,K]^T (+ bias). A, B fp16 in global.
// OMODE: 0 = fp32 out, 1 = fp16 out, 2 = fp16 out scaled by QSCALE
#define PITCH 80
#define TILE_B (128 * PITCH)      // 10240
#define STAGE_B (2 * TILE_B)      // A, B = 20480
#define HMMA_SMEM (2 * STAGE_B)   // 40960

__device__ __forceinline__ void
gemm_load_stage(uint32_t st, const __half* __restrict__ A,
                const __half* __restrict__ B,
                int m0, int n0, int kc, int K, int tid)
{
#pragma unroll
    for (int i = 0; i < 2; i++) {
        int idx = tid + i * 256;       // 0..511
        int row = idx >> 2;            // 0..127
        int ch  = idx & 3;             // 16B chunk within 64B row
        uint32_t so = st + (uint32_t)(row * PITCH + ch * 16);
        size_t go = (size_t)row * K + kc + ch * 8;
        cp16(so,          A + (size_t)m0 * K + go);
        cp16(so + TILE_B, B + (size_t)n0 * K + go);
    }
}

template <bool BIAS, int OMODE>
__device__ __forceinline__ void
hmma_core(const __half* __restrict__ A, const __half* __restrict__ B,
          const float* __restrict__ bias, float* __restrict__ C,
          __half* __restrict__ Chi,
          int m0, int n0, int N, int K)
{
    extern __shared__ char smem[];
    const uint32_t sb = smem_u32(smem);

    const int tid  = threadIdx.x;
    const int lane = tid & 31;
    const int wid  = tid >> 5;
    const int wm = (wid & 3) * 32;
    const int wn = (wid >> 2) * 64;

    const int a_row = wm + (lane & 7) + ((lane >> 3) & 1) * 8;
    const int a_kb  = ((lane >> 4) & 1) * 16;
    const int b_row = wn + (lane & 7) + ((lane >> 4) & 1) * 8;
    const int b_kb  = ((lane >> 3) & 1) * 16;

    float acc[2][8][4];
#pragma unroll
    for (int i = 0; i < 2; i++)
#pragma unroll
        for (int j = 0; j < 8; j++)
#pragma unroll
            for (int k = 0; k < 4; k++) acc[i][j][k] = 0.f;

    const int NC = K >> 5;

    gemm_load_stage(sb, A, B, m0, n0, 0, K, tid);
    CP_COMMIT();

    for (int c = 0; c < NC; c++) {
        if (c + 1 < NC) {
            gemm_load_stage(sb + (uint32_t)((c + 1) & 1) * STAGE_B,
                            A, B, m0, n0, (c + 1) << 5, K, tid);
            CP_COMMIT();
            CP_WAIT1();
        } else {
            CP_WAIT0();
        }
        __syncthreads();

        const uint32_t st = sb + (uint32_t)(c & 1) * STAGE_B;
#pragma unroll
        for (int ks = 0; ks < 2; ks++) {
            uint32_t ah[2][4];
#pragma unroll
            for (int mt = 0; mt < 2; mt++) {
                uint32_t aaddr = st + (uint32_t)((a_row + mt * 16) * PITCH + a_kb + ks * 32);
                ldsm_x4(aaddr, ah[mt]);
            }
#pragma unroll
            for (int nt2 = 0; nt2 < 4; nt2++) {
                uint32_t bh[4];
                uint32_t baddr = st + TILE_B +
                    (uint32_t)((b_row + nt2 * 16) * PITCH + b_kb + ks * 32);
                ldsm_x4(baddr, bh);
#pragma unroll
                for (int mt = 0; mt < 2; mt++) {
#pragma unroll
                    for (int half = 0; half < 2; half++)
                        mma16816h(acc[mt][nt2 * 2 + half], ah[mt], &bh[half * 2]);
                }
            }
        }
        __syncthreads();
    }

    const int g = lane >> 2;
    const int cpair = (lane & 3) * 2;
#pragma unroll
    for (int mt = 0; mt < 2; mt++) {
#pragma unroll
        for (int nt = 0; nt < 8; nt++) {
            int col = n0 + wn + nt * 8 + cpair;
            float bx = 0.f, by = 0.f;
            if (BIAS) { bx = bias[col]; by = bias[col + 1]; }
            int row0 = m0 + wm + mt * 16 + g;
            float x0 = acc[mt][nt][0] + bx, y0 = acc[mt][nt][1] + by;
            float x1 = acc[mt][nt][2] + bx, y1 = acc[mt][nt][3] + by;
            size_t o0 = (size_t)row0 * N + col;
            size_t o1 = (size_t)(row0 + 8) * N + col;
            if (OMODE == 0) {
                *reinterpret_cast<float2*>(&C[o0]) = make_float2(x0, y0);
                *reinterpret_cast<float2*>(&C[o1]) = make_float2(x1, y1);
            } else if (OMODE == 1) {
                *reinterpret_cast<uint32_t*>(Chi + o0) = pack_h2(x0, y0);
                *reinterpret_cast<uint32_t*>(Chi + o1) = pack_h2(x1, y1);
            } else {
                *reinterpret_cast<uint32_t*>(Chi + o0) =
                    pack_h2(x0 * QSCALE, y0 * QSCALE);
                *reinterpret_cast<uint32_t*>(Chi + o1) =
                    pack_h2(x1 * QSCALE, y1 * QSCALE);
            }
        }
    }
}

// fused projection launch: grid (8, 64, 2)
//   z=0            : Q = (hs @ WQ^T + b) * QSCALE          (N=1024, 8 x-blocks)
//   z=1, x in 0..3 : tmp_k = hs @ WK_A^T                   (N=512)
//   z=1, x in 4..7 : tmp_v = hs @ WV_A^T                   (N=512)
__global__ void __launch_bounds__(256, 2)
hmma_proj_fused(const __half* __restrict__ hsh,
                const __half* __restrict__ wqh,
                const __half* __restrict__ wkah, const __half* __restrict__ wvah,
                const float* __restrict__ WQ_b,
                __half* __restrict__ qh,
                __half* __restrict__ tmpkh, __half* __restrict__ tmpvh)
{
    const int m0 = blockIdx.y * 128;
    if (blockIdx.z == 0) {
        hmma_core<true, 2>(hsh, wqh, WQ_b, nullptr, qh,
                           m0, blockIdx.x * 128, DD, DD);
    } else if (blockIdx.x < 4) {
        hmma_core<false, 1>(hsh, wkah, nullptr, nullptr, tmpkh,
                            m0, blockIdx.x * 128, RR, DD);
    } else {
        hmma_core<false, 1>(hsh, wvah, nullptr, nullptr, tmpvh,
                            m0, (blockIdx.x - 4) * 128, RR, DD);
    }
}

// dual fp16-out GEMM (stage-2 K/V, bias): z selects operand set
__global__ void __launch_bounds__(256, 2)
hmma_gemm_dual_s2(const __half* __restrict__ A0, const __half* __restrict__ A1,
                  const __half* __restrict__ B0, const __half* __restrict__ B1,
                  const float* __restrict__ bias0, const float* __restrict__ bias1,
                  __half* __restrict__ C0h, __half* __restrict__ C1h,
                  int N, int K)
{
    const int m0 = blockIdx.y * 128, n0 = blockIdx.x * 128;
    if (blockIdx.z == 0)
        hmma_core<true, 1>(A0, B0, bias0, nullptr, C0h, m0, n0, N, K);
    else
        hmma_core<true, 1>(A1, B1, bias1, nullptr, C1h, m0, n0, N, K);
}

// c_proj: fp32 out
__global__ void __launch_bounds__(256, 2)
hmma_gemm_out(const __half* __restrict__ A, const __half* __restrict__ B,
              const float* __restrict__ bias, float* __restrict__ C,
              int N, int K)
{
    hmma_core<true, 0>(A, B, bias, C, nullptr,
                       blockIdx.y * 128, blockIdx.x * 128, N, K);
}

// ---------------- HMMA flash attention (fp16, 3-stage ring, 1 sync/iter) -------
// grid (S/128, H, B) with qt reversed (longest first), 256 threads, 2 blocks/SM.
// Q pre-scaled by QSCALE; softmax in exp2 domain.
#define APITCH 144                 // bytes per 64-fp16 row (128B + 16B pad)
#define QTILE (128 * APITCH)       // 18432
#define KTILE (64 * APITCH)        // 9216
#define STAGEA (2 * KTILE)         // Kh,Vh = 18432
#define ATT_SMEM (QTILE + 3 * STAGEA)   // 73728

__global__ void __launch_bounds__(256, 2)
attn_mma_kernel(const __half* __restrict__ Qh,
                const __half* __restrict__ Kh,
                const __half* __restrict__ Vh,
                __half* __restrict__ O)
{
    extern __shared__ char smem[];
    const uint32_t sb = smem_u32(smem);
    const int tid = threadIdx.x, lane = tid & 31, wid = tid >> 5;
    const int qt = (int)gridDim.x - 1 - (int)blockIdx.x;   // longest-first
    const int h = blockIdx.y, b = blockIdx.z;
    const int q0 = qt * 128;
    const int wm = wid * 16;

    const __half* qhb = Qh + ((size_t)b * SS + q0) * DD + h * HD;
    const __half* khb = Kh + (size_t)b * SS * DD + h * HD;
    const __half* vhb = Vh + (size_t)b * SS * DD + h * HD;

    const int lr = tid >> 3;        // 0..31
    const int lc = tid & 7;         // 16B chunk
    const uint32_t kv0 = sb + QTILE;

    const int nkt = 2 * qt + 2;

    // --- prologue: group0 = Q + k-tile 0; group1 = k-tile 1 (nkt >= 2 always) ---
#pragma unroll
    for (int it = 0; it < 4; it++) {
        int r = lr + it * 32;
        cp16(sb + (uint32_t)(r * APITCH + lc * 16), qhb + (size_t)r * DD + lc * 8);
    }
#pragma unroll
    for (int it = 0; it < 2; it++) {
        int r = lr + it * 32;
        size_t goff = (size_t)r * DD + lc * 8;
        uint32_t soff = kv0 + (uint32_t)(r * APITCH + lc * 16);
        cp16(soff,         khb + goff);
        cp16(soff + KTILE, vhb + goff);
    }
    CP_COMMIT();
#pragma unroll
    for (int it = 0; it < 2; it++) {
        int r = lr + it * 32;
        size_t goff = (size_t)(64 + r) * DD + lc * 8;
        uint32_t soff = kv0 + STAGEA + (uint32_t)(r * APITCH + lc * 16);
        cp16(soff,         khb + goff);
        cp16(soff + KTILE, vhb + goff);
    }
    CP_COMMIT();

    // fragment address components
    const int g  = lane >> 2;
    const int qd = lane & 3;
    const uint32_t a_off = (uint32_t)((wm + (lane & 7) + ((lane >> 3) & 1) * 8) * APITCH
                                      + ((lane >> 4) & 1) * 16);
    const uint32_t b_off = (uint32_t)(((lane & 7) + ((lane >> 4) & 1) * 8) * APITCH
                                      + ((lane >> 3) & 1) * 16);
    const uint32_t v_off = (uint32_t)(((lane & 7) + ((lane >> 3) & 1) * 8) * APITCH
                                      + ((lane >> 4) & 1) * 16);

    float m0 = -1e30f, m1 = -1e30f, l0 = 0.f, l1 = 0.f;
    float o[8][4];
#pragma unroll
    for (int i = 0; i < 8; i++)
#pragma unroll
        for (int j = 0; j < 4; j++) o[i][j] = 0.f;

    const int row0 = q0 + wm + g;

    for (int kt = 0; kt < nkt; kt++) {
        // wait for tile kt (allow tile kt+1 in flight), then one sync
        if (kt + 1 < nkt) { CP_WAIT1(); } else { CP_WAIT0(); }
        __syncthreads();
        // prefetch tile kt+2 into the stage all warps just finished (kt-1's)
        if (kt + 2 < nkt) {
            uint32_t pst = kv0 + (uint32_t)((kt + 2) % 3) * STAGEA;
#pragma unroll
            for (int it = 0; it < 2; it++) {
                int r = lr + it * 32;
                size_t goff = (size_t)((kt + 2) * 64 + r) * DD + lc * 8;
                uint32_t soff = pst + (uint32_t)(r * APITCH + lc * 16);
                cp16(soff,         khb + goff);
                cp16(soff + KTILE, vhb + goff);
            }
            CP_COMMIT();
        }

        if (kt * 64 <= q0 + wm + 15) {
            const uint32_t stage = kv0 + (uint32_t)(kt % 3) * STAGEA;

            // --- S = (Q*QSCALE) K^T  (log2-domain scores) ---
            float s[8][4];
#pragma unroll
            for (int i = 0; i < 8; i++)
#pragma unroll
                for (int j = 0; j < 4; j++) s[i][j] = 0.f;

#pragma unroll
            for (int ks = 0; ks < 4; ks++) {
                uint32_t qh[4];
                ldsm_x4(sb + a_off + ks * 32, qh);
#pragma unroll
                for (int np = 0; np < 4; np++) {
                    uint32_t kh[4];
                    ldsm_x4(stage + b_off + np * 16 * APITCH + ks * 32, kh);
#pragma unroll
                    for (int hh = 0; hh < 2; hh++)
                        mma16816h(s[np * 2 + hh], qh, &kh[hh * 2]);
                }
            }

            // --- causal mask ---
            const int kbase0 = kt * 64;
            if (kbase0 + 63 > row0) {
#pragma unroll
                for (int nt = 0; nt < 8; nt++) {
                    int col = kbase0 + nt * 8 + qd * 2;
                    if (col     > row0)     s[nt][0] = -1e30f;
                    if (col + 1 > row0)     s[nt][1] = -1e30f;
                    if (col     > row0 + 8) s[nt][2] = -1e30f;
                    if (col + 1 > row0 + 8) s[nt][3] = -1e30f;
                }
            }

            // --- online softmax (exp2 domain; rows g and g+8) ---
            float mx0 = -1e30f, mx1 = -1e30f;
#pragma unroll
            for (int nt = 0; nt < 8; nt++) {
                mx0 = fmaxf(mx0, fmaxf(s[nt][0], s[nt][1]));
                mx1 = fmaxf(mx1, fmaxf(s[nt][2], s[nt][3]));
            }
            mx0 = fmaxf(mx0, __shfl_xor_sync(0xffffffffu, mx0, 1));
            mx0 = fmaxf(mx0, __shfl_xor_sync(0xffffffffu, mx0, 2));
            mx1 = fmaxf(mx1, __shfl_xor_sync(0xffffffffu, mx1, 1));
            mx1 = fmaxf(mx1, __shfl_xor_sync(0xffffffffu, mx1, 2));

            float mn0 = fmaxf(m0, mx0), mn1 = fmaxf(m1, mx1);
            float c0 = exp2f(m0 - mn0), c1 = exp2f(m1 - mn1);
            m0 = mn0; m1 = mn1;

            float sum0 = 0.f, sum1 = 0.f;
#pragma unroll
            for (int nt = 0; nt < 8; nt++) {
                s[nt][0] = exp2f(s[nt][0] - mn0); sum0 += s[nt][0];
                s[nt][1] = exp2f(s[nt][1] - mn0); sum0 += s[nt][1];
                s[nt][2] = exp2f(s[nt][2] - mn1); sum1 += s[nt][2];
                s[nt][3] = exp2f(s[nt][3] - mn1); sum1 += s[nt][3];
            }
            sum0 += __shfl_xor_sync(0xffffffffu, sum0, 1);
            sum0 += __shfl_xor_sync(0xffffffffu, sum0, 2);
            sum1 += __shfl_xor_sync(0xffffffffu, sum1, 1);
            sum1 += __shfl_xor_sync(0xffffffffu, sum1, 2);
            l0 = l0 * c0 + sum0;
            l1 = l1 * c1 + sum1;

#pragma unroll
            for (int nt = 0; nt < 8; nt++) {
                o[nt][0] *= c0; o[nt][1] *= c0;
                o[nt][2] *= c1; o[nt][3] *= c1;
            }

            // --- O += Ph Vh ---
#pragma unroll
            for (int kc = 0; kc < 4; kc++) {
                uint32_t ph[4];
                ph[0] = pack_h2(s[2 * kc][0],     s[2 * kc][1]);
                ph[1] = pack_h2(s[2 * kc][2],     s[2 * kc][3]);
                ph[2] = pack_h2(s[2 * kc + 1][0], s[2 * kc + 1][1]);
                ph[3] = pack_h2(s[2 * kc + 1][2], s[2 * kc + 1][3]);
#pragma unroll
                for (int np = 0; np < 4; np++) {
                    uint32_t vh[4];
                    ldsm_x4_t(stage + KTILE + v_off + kc * 16 * APITCH + np * 32, vh);
#pragma unroll
                    for (int hh = 0; hh < 2; hh++)
                        mma16816h(o[np * 2 + hh], ph, &vh[hh * 2]);
                }
            }
        }
    }

    // --- epilogue: normalize and store as fp16 ---
    const float inv0 = 1.0f / l0, inv1 = 1.0f / l1;
    __half* ob0 = O + ((size_t)b * SS + row0) * DD + h * HD;
    __half* ob1 = O + ((size_t)b * SS + row0 + 8) * DD + h * HD;
#pragma unroll
    for (int nt = 0; nt < 8; nt++) {
        int col = nt * 8 + qd * 2;
        *reinterpret_cast<uint32_t*>(ob0 + col) =
            pack_h2(o[nt][0] * inv0, o[nt][1] * inv0);
        *reinterpret_cast<uint32_t*>(ob1 + col) =
            pack_h2(o[nt][2] * inv1, o[nt][3] * inv1);
    }
}

// ---------------- launch ------------------------------------------------------
extern "C" void kernel_launch(void* const* d_in, const int* in_sizes, int n_in,
                              void* d_out, int out_size)
{
    const float* hs     = (const float*)d_in[0];
    const float* WQ_w   = (const float*)d_in[1];
    const float* WQ_b   = (const float*)d_in[2];
    const float* WK_A_w = (const float*)d_in[3];
    const float* WK_B_w = (const float*)d_in[4];
    const float* WK_B_b = (const float*)d_in[5];
    const float* WV_A_w = (const float*)d_in[6];
    const float* WV_B_w = (const float*)d_in[7];
    const float* WV_B_b = (const float*)d_in[8];
    const float* c_w    = (const float*)d_in[9];
    const float* c_b    = (const float*)d_in[10];
    float* out = (float*)d_out;

    __half *hsh, *wqh, *wkah, *wkbh, *wvah, *wvbh, *cpth;
    __half *tmpkh, *tmpvh, *qh, *kh, *vh, *atth;
    cudaGetSymbolAddress((void**)&hsh,   g_hsh);
    cudaGetSymbolAddress((void**)&wqh,   g_wqh);
    cudaGetSymbolAddress((void**)&wkah,  g_wkah);
    cudaGetSymbolAddress((void**)&wkbh,  g_wkbh);
    cudaGetSymbolAddress((void**)&wvah,  g_wvah);
    cudaGetSymbolAddress((void**)&wvbh,  g_wvbh);
    cudaGetSymbolAddress((void**)&cpth,  g_cpth);
    cudaGetSymbolAddress((void**)&tmpkh, g_tmpkh);
    cudaGetSymbolAddress((void**)&tmpvh, g_tmpvh);
    cudaGetSymbolAddress((void**)&qh,    g_qh);
    cudaGetSymbolAddress((void**)&kh,    g_kh);
    cudaGetSymbolAddress((void**)&vh,    g_vh);
    cudaGetSymbolAddress((void**)&atth,  g_atth);

    cudaFuncSetAttribute(hmma_proj_fused,
                         cudaFuncAttributeMaxDynamicSharedMemorySize, HMMA_SMEM);
    cudaFuncSetAttribute(hmma_gemm_dual_s2,
                         cudaFuncAttributeMaxDynamicSharedMemorySize, HMMA_SMEM);
    cudaFuncSetAttribute(hmma_gemm_out,
                         cudaFuncAttributeMaxDynamicSharedMemorySize, HMMA_SMEM);
    cudaFuncSetAttribute(attn_mma_kernel,
                         cudaFuncAttributeMaxDynamicSharedMemorySize, ATT_SMEM);

    dim3 blk(256);

    // -------- fp32 -> fp16 conversions: one fused launch + transpose --------
    convert_all_kernel<<<11264, blk>>>(hs, WQ_w, WK_A_w, WK_B_w, WV_A_w, WV_B_w,
                                       hsh, wqh, wkah, wkbh, wvah, wvbh);
    transpose_convert_kernel<<<dim3(DD / 32, DD / 32), blk>>>(c_w, cpth, DD, DD);

    // -------- projections: Q + stage-1 K/V in one launch --------
    hmma_proj_fused<<<dim3(8, MTOT / 128, 2), blk, HMMA_SMEM>>>(
        hsh, wqh, wkah, wvah, WQ_b, qh, tmpkh, tmpvh);

    // stage-2: K/V (fp16 out, one launch)
    hmma_gemm_dual_s2<<<dim3(DD / 128, MTOT / 128, 2), blk, HMMA_SMEM>>>(
        tmpkh, tmpvh, wkbh, wvbh, WK_B_b, WV_B_b, kh, vh, DD, RR);

    // -------- attention --------
    attn_mma_kernel<<<dim3(SS / 128, HH, BB), blk, ATT_SMEM>>>(
        qh, kh, vh, atth);

    // -------- output projection (fp32 out) --------
    hmma_gemm_out<<<dim3(DD / 128, MTOT / 128), blk, HMMA_SMEM>>>(
        atth, cpth, c_b, out, DD, DD);

    (void)in_sizes; (void)n_in; (void)out_size;
}